// round 1
// baseline (speedup 1.0000x reference)
#include <cuda_runtime.h>
#include <cuda_bf16.h>
#include <math.h>

// Problem constants (fixed by the reference)
#define BATCH 4
#define SEQ   2048
#define DIM   1024
#define HEADS 16
#define HDIM  64
#define MROWS (BATCH * SEQ)          // 8192
#define QKVN  (3 * DIM)              // 3072

// Scratch (device globals; no dynamic allocation allowed)
__device__ float g_qkv[(size_t)MROWS * QKVN];   // [M, 3D] packed q|k|v
__device__ float g_ctx[(size_t)MROWS * DIM];    // attention context [B,S,D]
__device__ float g_att[(size_t)MROWS * DIM];    // out-proj result

// ---------------------------------------------------------------------------
// SGEMM (NT): C[M,N] = A[M,K] @ B[N,K]^T + bias[N]
// 128x128x16 tile, 256 threads, 8x8 per thread, double-buffered smem.
// M, N, K all multiples of tile sizes here (no edge guards needed).
// ---------------------------------------------------------------------------
__global__ __launch_bounds__(256) void sgemm_nt(
    const float* __restrict__ A, const float* __restrict__ B,
    const float* __restrict__ bias, float* __restrict__ C,
    int M, int N, int K)
{
    __shared__ float As[2][16][132];
    __shared__ float Bs[2][16][132];

    const int tid = threadIdx.x;
    const int tx = tid & 15;         // 0..15 -> N
    const int ty = tid >> 4;         // 0..15 -> M
    const int bm = blockIdx.y * 128;
    const int bn = blockIdx.x * 128;

    const int lr = tid >> 2;         // 0..63 row within tile
    const int lc = (tid & 3) * 4;    // 0,4,8,12 col (k) within tile

    const float* Ab = A + (size_t)bm * K + (size_t)lr * K + lc;
    const float* Bb = B + (size_t)bn * K + (size_t)lr * K + lc;

    float4 ra0, ra1, rb0, rb1;

    const int nk = K / 16;

    // prologue: stage 0
    {
        const float* ap = Ab;
        ra0 = *(const float4*)(ap);
        ra1 = *(const float4*)(ap + (size_t)64 * K);
        const float* bp = Bb;
        rb0 = *(const float4*)(bp);
        rb1 = *(const float4*)(bp + (size_t)64 * K);
        As[0][lc + 0][lr] = ra0.x; As[0][lc + 1][lr] = ra0.y;
        As[0][lc + 2][lr] = ra0.z; As[0][lc + 3][lr] = ra0.w;
        As[0][lc + 0][lr + 64] = ra1.x; As[0][lc + 1][lr + 64] = ra1.y;
        As[0][lc + 2][lr + 64] = ra1.z; As[0][lc + 3][lr + 64] = ra1.w;
        Bs[0][lc + 0][lr] = rb0.x; Bs[0][lc + 1][lr] = rb0.y;
        Bs[0][lc + 2][lr] = rb0.z; Bs[0][lc + 3][lr] = rb0.w;
        Bs[0][lc + 0][lr + 64] = rb1.x; Bs[0][lc + 1][lr + 64] = rb1.y;
        Bs[0][lc + 2][lr + 64] = rb1.z; Bs[0][lc + 3][lr + 64] = rb1.w;
    }
    __syncthreads();

    float acc[8][8];
#pragma unroll
    for (int i = 0; i < 8; i++)
#pragma unroll
        for (int j = 0; j < 8; j++) acc[i][j] = 0.0f;

    for (int kt = 0; kt < nk; kt++) {
        const int cur = kt & 1;
        if (kt + 1 < nk) {
            const float* ap = Ab + (size_t)(kt + 1) * 16;
            ra0 = *(const float4*)(ap);
            ra1 = *(const float4*)(ap + (size_t)64 * K);
            const float* bp = Bb + (size_t)(kt + 1) * 16;
            rb0 = *(const float4*)(bp);
            rb1 = *(const float4*)(bp + (size_t)64 * K);
        }
#pragma unroll
        for (int k = 0; k < 16; k++) {
            float4 a0 = *(const float4*)&As[cur][k][ty * 8];
            float4 a1 = *(const float4*)&As[cur][k][ty * 8 + 4];
            float4 b0 = *(const float4*)&Bs[cur][k][tx * 8];
            float4 b1 = *(const float4*)&Bs[cur][k][tx * 8 + 4];
            float av[8] = {a0.x, a0.y, a0.z, a0.w, a1.x, a1.y, a1.z, a1.w};
            float bv[8] = {b0.x, b0.y, b0.z, b0.w, b1.x, b1.y, b1.z, b1.w};
#pragma unroll
            for (int i = 0; i < 8; i++)
#pragma unroll
                for (int j = 0; j < 8; j++)
                    acc[i][j] = fmaf(av[i], bv[j], acc[i][j]);
        }
        if (kt + 1 < nk) {
            const int nxt = (kt + 1) & 1;
            As[nxt][lc + 0][lr] = ra0.x; As[nxt][lc + 1][lr] = ra0.y;
            As[nxt][lc + 2][lr] = ra0.z; As[nxt][lc + 3][lr] = ra0.w;
            As[nxt][lc + 0][lr + 64] = ra1.x; As[nxt][lc + 1][lr + 64] = ra1.y;
            As[nxt][lc + 2][lr + 64] = ra1.z; As[nxt][lc + 3][lr + 64] = ra1.w;
            Bs[nxt][lc + 0][lr] = rb0.x; Bs[nxt][lc + 1][lr] = rb0.y;
            Bs[nxt][lc + 2][lr] = rb0.z; Bs[nxt][lc + 3][lr] = rb0.w;
            Bs[nxt][lc + 0][lr + 64] = rb1.x; Bs[nxt][lc + 1][lr + 64] = rb1.y;
            Bs[nxt][lc + 2][lr + 64] = rb1.z; Bs[nxt][lc + 3][lr + 64] = rb1.w;
        }
        __syncthreads();
    }

    // epilogue with bias
    float bv[8];
#pragma unroll
    for (int j = 0; j < 8; j++) bv[j] = bias[bn + tx * 8 + j];

#pragma unroll
    for (int i = 0; i < 8; i++) {
        float* cp = C + (size_t)(bm + ty * 8 + i) * N + bn + tx * 8;
        float4 v0 = {acc[i][0] + bv[0], acc[i][1] + bv[1],
                     acc[i][2] + bv[2], acc[i][3] + bv[3]};
        float4 v1 = {acc[i][4] + bv[4], acc[i][5] + bv[5],
                     acc[i][6] + bv[6], acc[i][7] + bv[7]};
        *(float4*)(cp) = v0;
        *(float4*)(cp + 4) = v1;
    }
}

// ---------------------------------------------------------------------------
// Flash attention, causal, fp32. One CTA per (b, h, qtile of 64).
// Q pre-scaled by 1/sqrt(64). 256 threads as 16x16; 4x4 regs per thread.
// smem: Qt/Kt/Pt transposed [d][r] with pad stride 65, Vs natural [k][d].
// ---------------------------------------------------------------------------
#define FSP 65
#define FLASH_SMEM ((3 * 64 * FSP + 64 * 64) * 4)

__global__ __launch_bounds__(256) void flash_kernel(
    const float* __restrict__ qkv, float* __restrict__ ctx)
{
    extern __shared__ float sm[];
    float* Qt = sm;
    float* Kt = Qt + 64 * FSP;
    float* Pt = Kt + 64 * FSP;
    float* Vs = Pt + 64 * FSP;     // [64][64]

    const int tid = threadIdx.x;
    const int tx = tid & 15;       // key / dv dimension
    const int ty = tid >> 4;       // query dimension
    const int qt = (int)gridDim.x - 1 - (int)blockIdx.x;  // heavy tiles first
    const int h = blockIdx.y;
    const int b = blockIdx.z;

    const float* qb = qkv + (size_t)b * SEQ * QKVN + h * HDIM;
    const float* kb = qb + DIM;
    const float* vb = qb + 2 * DIM;
    const int q0 = qt * 64;

    // load Q tile transposed + pre-scale
#pragma unroll
    for (int i = 0; i < 4; i++) {
        int idx = tid + i * 256;
        int r = idx >> 4;
        int c = (idx & 15) * 4;
        float4 v = *(const float4*)(qb + (size_t)(q0 + r) * QKVN + c);
        Qt[(c + 0) * FSP + r] = v.x * 0.125f;
        Qt[(c + 1) * FSP + r] = v.y * 0.125f;
        Qt[(c + 2) * FSP + r] = v.z * 0.125f;
        Qt[(c + 3) * FSP + r] = v.w * 0.125f;
    }

    float acc[4][4];
#pragma unroll
    for (int i = 0; i < 4; i++)
#pragma unroll
        for (int j = 0; j < 4; j++) acc[i][j] = 0.0f;
    float mprev[4] = {-INFINITY, -INFINITY, -INFINITY, -INFINITY};
    float lsum[4] = {0.0f, 0.0f, 0.0f, 0.0f};

    for (int kt = 0; kt <= qt; kt++) {
        const int k0 = kt * 64;
        __syncthreads();   // previous iter reads of Kt/Vs/Pt done; Qt stores visible
        // load K (transposed) and V (natural)
#pragma unroll
        for (int i = 0; i < 4; i++) {
            int idx = tid + i * 256;
            int r = idx >> 4;
            int c = (idx & 15) * 4;
            float4 kv = *(const float4*)(kb + (size_t)(k0 + r) * QKVN + c);
            Kt[(c + 0) * FSP + r] = kv.x;
            Kt[(c + 1) * FSP + r] = kv.y;
            Kt[(c + 2) * FSP + r] = kv.z;
            Kt[(c + 3) * FSP + r] = kv.w;
            *(float4*)(Vs + r * 64 + c) =
                *(const float4*)(vb + (size_t)(k0 + r) * QKVN + c);
        }
        __syncthreads();

        // S = Q K^T  (contraction over d)
        float s[4][4];
#pragma unroll
        for (int i = 0; i < 4; i++)
#pragma unroll
            for (int j = 0; j < 4; j++) s[i][j] = 0.0f;
#pragma unroll 8
        for (int d = 0; d < 64; d++) {
            float av[4], bv[4];
#pragma unroll
            for (int i = 0; i < 4; i++) av[i] = Qt[d * FSP + ty * 4 + i];
#pragma unroll
            for (int j = 0; j < 4; j++) bv[j] = Kt[d * FSP + tx * 4 + j];
#pragma unroll
            for (int i = 0; i < 4; i++)
#pragma unroll
                for (int j = 0; j < 4; j++)
                    s[i][j] = fmaf(av[i], bv[j], s[i][j]);
        }

        // causal mask (only the diagonal tile needs it; k0 == q0 there)
        if (kt == qt) {
#pragma unroll
            for (int i = 0; i < 4; i++)
#pragma unroll
                for (int j = 0; j < 4; j++)
                    if (tx * 4 + j > ty * 4 + i) s[i][j] = -INFINITY;
        }

        // online softmax update + write P (transposed)
#pragma unroll
        for (int i = 0; i < 4; i++) {
            float mx = fmaxf(fmaxf(s[i][0], s[i][1]), fmaxf(s[i][2], s[i][3]));
#pragma unroll
            for (int off = 8; off >= 1; off >>= 1)
                mx = fmaxf(mx, __shfl_xor_sync(0xffffffffu, mx, off));
            float mnew = fmaxf(mprev[i], mx);
            float alpha = __expf(mprev[i] - mnew);
            float ps = 0.0f;
#pragma unroll
            for (int j = 0; j < 4; j++) {
                float p = __expf(s[i][j] - mnew);
                Pt[(tx * 4 + j) * FSP + ty * 4 + i] = p;
                ps += p;
            }
#pragma unroll
            for (int off = 8; off >= 1; off >>= 1)
                ps += __shfl_xor_sync(0xffffffffu, ps, off);
            lsum[i] = lsum[i] * alpha + ps;
            mprev[i] = mnew;
#pragma unroll
            for (int j = 0; j < 4; j++) acc[i][j] *= alpha;
        }
        __syncthreads();

        // O += P V  (contraction over key)
#pragma unroll 8
        for (int k = 0; k < 64; k++) {
            float av[4], bv[4];
#pragma unroll
            for (int i = 0; i < 4; i++) av[i] = Pt[k * FSP + ty * 4 + i];
#pragma unroll
            for (int j = 0; j < 4; j++) bv[j] = Vs[k * 64 + tx * 4 + j];
#pragma unroll
            for (int i = 0; i < 4; i++)
#pragma unroll
                for (int j = 0; j < 4; j++)
                    acc[i][j] = fmaf(av[i], bv[j], acc[i][j]);
        }
    }

    // normalize + write ctx as [B,S,H,hd] = [B,S,D]
#pragma unroll
    for (int i = 0; i < 4; i++) {
        float inv = 1.0f / lsum[i];
        int q = q0 + ty * 4 + i;
        float4 o = {acc[i][0] * inv, acc[i][1] * inv,
                    acc[i][2] * inv, acc[i][3] * inv};
        *(float4*)(ctx + ((size_t)b * SEQ + q) * DIM + h * HDIM + tx * 4) = o;
    }
}

// ---------------------------------------------------------------------------
// Residual + LayerNorm: one CTA per row of 1024.
// ---------------------------------------------------------------------------
__global__ __launch_bounds__(256) void ln_kernel(
    const float* __restrict__ x, const float* __restrict__ att,
    const float* __restrict__ gamma, const float* __restrict__ beta,
    float* __restrict__ out)
{
    __shared__ float red[2][8];
    const int row = blockIdx.x;
    const int tid = threadIdx.x;
    const float* xr = x + (size_t)row * DIM;
    const float* ar = att + (size_t)row * DIM;

    float v[4];
    float s = 0.0f, s2 = 0.0f;
#pragma unroll
    for (int i = 0; i < 4; i++) {
        int c = tid + i * 256;
        float t = xr[c] + ar[c];
        v[i] = t;
        s += t;
        s2 += t * t;
    }
#pragma unroll
    for (int off = 16; off >= 1; off >>= 1) {
        s  += __shfl_xor_sync(0xffffffffu, s, off);
        s2 += __shfl_xor_sync(0xffffffffu, s2, off);
    }
    if ((tid & 31) == 0) {
        red[0][tid >> 5] = s;
        red[1][tid >> 5] = s2;
    }
    __syncthreads();
    s = 0.0f; s2 = 0.0f;
#pragma unroll
    for (int k = 0; k < 8; k++) { s += red[0][k]; s2 += red[1][k]; }

    const float mu = s * (1.0f / DIM);
    const float var = s2 * (1.0f / DIM) - mu * mu;
    const float rs = rsqrtf(var + 1e-5f);

    float* orow = out + (size_t)row * DIM;
#pragma unroll
    for (int i = 0; i < 4; i++) {
        int c = tid + i * 256;
        orow[c] = (v[i] - mu) * rs * gamma[c] + beta[c];
    }
}

// ---------------------------------------------------------------------------
// Launch
// ---------------------------------------------------------------------------
extern "C" void kernel_launch(void* const* d_in, const int* in_sizes, int n_in,
                              void* d_out, int out_size)
{
    const float* x      = (const float*)d_in[0];
    const float* w_in   = (const float*)d_in[1];
    const float* b_in   = (const float*)d_in[2];
    const float* w_out  = (const float*)d_in[3];
    const float* b_out  = (const float*)d_in[4];
    const float* gamma  = (const float*)d_in[5];
    const float* beta   = (const float*)d_in[6];
    float* out = (float*)d_out;

    void* p_qkv = nullptr; cudaGetSymbolAddress(&p_qkv, g_qkv);
    void* p_ctx = nullptr; cudaGetSymbolAddress(&p_ctx, g_ctx);
    void* p_att = nullptr; cudaGetSymbolAddress(&p_att, g_att);
    float* qkv = (float*)p_qkv;
    float* ctx = (float*)p_ctx;
    float* att = (float*)p_att;

    cudaFuncSetAttribute(flash_kernel,
                         cudaFuncAttributeMaxDynamicSharedMemorySize,
                         FLASH_SMEM);

    // 1) QKV projection: [8192,3072] = x @ in_proj_w^T + b
    sgemm_nt<<<dim3(QKVN / 128, MROWS / 128), 256>>>(
        x, w_in, b_in, qkv, MROWS, QKVN, DIM);

    // 2) causal flash attention -> ctx [B,S,D]
    flash_kernel<<<dim3(SEQ / 64, HEADS, BATCH), 256, FLASH_SMEM>>>(qkv, ctx);

    // 3) out projection: [8192,1024] = ctx @ out_w^T + b
    sgemm_nt<<<dim3(DIM / 128, MROWS / 128), 256>>>(
        ctx, w_out, b_out, att, MROWS, DIM, DIM);

    // 4) residual + layernorm -> out
    ln_kernel<<<MROWS, 256>>>(x, att, gamma, beta, out);
}

// round 5
// speedup vs baseline: 1.3073x; 1.3073x over previous
#include <cuda_runtime.h>
#include <cuda_bf16.h>
#include <stdint.h>
#include <math.h>

// Problem constants
#define BATCH 4
#define SEQ   2048
#define DIM   1024
#define HEADS 16
#define HDIM  64
#define MROWS (BATCH * SEQ)          // 8192
#define QKVN  (3 * DIM)              // 3072
#define K3    3072                   // split-bf16 K (3 * 1024)

// Scratch (device globals; no dynamic allocation allowed)
__device__ __nv_bfloat16 g_abuf[(size_t)MROWS * K3];   // split-bf16 A operand
__device__ __nv_bfloat16 g_bbuf[(size_t)QKVN * K3];    // split-bf16 B operand
__device__ float g_qkv[(size_t)MROWS * QKVN];          // qkv packed [M,3D]
__device__ float g_ctx[(size_t)MROWS * DIM];           // attention context
__device__ float g_att[(size_t)MROWS * DIM];           // out-proj result

// ===========================================================================
// Helpers (base-ISA only: cp.async, ldmatrix, mma.sync — no tcgen05)
// ===========================================================================
__device__ __forceinline__ uint32_t smem_u32(const void* p) {
    uint32_t a;
    asm("{ .reg .u64 t; cvta.to.shared.u64 t, %1; cvt.u32.u64 %0, t; }"
        : "=r"(a) : "l"(p));
    return a;
}
__device__ __forceinline__ void cp_async16(uint32_t dst, const void* src) {
    asm volatile("cp.async.cg.shared.global [%0], [%1], 16;"
                 :: "r"(dst), "l"(src) : "memory");
}
#define CP_COMMIT() asm volatile("cp.async.commit_group;" ::: "memory")
#define CP_WAIT(n)  asm volatile("cp.async.wait_group %0;" :: "n"(n) : "memory")

__device__ __forceinline__ void ldmatrix_x4(uint32_t& r0, uint32_t& r1,
                                            uint32_t& r2, uint32_t& r3,
                                            uint32_t addr) {
    asm volatile("ldmatrix.sync.aligned.m8n8.x4.shared.b16 {%0,%1,%2,%3}, [%4];"
                 : "=r"(r0), "=r"(r1), "=r"(r2), "=r"(r3) : "r"(addr));
}
__device__ __forceinline__ void mma_bf16(float* d, const uint32_t* a,
                                         uint32_t b0, uint32_t b1) {
    asm volatile(
        "mma.sync.aligned.m16n8k16.row.col.f32.bf16.bf16.f32 "
        "{%0,%1,%2,%3}, {%4,%5,%6,%7}, {%8,%9}, {%0,%1,%2,%3};"
        : "+f"(d[0]), "+f"(d[1]), "+f"(d[2]), "+f"(d[3])
        : "r"(a[0]), "r"(a[1]), "r"(a[2]), "r"(a[3]), "r"(b0), "r"(b1));
}

// ===========================================================================
// Split fp32 -> (hi, lo) bf16 along K3: mode 0 (A): hi|lo|hi, mode 1 (B): hi|hi|lo
// ===========================================================================
__global__ __launch_bounds__(256) void split_bf16_kernel(
    const float* __restrict__ in, __nv_bfloat16* __restrict__ out, int mode)
{
    const int i = blockIdx.x * 256 + threadIdx.x;
    const int row = i >> 8;
    const int c4 = (i & 255) * 4;
    float4 v = ((const float4*)in)[i];

    __nv_bfloat16 h0 = __float2bfloat16_rn(v.x);
    __nv_bfloat16 h1 = __float2bfloat16_rn(v.y);
    __nv_bfloat16 h2 = __float2bfloat16_rn(v.z);
    __nv_bfloat16 h3 = __float2bfloat16_rn(v.w);
    __nv_bfloat16 l0 = __float2bfloat16_rn(v.x - __bfloat162float(h0));
    __nv_bfloat16 l1 = __float2bfloat16_rn(v.y - __bfloat162float(h1));
    __nv_bfloat16 l2 = __float2bfloat16_rn(v.z - __bfloat162float(h2));
    __nv_bfloat16 l3 = __float2bfloat16_rn(v.w - __bfloat162float(h3));

    uint2 H, L;
    H.x = (uint32_t)__bfloat16_as_ushort(h0) | ((uint32_t)__bfloat16_as_ushort(h1) << 16);
    H.y = (uint32_t)__bfloat16_as_ushort(h2) | ((uint32_t)__bfloat16_as_ushort(h3) << 16);
    L.x = (uint32_t)__bfloat16_as_ushort(l0) | ((uint32_t)__bfloat16_as_ushort(l1) << 16);
    L.y = (uint32_t)__bfloat16_as_ushort(l2) | ((uint32_t)__bfloat16_as_ushort(l3) << 16);

    size_t ob = (size_t)row * K3 + c4;
    *(uint2*)(out + ob)        = H;
    *(uint2*)(out + ob + 1024) = mode ? H : L;
    *(uint2*)(out + ob + 2048) = mode ? L : H;
}

// ===========================================================================
// mma.sync bf16 GEMM: C[M,N] = A[M,K3] @ B[N,K3]^T + bias (fp32 out)
// CTA: 128x128, BK=32, 3-stage cp.async. 8 warps (2m x 4n), warp tile 64x32.
// smem rows padded to 80 B (40 bf16): conflict-free ldmatrix + aligned cp.async.
// ===========================================================================
#define BK 32
#define STG 3
#define ROWB 80                              // bytes per smem row
#define TILEB (128 * ROWB)                   // 10240 B per operand per stage
#define GEMM_SMEM (2 * STG * TILEB)          // 61440 B

__device__ __forceinline__ void g_load_tiles(
    const __nv_bfloat16* __restrict__ Ab, const __nv_bfloat16* __restrict__ Bb,
    uint32_t sA, uint32_t sB, int stage, int chunk, int tid)
{
    const uint32_t sa = sA + stage * TILEB;
    const uint32_t sb = sB + stage * TILEB;
#pragma unroll
    for (int i = 0; i < 2; i++) {
        int idx = tid + i * 256;             // 0..511
        int row = idx >> 2;
        int cc = idx & 3;                    // 16B chunk within 64B row
        uint32_t dst = row * ROWB + cc * 16;
        cp_async16(sa + dst, Ab + (size_t)row * K3 + chunk * BK + cc * 8);
        cp_async16(sb + dst, Bb + (size_t)row * K3 + chunk * BK + cc * 8);
    }
}

__global__ __launch_bounds__(256, 2) void gemm_mma(
    const __nv_bfloat16* __restrict__ A, const __nv_bfloat16* __restrict__ B,
    const float* __restrict__ bias, float* __restrict__ C, int N)
{
    extern __shared__ __align__(16) char smem[];
    const uint32_t sA = smem_u32(smem);
    const uint32_t sB = sA + STG * TILEB;

    const int tid = threadIdx.x;
    const int warp = tid >> 5;
    const int lane = tid & 31;
    const int wm = warp >> 2;        // 0..1 -> m offset wm*64
    const int wn = warp & 3;         // 0..3 -> n offset wn*32
    const int bm = blockIdx.y * 128;
    const int bn = blockIdx.x * 128;
    const int NC = K3 / BK;          // 96

    const __nv_bfloat16* Ab = A + (size_t)bm * K3;
    const __nv_bfloat16* Bb = B + (size_t)bn * K3;

    float acc[4][4][4];
#pragma unroll
    for (int mt = 0; mt < 4; mt++)
#pragma unroll
        for (int nt = 0; nt < 4; nt++)
#pragma unroll
            for (int r = 0; r < 4; r++) acc[mt][nt][r] = 0.0f;

    // ldmatrix lane addressing: (lane&15) selects row, (lane>>4) selects 16B k-chunk
    const int lrow = lane & 15;
    const int lcol = (lane >> 4) * 16;

#pragma unroll
    for (int c = 0; c < STG - 1; c++) {
        g_load_tiles(Ab, Bb, sA, sB, c, c, tid);
        CP_COMMIT();
    }

    for (int c = 0; c < NC; c++) {
        CP_WAIT(STG - 2);
        __syncthreads();

        const int t = c + STG - 1;
        if (t < NC) g_load_tiles(Ab, Bb, sA, sB, t % STG, t, tid);
        CP_COMMIT();

        const int s = c % STG;
        const uint32_t aBase = sA + s * TILEB;
        const uint32_t bBase = sB + s * TILEB;

#pragma unroll
        for (int ks = 0; ks < 2; ks++) {
            const int k0 = ks * 16;          // bf16 elems -> *2 bytes
            uint32_t af[4][4];
#pragma unroll
            for (int mt = 0; mt < 4; mt++) {
                uint32_t addr = aBase + (wm * 64 + mt * 16 + lrow) * ROWB
                              + k0 * 2 + lcol;
                ldmatrix_x4(af[mt][0], af[mt][1], af[mt][2], af[mt][3], addr);
            }
            uint32_t bf[2][4];
#pragma unroll
            for (int bt = 0; bt < 2; bt++) {
                uint32_t addr = bBase + (wn * 32 + bt * 16 + lrow) * ROWB
                              + k0 * 2 + lcol;
                ldmatrix_x4(bf[bt][0], bf[bt][1], bf[bt][2], bf[bt][3], addr);
            }
#pragma unroll
            for (int mt = 0; mt < 4; mt++)
#pragma unroll
                for (int nt = 0; nt < 4; nt++) {
                    const int bt = nt >> 1, sel = nt & 1;
                    mma_bf16(acc[mt][nt], af[mt], bf[bt][sel], bf[bt][sel + 2]);
                }
        }
        __syncthreads();
    }

    // epilogue: fragment layout c0:(r=l/4, c=(l%4)*2), c1:c+1, c2:r+8, c3:r+8,c+1
    const int er = lane >> 2;
    const int ec = (lane & 3) * 2;
#pragma unroll
    for (int mt = 0; mt < 4; mt++) {
#pragma unroll
        for (int nt = 0; nt < 4; nt++) {
            const int col = bn + wn * 32 + nt * 8 + ec;
            const float b0 = bias[col], b1 = bias[col + 1];
            const int r0 = bm + wm * 64 + mt * 16 + er;
            float2 v0 = {acc[mt][nt][0] + b0, acc[mt][nt][1] + b1};
            float2 v1 = {acc[mt][nt][2] + b0, acc[mt][nt][3] + b1};
            *(float2*)(C + (size_t)r0 * N + col) = v0;
            *(float2*)(C + (size_t)(r0 + 8) * N + col) = v1;
        }
    }
}

// ===========================================================================
// Flash attention, causal, fp32 (unchanged)
// ===========================================================================
#define FSP 65
#define FLASH_SMEM ((3 * 64 * FSP + 64 * 64) * 4)

__global__ __launch_bounds__(256) void flash_kernel(
    const float* __restrict__ qkv, float* __restrict__ ctx)
{
    extern __shared__ float sm[];
    float* Qt = sm;
    float* Kt = Qt + 64 * FSP;
    float* Pt = Kt + 64 * FSP;
    float* Vs = Pt + 64 * FSP;

    const int tid = threadIdx.x;
    const int tx = tid & 15;
    const int ty = tid >> 4;
    const int qt = (int)gridDim.x - 1 - (int)blockIdx.x;
    const int h = blockIdx.y;
    const int b = blockIdx.z;

    const float* qb = qkv + (size_t)b * SEQ * QKVN + h * HDIM;
    const float* kb = qb + DIM;
    const float* vb = qb + 2 * DIM;
    const int q0 = qt * 64;

#pragma unroll
    for (int i = 0; i < 4; i++) {
        int idx = tid + i * 256;
        int r = idx >> 4;
        int c = (idx & 15) * 4;
        float4 v = *(const float4*)(qb + (size_t)(q0 + r) * QKVN + c);
        Qt[(c + 0) * FSP + r] = v.x * 0.125f;
        Qt[(c + 1) * FSP + r] = v.y * 0.125f;
        Qt[(c + 2) * FSP + r] = v.z * 0.125f;
        Qt[(c + 3) * FSP + r] = v.w * 0.125f;
    }

    float acc[4][4];
#pragma unroll
    for (int i = 0; i < 4; i++)
#pragma unroll
        for (int j = 0; j < 4; j++) acc[i][j] = 0.0f;
    float mprev[4] = {-INFINITY, -INFINITY, -INFINITY, -INFINITY};
    float lsum[4] = {0.0f, 0.0f, 0.0f, 0.0f};

    for (int kt = 0; kt <= qt; kt++) {
        const int k0 = kt * 64;
        __syncthreads();
#pragma unroll
        for (int i = 0; i < 4; i++) {
            int idx = tid + i * 256;
            int r = idx >> 4;
            int c = (idx & 15) * 4;
            float4 kv = *(const float4*)(kb + (size_t)(k0 + r) * QKVN + c);
            Kt[(c + 0) * FSP + r] = kv.x;
            Kt[(c + 1) * FSP + r] = kv.y;
            Kt[(c + 2) * FSP + r] = kv.z;
            Kt[(c + 3) * FSP + r] = kv.w;
            *(float4*)(Vs + r * 64 + c) =
                *(const float4*)(vb + (size_t)(k0 + r) * QKVN + c);
        }
        __syncthreads();

        float s[4][4];
#pragma unroll
        for (int i = 0; i < 4; i++)
#pragma unroll
            for (int j = 0; j < 4; j++) s[i][j] = 0.0f;
#pragma unroll 8
        for (int d = 0; d < 64; d++) {
            float av[4], bv[4];
#pragma unroll
            for (int i = 0; i < 4; i++) av[i] = Qt[d * FSP + ty * 4 + i];
#pragma unroll
            for (int j = 0; j < 4; j++) bv[j] = Kt[d * FSP + tx * 4 + j];
#pragma unroll
            for (int i = 0; i < 4; i++)
#pragma unroll
                for (int j = 0; j < 4; j++)
                    s[i][j] = fmaf(av[i], bv[j], s[i][j]);
        }

        if (kt == qt) {
#pragma unroll
            for (int i = 0; i < 4; i++)
#pragma unroll
                for (int j = 0; j < 4; j++)
                    if (tx * 4 + j > ty * 4 + i) s[i][j] = -INFINITY;
        }

#pragma unroll
        for (int i = 0; i < 4; i++) {
            float mx = fmaxf(fmaxf(s[i][0], s[i][1]), fmaxf(s[i][2], s[i][3]));
#pragma unroll
            for (int off = 8; off >= 1; off >>= 1)
                mx = fmaxf(mx, __shfl_xor_sync(0xffffffffu, mx, off));
            float mnew = fmaxf(mprev[i], mx);
            float alpha = __expf(mprev[i] - mnew);
            float ps = 0.0f;
#pragma unroll
            for (int j = 0; j < 4; j++) {
                float p = __expf(s[i][j] - mnew);
                Pt[(tx * 4 + j) * FSP + ty * 4 + i] = p;
                ps += p;
            }
#pragma unroll
            for (int off = 8; off >= 1; off >>= 1)
                ps += __shfl_xor_sync(0xffffffffu, ps, off);
            lsum[i] = lsum[i] * alpha + ps;
            mprev[i] = mnew;
#pragma unroll
            for (int j = 0; j < 4; j++) acc[i][j] *= alpha;
        }
        __syncthreads();

#pragma unroll 8
        for (int k = 0; k < 64; k++) {
            float av[4], bv[4];
#pragma unroll
            for (int i = 0; i < 4; i++) av[i] = Pt[k * FSP + ty * 4 + i];
#pragma unroll
            for (int j = 0; j < 4; j++) bv[j] = Vs[k * 64 + tx * 4 + j];
#pragma unroll
            for (int i = 0; i < 4; i++)
#pragma unroll
                for (int j = 0; j < 4; j++)
                    acc[i][j] = fmaf(av[i], bv[j], acc[i][j]);
        }
    }

#pragma unroll
    for (int i = 0; i < 4; i++) {
        float inv = 1.0f / lsum[i];
        int q = q0 + ty * 4 + i;
        float4 o = {acc[i][0] * inv, acc[i][1] * inv,
                    acc[i][2] * inv, acc[i][3] * inv};
        *(float4*)(ctx + ((size_t)b * SEQ + q) * DIM + h * HDIM + tx * 4) = o;
    }
}

// ===========================================================================
// Residual + LayerNorm (unchanged)
// ===========================================================================
__global__ __launch_bounds__(256) void ln_kernel(
    const float* __restrict__ x, const float* __restrict__ att,
    const float* __restrict__ gamma, const float* __restrict__ beta,
    float* __restrict__ out)
{
    __shared__ float red[2][8];
    const int row = blockIdx.x;
    const int tid = threadIdx.x;
    const float* xr = x + (size_t)row * DIM;
    const float* ar = att + (size_t)row * DIM;

    float v[4];
    float s = 0.0f, s2 = 0.0f;
#pragma unroll
    for (int i = 0; i < 4; i++) {
        int c = tid + i * 256;
        float t = xr[c] + ar[c];
        v[i] = t;
        s += t;
        s2 += t * t;
    }
#pragma unroll
    for (int off = 16; off >= 1; off >>= 1) {
        s  += __shfl_xor_sync(0xffffffffu, s, off);
        s2 += __shfl_xor_sync(0xffffffffu, s2, off);
    }
    if ((tid & 31) == 0) { red[0][tid >> 5] = s; red[1][tid >> 5] = s2; }
    __syncthreads();
    s = 0.0f; s2 = 0.0f;
#pragma unroll
    for (int k = 0; k < 8; k++) { s += red[0][k]; s2 += red[1][k]; }

    const float mu = s * (1.0f / DIM);
    const float var = s2 * (1.0f / DIM) - mu * mu;
    const float rs = rsqrtf(var + 1e-5f);

    float* orow = out + (size_t)row * DIM;
#pragma unroll
    for (int i = 0; i < 4; i++) {
        int c = tid + i * 256;
        orow[c] = (v[i] - mu) * rs * gamma[c] + beta[c];
    }
}

// ===========================================================================
// Launch
// ===========================================================================
extern "C" void kernel_launch(void* const* d_in, const int* in_sizes, int n_in,
                              void* d_out, int out_size)
{
    const float* x      = (const float*)d_in[0];
    const float* w_in   = (const float*)d_in[1];
    const float* b_in   = (const float*)d_in[2];
    const float* w_out  = (const float*)d_in[3];
    const float* b_out  = (const float*)d_in[4];
    const float* gamma  = (const float*)d_in[5];
    const float* beta   = (const float*)d_in[6];
    float* out = (float*)d_out;

    void* p;
    cudaGetSymbolAddress(&p, g_abuf);  __nv_bfloat16* abuf = (__nv_bfloat16*)p;
    cudaGetSymbolAddress(&p, g_bbuf);  __nv_bfloat16* bbuf = (__nv_bfloat16*)p;
    cudaGetSymbolAddress(&p, g_qkv);   float* qkv = (float*)p;
    cudaGetSymbolAddress(&p, g_ctx);   float* ctx = (float*)p;
    cudaGetSymbolAddress(&p, g_att);   float* att = (float*)p;

    cudaFuncSetAttribute(gemm_mma,
                         cudaFuncAttributeMaxDynamicSharedMemorySize, GEMM_SMEM);
    cudaFuncSetAttribute(flash_kernel,
                         cudaFuncAttributeMaxDynamicSharedMemorySize, FLASH_SMEM);

    // 1) split-convert x (A side) and in_proj_w (B side)
    split_bf16_kernel<<<MROWS, 256>>>(x, abuf, 0);
    split_bf16_kernel<<<QKVN, 256>>>(w_in, bbuf, 1);

    // 2) QKV projection on tensor cores: [8192,3072]
    gemm_mma<<<dim3(QKVN / 128, MROWS / 128), 256, GEMM_SMEM>>>(
        abuf, bbuf, b_in, qkv, QKVN);

    // 3) causal flash attention -> ctx
    flash_kernel<<<dim3(SEQ / 64, HEADS, BATCH), 256, FLASH_SMEM>>>(qkv, ctx);

    // 4) split-convert ctx and out_w, then out projection: [8192,1024]
    split_bf16_kernel<<<MROWS, 256>>>(ctx, abuf, 0);
    split_bf16_kernel<<<DIM, 256>>>(w_out, bbuf, 1);
    gemm_mma<<<dim3(DIM / 128, MROWS / 128), 256, GEMM_SMEM>>>(
        abuf, bbuf, b_out, att, DIM);

    // 5) residual + layernorm
    ln_kernel<<<MROWS, 256>>>(x, att, gamma, beta, out);
}

// round 6
// speedup vs baseline: 2.1954x; 1.6794x over previous
#include <cuda_runtime.h>
#include <cuda_fp16.h>
#include <cuda_bf16.h>
#include <stdint.h>
#include <math.h>

// Problem constants
#define BATCH 4
#define SEQ   2048
#define DIM   1024
#define HEADS 16
#define HDIM  64
#define MROWS (BATCH * SEQ)          // 8192
#define QKVN  (3 * DIM)              // 3072
#define K3    3072                   // split-bf16 K (3 * 1024)

// Scratch (device globals; no dynamic allocation allowed)
__device__ __nv_bfloat16 g_abuf[(size_t)MROWS * K3];   // split-bf16 A operand
__device__ __nv_bfloat16 g_bbuf[(size_t)QKVN * K3];    // split-bf16 B operand
__device__ float g_qkv[(size_t)MROWS * QKVN];          // qkv packed [M,3D]
__device__ float g_ctx[(size_t)MROWS * DIM];           // attention context
__device__ float g_att[(size_t)MROWS * DIM];           // out-proj result

// ===========================================================================
// Helpers (base-ISA only: cp.async, ldmatrix, mma.sync)
// ===========================================================================
__device__ __forceinline__ uint32_t smem_u32(const void* p) {
    uint32_t a;
    asm("{ .reg .u64 t; cvta.to.shared.u64 t, %1; cvt.u32.u64 %0, t; }"
        : "=r"(a) : "l"(p));
    return a;
}
__device__ __forceinline__ void cp_async16(uint32_t dst, const void* src) {
    asm volatile("cp.async.cg.shared.global [%0], [%1], 16;"
                 :: "r"(dst), "l"(src) : "memory");
}
#define CP_COMMIT() asm volatile("cp.async.commit_group;" ::: "memory")
#define CP_WAIT(n)  asm volatile("cp.async.wait_group %0;" :: "n"(n) : "memory")

__device__ __forceinline__ void ldmatrix_x4(uint32_t& r0, uint32_t& r1,
                                            uint32_t& r2, uint32_t& r3,
                                            uint32_t addr) {
    asm volatile("ldmatrix.sync.aligned.m8n8.x4.shared.b16 {%0,%1,%2,%3}, [%4];"
                 : "=r"(r0), "=r"(r1), "=r"(r2), "=r"(r3) : "r"(addr));
}
__device__ __forceinline__ void ldmatrix_x4_trans(uint32_t& r0, uint32_t& r1,
                                                  uint32_t& r2, uint32_t& r3,
                                                  uint32_t addr) {
    asm volatile("ldmatrix.sync.aligned.m8n8.x4.trans.shared.b16 {%0,%1,%2,%3}, [%4];"
                 : "=r"(r0), "=r"(r1), "=r"(r2), "=r"(r3) : "r"(addr));
}
__device__ __forceinline__ void mma_bf16(float* d, const uint32_t* a,
                                         uint32_t b0, uint32_t b1) {
    asm volatile(
        "mma.sync.aligned.m16n8k16.row.col.f32.bf16.bf16.f32 "
        "{%0,%1,%2,%3}, {%4,%5,%6,%7}, {%8,%9}, {%0,%1,%2,%3};"
        : "+f"(d[0]), "+f"(d[1]), "+f"(d[2]), "+f"(d[3])
        : "r"(a[0]), "r"(a[1]), "r"(a[2]), "r"(a[3]), "r"(b0), "r"(b1));
}
__device__ __forceinline__ void mma_f16(float* d, const uint32_t* a,
                                        uint32_t b0, uint32_t b1) {
    asm volatile(
        "mma.sync.aligned.m16n8k16.row.col.f32.f16.f16.f32 "
        "{%0,%1,%2,%3}, {%4,%5,%6,%7}, {%8,%9}, {%0,%1,%2,%3};"
        : "+f"(d[0]), "+f"(d[1]), "+f"(d[2]), "+f"(d[3])
        : "r"(a[0]), "r"(a[1]), "r"(a[2]), "r"(a[3]), "r"(b0), "r"(b1));
}
__device__ __forceinline__ uint32_t packh2(float a, float b) {
    __half2 h = __floats2half2_rn(a, b);
    return *(uint32_t*)&h;
}

// ===========================================================================
// Split fp32 -> (hi, lo) bf16 along K3: mode 0 (A): hi|lo|hi, mode 1 (B): hi|hi|lo
// ===========================================================================
__global__ __launch_bounds__(256) void split_bf16_kernel(
    const float* __restrict__ in, __nv_bfloat16* __restrict__ out, int mode)
{
    const int i = blockIdx.x * 256 + threadIdx.x;
    const int row = i >> 8;
    const int c4 = (i & 255) * 4;
    float4 v = ((const float4*)in)[i];

    __nv_bfloat16 h0 = __float2bfloat16_rn(v.x);
    __nv_bfloat16 h1 = __float2bfloat16_rn(v.y);
    __nv_bfloat16 h2 = __float2bfloat16_rn(v.z);
    __nv_bfloat16 h3 = __float2bfloat16_rn(v.w);
    __nv_bfloat16 l0 = __float2bfloat16_rn(v.x - __bfloat162float(h0));
    __nv_bfloat16 l1 = __float2bfloat16_rn(v.y - __bfloat162float(h1));
    __nv_bfloat16 l2 = __float2bfloat16_rn(v.z - __bfloat162float(h2));
    __nv_bfloat16 l3 = __float2bfloat16_rn(v.w - __bfloat162float(h3));

    uint2 H, L;
    H.x = (uint32_t)__bfloat16_as_ushort(h0) | ((uint32_t)__bfloat16_as_ushort(h1) << 16);
    H.y = (uint32_t)__bfloat16_as_ushort(h2) | ((uint32_t)__bfloat16_as_ushort(h3) << 16);
    L.x = (uint32_t)__bfloat16_as_ushort(l0) | ((uint32_t)__bfloat16_as_ushort(l1) << 16);
    L.y = (uint32_t)__bfloat16_as_ushort(l2) | ((uint32_t)__bfloat16_as_ushort(l3) << 16);

    size_t ob = (size_t)row * K3 + c4;
    *(uint2*)(out + ob)        = H;
    *(uint2*)(out + ob + 1024) = mode ? H : L;
    *(uint2*)(out + ob + 2048) = mode ? L : H;
}

// ===========================================================================
// mma.sync bf16 GEMM (unchanged from R5 — validated)
// ===========================================================================
#define BK 32
#define STG 3
#define ROWB 80
#define TILEB (128 * ROWB)
#define GEMM_SMEM (2 * STG * TILEB)

__device__ __forceinline__ void g_load_tiles(
    const __nv_bfloat16* __restrict__ Ab, const __nv_bfloat16* __restrict__ Bb,
    uint32_t sA, uint32_t sB, int stage, int chunk, int tid)
{
    const uint32_t sa = sA + stage * TILEB;
    const uint32_t sb = sB + stage * TILEB;
#pragma unroll
    for (int i = 0; i < 2; i++) {
        int idx = tid + i * 256;
        int row = idx >> 2;
        int cc = idx & 3;
        uint32_t dst = row * ROWB + cc * 16;
        cp_async16(sa + dst, Ab + (size_t)row * K3 + chunk * BK + cc * 8);
        cp_async16(sb + dst, Bb + (size_t)row * K3 + chunk * BK + cc * 8);
    }
}

__global__ __launch_bounds__(256, 2) void gemm_mma(
    const __nv_bfloat16* __restrict__ A, const __nv_bfloat16* __restrict__ B,
    const float* __restrict__ bias, float* __restrict__ C, int N)
{
    extern __shared__ __align__(16) char smem[];
    const uint32_t sA = smem_u32(smem);
    const uint32_t sB = sA + STG * TILEB;

    const int tid = threadIdx.x;
    const int warp = tid >> 5;
    const int lane = tid & 31;
    const int wm = warp >> 2;
    const int wn = warp & 3;
    const int bm = blockIdx.y * 128;
    const int bn = blockIdx.x * 128;
    const int NC = K3 / BK;

    const __nv_bfloat16* Ab = A + (size_t)bm * K3;
    const __nv_bfloat16* Bb = B + (size_t)bn * K3;

    float acc[4][4][4];
#pragma unroll
    for (int mt = 0; mt < 4; mt++)
#pragma unroll
        for (int nt = 0; nt < 4; nt++)
#pragma unroll
            for (int r = 0; r < 4; r++) acc[mt][nt][r] = 0.0f;

    const int lrow = lane & 15;
    const int lcol = (lane >> 4) * 16;

#pragma unroll
    for (int c = 0; c < STG - 1; c++) {
        g_load_tiles(Ab, Bb, sA, sB, c, c, tid);
        CP_COMMIT();
    }

    for (int c = 0; c < NC; c++) {
        CP_WAIT(STG - 2);
        __syncthreads();

        const int t = c + STG - 1;
        if (t < NC) g_load_tiles(Ab, Bb, sA, sB, t % STG, t, tid);
        CP_COMMIT();

        const int s = c % STG;
        const uint32_t aBase = sA + s * TILEB;
        const uint32_t bBase = sB + s * TILEB;

#pragma unroll
        for (int ks = 0; ks < 2; ks++) {
            const int k0 = ks * 16;
            uint32_t af[4][4];
#pragma unroll
            for (int mt = 0; mt < 4; mt++) {
                uint32_t addr = aBase + (wm * 64 + mt * 16 + lrow) * ROWB
                              + k0 * 2 + lcol;
                ldmatrix_x4(af[mt][0], af[mt][1], af[mt][2], af[mt][3], addr);
            }
            uint32_t bf[2][4];
#pragma unroll
            for (int bt = 0; bt < 2; bt++) {
                uint32_t addr = bBase + (wn * 32 + bt * 16 + lrow) * ROWB
                              + k0 * 2 + lcol;
                ldmatrix_x4(bf[bt][0], bf[bt][1], bf[bt][2], bf[bt][3], addr);
            }
#pragma unroll
            for (int mt = 0; mt < 4; mt++)
#pragma unroll
                for (int nt = 0; nt < 4; nt++) {
                    const int bt = nt >> 1, sel = nt & 1;
                    mma_bf16(acc[mt][nt], af[mt], bf[bt][sel], bf[bt][sel + 2]);
                }
        }
        __syncthreads();
    }

    const int er = lane >> 2;
    const int ec = (lane & 3) * 2;
#pragma unroll
    for (int mt = 0; mt < 4; mt++) {
#pragma unroll
        for (int nt = 0; nt < 4; nt++) {
            const int col = bn + wn * 32 + nt * 8 + ec;
            const float b0 = bias[col], b1 = bias[col + 1];
            const int r0 = bm + wm * 64 + mt * 16 + er;
            float2 v0 = {acc[mt][nt][0] + b0, acc[mt][nt][1] + b1};
            float2 v1 = {acc[mt][nt][2] + b0, acc[mt][nt][3] + b1};
            *(float2*)(C + (size_t)r0 * N + col) = v0;
            *(float2*)(C + (size_t)(r0 + 8) * N + col) = v1;
        }
    }
}

// ===========================================================================
// Flash attention on tensor cores (mma.sync fp16, split-precision).
// CTA: 128 queries x 64 keys. 8 warps, warp = 16 query rows, full key tile.
// S = qh*kh + qh*kl + ql*kh (fp16 splits); P fp16 in-register; PV with V split.
// smem: phase0 Qh[128x72h]|Ql ; loop Kh|Kl|Vh|Vl each [64x72h]. Row = 144 B.
// ===========================================================================
#define FROWB 144
#define FSMEM 36864

__global__ __launch_bounds__(256, 1) void flash_mma(
    const float* __restrict__ qkv, float* __restrict__ ctx)
{
    __shared__ __align__(16) char fsm[FSMEM];
    const uint32_t sb = smem_u32(fsm);

    const int tid = threadIdx.x;
    const int w = tid >> 5;
    const int lane = tid & 31;
    const int er = lane >> 2;
    const int ec = (lane & 3) * 2;
    const int lrow = lane & 15;
    const int lcol = (lane >> 4) * 16;

    const int qt = (int)gridDim.x - 1 - (int)blockIdx.x;   // heavy tiles first
    const int h = blockIdx.y;
    const int b = blockIdx.z;
    const int q0 = qt * 128;

    const float* qb = qkv + (size_t)b * SEQ * QKVN + h * HDIM;
    const float* kb = qb + DIM;
    const float* vb = qb + 2 * DIM;

    // ---- stage Q (pre-scaled by 1/8) as fp16 hi/lo, then grab fragments ----
    const uint32_t Qh = sb, Ql = sb + 18432;
#pragma unroll
    for (int i = 0; i < 8; i++) {
        int idx = tid + i * 256;            // 2048 float4 = 128x64 floats
        int r = idx >> 4;
        int c4 = (idx & 15) * 4;
        float4 v = *(const float4*)(qb + (size_t)(q0 + r) * QKVN + c4);
        v.x *= 0.125f; v.y *= 0.125f; v.z *= 0.125f; v.w *= 0.125f;
        __half hx = __float2half_rn(v.x), hy = __float2half_rn(v.y);
        __half hz = __float2half_rn(v.z), hw = __float2half_rn(v.w);
        uint32_t base = r * FROWB + c4 * 2;
        *(uint32_t*)(fsm + base)     = packh2(v.x, v.y) * 0 + (([&]{ __half2 t = {hx, hy}; return *(uint32_t*)&t; })());
        *(uint32_t*)(fsm + base + 4) = (([&]{ __half2 t = {hz, hw}; return *(uint32_t*)&t; })());
        __half lx = __float2half_rn(v.x - __half2float(hx));
        __half ly = __float2half_rn(v.y - __half2float(hy));
        __half lz = __float2half_rn(v.z - __half2float(hz));
        __half lw = __float2half_rn(v.w - __half2float(hw));
        *(uint32_t*)(fsm + 18432 + base)     = (([&]{ __half2 t = {lx, ly}; return *(uint32_t*)&t; })());
        *(uint32_t*)(fsm + 18432 + base + 4) = (([&]{ __half2 t = {lz, lw}; return *(uint32_t*)&t; })());
    }
    __syncthreads();

    uint32_t qh[4][4], ql[4][4];
#pragma unroll
    for (int ks = 0; ks < 4; ks++) {
        uint32_t a = Qh + (w * 16 + lrow) * FROWB + ks * 32 + lcol;
        ldmatrix_x4(qh[ks][0], qh[ks][1], qh[ks][2], qh[ks][3], a);
        uint32_t a2 = Ql + (w * 16 + lrow) * FROWB + ks * 32 + lcol;
        ldmatrix_x4(ql[ks][0], ql[ks][1], ql[ks][2], ql[ks][3], a2);
    }
    __syncthreads();

    const uint32_t Kh = sb, Kl = sb + 9216, Vh = sb + 18432, Vl = sb + 27648;

    float o[8][4];
#pragma unroll
    for (int nf = 0; nf < 8; nf++)
#pragma unroll
        for (int r = 0; r < 4; r++) o[nf][r] = 0.0f;
    float mprev[2] = {-INFINITY, -INFINITY};
    float lsum[2] = {0.0f, 0.0f};

    const int nkt = 2 * qt + 2;
    for (int kt = 0; kt < nkt; kt++) {
        const int k0 = kt * 64;
        __syncthreads();
        // load + convert K, V tiles (64x64 each)
#pragma unroll
        for (int i = 0; i < 4; i++) {
            int idx = tid + i * 256;        // 1024 float4 per operand
            int r = idx >> 4;
            int c4 = (idx & 15) * 4;
            uint32_t base = r * FROWB + c4 * 2;

            float4 kv = *(const float4*)(kb + (size_t)(k0 + r) * QKVN + c4);
            __half ax = __float2half_rn(kv.x), ay = __float2half_rn(kv.y);
            __half az = __float2half_rn(kv.z), aw = __float2half_rn(kv.w);
            { __half2 t = {ax, ay}; *(uint32_t*)(fsm + base) = *(uint32_t*)&t; }
            { __half2 t = {az, aw}; *(uint32_t*)(fsm + base + 4) = *(uint32_t*)&t; }
            __half bx = __float2half_rn(kv.x - __half2float(ax));
            __half by = __float2half_rn(kv.y - __half2float(ay));
            __half bz = __float2half_rn(kv.z - __half2float(az));
            __half bw = __float2half_rn(kv.w - __half2float(aw));
            { __half2 t = {bx, by}; *(uint32_t*)(fsm + 9216 + base) = *(uint32_t*)&t; }
            { __half2 t = {bz, bw}; *(uint32_t*)(fsm + 9216 + base + 4) = *(uint32_t*)&t; }

            float4 vv = *(const float4*)(vb + (size_t)(k0 + r) * QKVN + c4);
            __half cx = __float2half_rn(vv.x), cy = __float2half_rn(vv.y);
            __half cz = __float2half_rn(vv.z), cw = __float2half_rn(vv.w);
            { __half2 t = {cx, cy}; *(uint32_t*)(fsm + 18432 + base) = *(uint32_t*)&t; }
            { __half2 t = {cz, cw}; *(uint32_t*)(fsm + 18432 + base + 4) = *(uint32_t*)&t; }
            __half dx = __float2half_rn(vv.x - __half2float(cx));
            __half dy = __float2half_rn(vv.y - __half2float(cy));
            __half dz = __float2half_rn(vv.z - __half2float(cz));
            __half dw = __float2half_rn(vv.w - __half2float(cw));
            { __half2 t = {dx, dy}; *(uint32_t*)(fsm + 27648 + base) = *(uint32_t*)&t; }
            { __half2 t = {dz, dw}; *(uint32_t*)(fsm + 27648 + base + 4) = *(uint32_t*)&t; }
        }
        __syncthreads();

        // ---- S = Q K^T (split: qh*kh + qh*kl + ql*kh) ----
        float s[8][4];
#pragma unroll
        for (int nf = 0; nf < 8; nf++)
#pragma unroll
            for (int r = 0; r < 4; r++) s[nf][r] = 0.0f;

#pragma unroll
        for (int ks = 0; ks < 4; ks++) {
#pragma unroll
            for (int g = 0; g < 4; g++) {
                uint32_t kh4[4], kl4[4];
                uint32_t a = Kh + (g * 16 + lrow) * FROWB + ks * 32 + lcol;
                ldmatrix_x4(kh4[0], kh4[1], kh4[2], kh4[3], a);
                uint32_t a2 = Kl + (g * 16 + lrow) * FROWB + ks * 32 + lcol;
                ldmatrix_x4(kl4[0], kl4[1], kl4[2], kl4[3], a2);
                mma_f16(s[2 * g],     qh[ks], kh4[0], kh4[2]);
                mma_f16(s[2 * g],     qh[ks], kl4[0], kl4[2]);
                mma_f16(s[2 * g],     ql[ks], kh4[0], kh4[2]);
                mma_f16(s[2 * g + 1], qh[ks], kh4[1], kh4[3]);
                mma_f16(s[2 * g + 1], qh[ks], kl4[1], kl4[3]);
                mma_f16(s[2 * g + 1], ql[ks], kh4[1], kh4[3]);
            }
        }

        // ---- causal mask (only tiles overlapping the diagonal) ----
        if (kt >= 2 * qt) {
            const int row0 = q0 + w * 16 + er;
#pragma unroll
            for (int nf = 0; nf < 8; nf++) {
                const int keyb = k0 + (nf >> 1) * 16 + (nf & 1) * 8 + ec;
#pragma unroll
                for (int r = 0; r < 4; r++) {
                    int key = keyb + (r & 1);
                    int row = row0 + (r >> 1) * 8;
                    if (key > row) s[nf][r] = -INFINITY;
                }
            }
        }

        // ---- online softmax (rows er, er+8; quad = 4 lanes share a row) ----
        float mx0 = -INFINITY, mx1 = -INFINITY;
#pragma unroll
        for (int nf = 0; nf < 8; nf++) {
            mx0 = fmaxf(mx0, fmaxf(s[nf][0], s[nf][1]));
            mx1 = fmaxf(mx1, fmaxf(s[nf][2], s[nf][3]));
        }
        mx0 = fmaxf(mx0, __shfl_xor_sync(0xffffffffu, mx0, 1));
        mx0 = fmaxf(mx0, __shfl_xor_sync(0xffffffffu, mx0, 2));
        mx1 = fmaxf(mx1, __shfl_xor_sync(0xffffffffu, mx1, 1));
        mx1 = fmaxf(mx1, __shfl_xor_sync(0xffffffffu, mx1, 2));

        float mn0 = fmaxf(mprev[0], mx0);
        float mn1 = fmaxf(mprev[1], mx1);
        float al0 = __expf(mprev[0] - mn0);
        float al1 = __expf(mprev[1] - mn1);
        float sum0 = 0.0f, sum1 = 0.0f;
#pragma unroll
        for (int nf = 0; nf < 8; nf++) {
            s[nf][0] = __expf(s[nf][0] - mn0);
            s[nf][1] = __expf(s[nf][1] - mn0);
            s[nf][2] = __expf(s[nf][2] - mn1);
            s[nf][3] = __expf(s[nf][3] - mn1);
            sum0 += s[nf][0] + s[nf][1];
            sum1 += s[nf][2] + s[nf][3];
        }
        sum0 += __shfl_xor_sync(0xffffffffu, sum0, 1);
        sum0 += __shfl_xor_sync(0xffffffffu, sum0, 2);
        sum1 += __shfl_xor_sync(0xffffffffu, sum1, 1);
        sum1 += __shfl_xor_sync(0xffffffffu, sum1, 2);
        lsum[0] = lsum[0] * al0 + sum0;
        lsum[1] = lsum[1] * al1 + sum1;
        mprev[0] = mn0;
        mprev[1] = mn1;
#pragma unroll
        for (int nf = 0; nf < 8; nf++) {
            o[nf][0] *= al0; o[nf][1] *= al0;
            o[nf][2] *= al1; o[nf][3] *= al1;
        }

        // ---- O += P V (P fp16 in-register; V split hi+lo via ldmatrix.trans)
#pragma unroll
        for (int kk = 0; kk < 4; kk++) {
            uint32_t pa[4];
            pa[0] = packh2(s[2 * kk][0], s[2 * kk][1]);
            pa[1] = packh2(s[2 * kk][2], s[2 * kk][3]);
            pa[2] = packh2(s[2 * kk + 1][0], s[2 * kk + 1][1]);
            pa[3] = packh2(s[2 * kk + 1][2], s[2 * kk + 1][3]);
#pragma unroll
            for (int g = 0; g < 4; g++) {
                uint32_t vh4[4], vl4[4];
                uint32_t a = Vh + (kk * 16 + lrow) * FROWB + g * 32 + lcol;
                ldmatrix_x4_trans(vh4[0], vh4[1], vh4[2], vh4[3], a);
                uint32_t a2 = Vl + (kk * 16 + lrow) * FROWB + g * 32 + lcol;
                ldmatrix_x4_trans(vl4[0], vl4[1], vl4[2], vl4[3], a2);
                mma_f16(o[2 * g],     pa, vh4[0], vh4[1]);
                mma_f16(o[2 * g],     pa, vl4[0], vl4[1]);
                mma_f16(o[2 * g + 1], pa, vh4[2], vh4[3]);
                mma_f16(o[2 * g + 1], pa, vl4[2], vl4[3]);
            }
        }
    }

    // ---- normalize + write ctx [B,S,D] ----
    const float inv0 = 1.0f / lsum[0];
    const float inv1 = 1.0f / lsum[1];
    const int row0 = q0 + w * 16 + er;
    float* cb = ctx + ((size_t)b * SEQ) * DIM + h * HDIM;
#pragma unroll
    for (int nf = 0; nf < 8; nf++) {
        const int col = nf * 8 + ec;
        float2 v0 = {o[nf][0] * inv0, o[nf][1] * inv0};
        float2 v1 = {o[nf][2] * inv1, o[nf][3] * inv1};
        *(float2*)(cb + (size_t)row0 * DIM + col) = v0;
        *(float2*)(cb + (size_t)(row0 + 8) * DIM + col) = v1;
    }
}

// ===========================================================================
// Residual + LayerNorm (unchanged)
// ===========================================================================
__global__ __launch_bounds__(256) void ln_kernel(
    const float* __restrict__ x, const float* __restrict__ att,
    const float* __restrict__ gamma, const float* __restrict__ beta,
    float* __restrict__ out)
{
    __shared__ float red[2][8];
    const int row = blockIdx.x;
    const int tid = threadIdx.x;
    const float* xr = x + (size_t)row * DIM;
    const float* ar = att + (size_t)row * DIM;

    float v[4];
    float s = 0.0f, s2 = 0.0f;
#pragma unroll
    for (int i = 0; i < 4; i++) {
        int c = tid + i * 256;
        float t = xr[c] + ar[c];
        v[i] = t;
        s += t;
        s2 += t * t;
    }
#pragma unroll
    for (int off = 16; off >= 1; off >>= 1) {
        s  += __shfl_xor_sync(0xffffffffu, s, off);
        s2 += __shfl_xor_sync(0xffffffffu, s2, off);
    }
    if ((tid & 31) == 0) { red[0][tid >> 5] = s; red[1][tid >> 5] = s2; }
    __syncthreads();
    s = 0.0f; s2 = 0.0f;
#pragma unroll
    for (int k = 0; k < 8; k++) { s += red[0][k]; s2 += red[1][k]; }

    const float mu = s * (1.0f / DIM);
    const float var = s2 * (1.0f / DIM) - mu * mu;
    const float rs = rsqrtf(var + 1e-5f);

    float* orow = out + (size_t)row * DIM;
#pragma unroll
    for (int i = 0; i < 4; i++) {
        int c = tid + i * 256;
        orow[c] = (v[i] - mu) * rs * gamma[c] + beta[c];
    }
}

// ===========================================================================
// Launch
// ===========================================================================
extern "C" void kernel_launch(void* const* d_in, const int* in_sizes, int n_in,
                              void* d_out, int out_size)
{
    const float* x      = (const float*)d_in[0];
    const float* w_in   = (const float*)d_in[1];
    const float* b_in   = (const float*)d_in[2];
    const float* w_out  = (const float*)d_in[3];
    const float* b_out  = (const float*)d_in[4];
    const float* gamma  = (const float*)d_in[5];
    const float* beta   = (const float*)d_in[6];
    float* out = (float*)d_out;

    void* p;
    cudaGetSymbolAddress(&p, g_abuf);  __nv_bfloat16* abuf = (__nv_bfloat16*)p;
    cudaGetSymbolAddress(&p, g_bbuf);  __nv_bfloat16* bbuf = (__nv_bfloat16*)p;
    cudaGetSymbolAddress(&p, g_qkv);   float* qkv = (float*)p;
    cudaGetSymbolAddress(&p, g_ctx);   float* ctx = (float*)p;
    cudaGetSymbolAddress(&p, g_att);   float* att = (float*)p;

    cudaFuncSetAttribute(gemm_mma,
                         cudaFuncAttributeMaxDynamicSharedMemorySize, GEMM_SMEM);

    // 1) split-convert x (A side) and in_proj_w (B side)
    split_bf16_kernel<<<MROWS, 256>>>(x, abuf, 0);
    split_bf16_kernel<<<QKVN, 256>>>(w_in, bbuf, 1);

    // 2) QKV projection on tensor cores: [8192,3072]
    gemm_mma<<<dim3(QKVN / 128, MROWS / 128), 256, GEMM_SMEM>>>(
        abuf, bbuf, b_in, qkv, QKVN);

    // 3) causal flash attention (tensor cores) -> ctx
    flash_mma<<<dim3(SEQ / 128, HEADS, BATCH), 256>>>(qkv, ctx);

    // 4) split-convert ctx and out_w, then out projection: [8192,1024]
    split_bf16_kernel<<<MROWS, 256>>>(ctx, abuf, 0);
    split_bf16_kernel<<<DIM, 256>>>(w_out, bbuf, 1);
    gemm_mma<<<dim3(DIM / 128, MROWS / 128), 256, GEMM_SMEM>>>(
        abuf, bbuf, b_out, att, DIM);

    // 5) residual + layernorm
    ln_kernel<<<MROWS, 256>>>(x, att, gamma, beta, out);
}

// round 7
// speedup vs baseline: 2.2667x; 1.0325x over previous
#include <cuda_runtime.h>
#include <cuda_fp16.h>
#include <cuda_bf16.h>
#include <stdint.h>
#include <math.h>

// Problem constants
#define BATCH 4
#define SEQ   2048
#define DIM   1024
#define HEADS 16
#define HDIM  64
#define MROWS (BATCH * SEQ)          // 8192
#define QKVN  (3 * DIM)              // 3072
#define K3    3072                   // split-bf16 K (3 * 1024)
#define PLANE ((size_t)BATCH * HEADS * SEQ * HDIM)   // 8388608 halves / plane

// Scratch (device globals; no dynamic allocation allowed)
__device__ __nv_bfloat16 g_abuf[(size_t)MROWS * K3];   // split-bf16 A operand
__device__ __nv_bfloat16 g_bbuf[(size_t)QKVN * K3];    // split-bf16 B operand
__device__ __half g_f16[6 * PLANE];                    // Qh,Ql,Kh,Kl,Vh,Vl planes
__device__ float g_att[(size_t)MROWS * DIM];           // out-proj result

// ===========================================================================
// Helpers (base-ISA only: cp.async, ldmatrix, mma.sync)
// ===========================================================================
__device__ __forceinline__ uint32_t smem_u32(const void* p) {
    uint32_t a;
    asm("{ .reg .u64 t; cvta.to.shared.u64 t, %1; cvt.u32.u64 %0, t; }"
        : "=r"(a) : "l"(p));
    return a;
}
__device__ __forceinline__ void cp_async16(uint32_t dst, const void* src) {
    asm volatile("cp.async.cg.shared.global [%0], [%1], 16;"
                 :: "r"(dst), "l"(src) : "memory");
}
#define CP_COMMIT() asm volatile("cp.async.commit_group;" ::: "memory")
#define CP_WAIT(n)  asm volatile("cp.async.wait_group %0;" :: "n"(n) : "memory")

__device__ __forceinline__ void ldmatrix_x4(uint32_t& r0, uint32_t& r1,
                                            uint32_t& r2, uint32_t& r3,
                                            uint32_t addr) {
    asm volatile("ldmatrix.sync.aligned.m8n8.x4.shared.b16 {%0,%1,%2,%3}, [%4];"
                 : "=r"(r0), "=r"(r1), "=r"(r2), "=r"(r3) : "r"(addr));
}
__device__ __forceinline__ void ldmatrix_x4_trans(uint32_t& r0, uint32_t& r1,
                                                  uint32_t& r2, uint32_t& r3,
                                                  uint32_t addr) {
    asm volatile("ldmatrix.sync.aligned.m8n8.x4.trans.shared.b16 {%0,%1,%2,%3}, [%4];"
                 : "=r"(r0), "=r"(r1), "=r"(r2), "=r"(r3) : "r"(addr));
}
__device__ __forceinline__ void mma_bf16(float* d, const uint32_t* a,
                                         uint32_t b0, uint32_t b1) {
    asm volatile(
        "mma.sync.aligned.m16n8k16.row.col.f32.bf16.bf16.f32 "
        "{%0,%1,%2,%3}, {%4,%5,%6,%7}, {%8,%9}, {%0,%1,%2,%3};"
        : "+f"(d[0]), "+f"(d[1]), "+f"(d[2]), "+f"(d[3])
        : "r"(a[0]), "r"(a[1]), "r"(a[2]), "r"(a[3]), "r"(b0), "r"(b1));
}
__device__ __forceinline__ void mma_f16(float* d, const uint32_t* a,
                                        uint32_t b0, uint32_t b1) {
    asm volatile(
        "mma.sync.aligned.m16n8k16.row.col.f32.f16.f16.f32 "
        "{%0,%1,%2,%3}, {%4,%5,%6,%7}, {%8,%9}, {%0,%1,%2,%3};"
        : "+f"(d[0]), "+f"(d[1]), "+f"(d[2]), "+f"(d[3])
        : "r"(a[0]), "r"(a[1]), "r"(a[2]), "r"(a[3]), "r"(b0), "r"(b1));
}
__device__ __forceinline__ uint32_t packh2(float a, float b) {
    __half2 h = __floats2half2_rn(a, b);
    return *(uint32_t*)&h;
}

// ===========================================================================
// Split fp32 -> (hi, lo) bf16 along K3: mode 0 (A): hi|lo|hi, mode 1 (B): hi|hi|lo
// ===========================================================================
__global__ __launch_bounds__(256) void split_bf16_kernel(
    const float* __restrict__ in, __nv_bfloat16* __restrict__ out, int mode)
{
    const int i = blockIdx.x * 256 + threadIdx.x;
    const int row = i >> 8;
    const int c4 = (i & 255) * 4;
    float4 v = ((const float4*)in)[i];

    __nv_bfloat16 h0 = __float2bfloat16_rn(v.x);
    __nv_bfloat16 h1 = __float2bfloat16_rn(v.y);
    __nv_bfloat16 h2 = __float2bfloat16_rn(v.z);
    __nv_bfloat16 h3 = __float2bfloat16_rn(v.w);
    __nv_bfloat16 l0 = __float2bfloat16_rn(v.x - __bfloat162float(h0));
    __nv_bfloat16 l1 = __float2bfloat16_rn(v.y - __bfloat162float(h1));
    __nv_bfloat16 l2 = __float2bfloat16_rn(v.z - __bfloat162float(h2));
    __nv_bfloat16 l3 = __float2bfloat16_rn(v.w - __bfloat162float(h3));

    uint2 H, L;
    H.x = (uint32_t)__bfloat16_as_ushort(h0) | ((uint32_t)__bfloat16_as_ushort(h1) << 16);
    H.y = (uint32_t)__bfloat16_as_ushort(h2) | ((uint32_t)__bfloat16_as_ushort(h3) << 16);
    L.x = (uint32_t)__bfloat16_as_ushort(l0) | ((uint32_t)__bfloat16_as_ushort(l1) << 16);
    L.y = (uint32_t)__bfloat16_as_ushort(l2) | ((uint32_t)__bfloat16_as_ushort(l3) << 16);

    size_t ob = (size_t)row * K3 + c4;
    *(uint2*)(out + ob)        = H;
    *(uint2*)(out + ob + 1024) = mode ? H : L;
    *(uint2*)(out + ob + 2048) = mode ? L : H;
}

// ===========================================================================
// mma.sync bf16 GEMM: C = A[M,K3] @ B[N,K3]^T + bias
// MODE 0: fp32 out (out-projection).  MODE 1: QKV -> fp16 hi/lo planes.
// ===========================================================================
#define BK 32
#define STG 3
#define ROWB 80
#define TILEB (128 * ROWB)
#define GEMM_SMEM (2 * STG * TILEB)

__device__ __forceinline__ void g_load_tiles(
    const __nv_bfloat16* __restrict__ Ab, const __nv_bfloat16* __restrict__ Bb,
    uint32_t sA, uint32_t sB, int stage, int chunk, int tid)
{
    const uint32_t sa = sA + stage * TILEB;
    const uint32_t sb = sB + stage * TILEB;
#pragma unroll
    for (int i = 0; i < 2; i++) {
        int idx = tid + i * 256;
        int row = idx >> 2;
        int cc = idx & 3;
        uint32_t dst = row * ROWB + cc * 16;
        cp_async16(sa + dst, Ab + (size_t)row * K3 + chunk * BK + cc * 8);
        cp_async16(sb + dst, Bb + (size_t)row * K3 + chunk * BK + cc * 8);
    }
}

template <int MODE>
__global__ __launch_bounds__(256, 2) void gemm_mma(
    const __nv_bfloat16* __restrict__ A, const __nv_bfloat16* __restrict__ B,
    const float* __restrict__ bias, float* __restrict__ C,
    __half* __restrict__ f16out, int N)
{
    extern __shared__ __align__(16) char smem[];
    const uint32_t sA = smem_u32(smem);
    const uint32_t sB = sA + STG * TILEB;

    const int tid = threadIdx.x;
    const int warp = tid >> 5;
    const int lane = tid & 31;
    const int wm = warp >> 2;
    const int wn = warp & 3;
    const int bm = blockIdx.y * 128;
    const int bn = blockIdx.x * 128;
    const int NC = K3 / BK;

    const __nv_bfloat16* Ab = A + (size_t)bm * K3;
    const __nv_bfloat16* Bb = B + (size_t)bn * K3;

    float acc[4][4][4];
#pragma unroll
    for (int mt = 0; mt < 4; mt++)
#pragma unroll
        for (int nt = 0; nt < 4; nt++)
#pragma unroll
            for (int r = 0; r < 4; r++) acc[mt][nt][r] = 0.0f;

    const int lrow = lane & 15;
    const int lcol = (lane >> 4) * 16;

#pragma unroll
    for (int c = 0; c < STG - 1; c++) {
        g_load_tiles(Ab, Bb, sA, sB, c, c, tid);
        CP_COMMIT();
    }

    for (int c = 0; c < NC; c++) {
        CP_WAIT(STG - 2);
        __syncthreads();

        const int t = c + STG - 1;
        if (t < NC) g_load_tiles(Ab, Bb, sA, sB, t % STG, t, tid);
        CP_COMMIT();

        const int s = c % STG;
        const uint32_t aBase = sA + s * TILEB;
        const uint32_t bBase = sB + s * TILEB;

#pragma unroll
        for (int ks = 0; ks < 2; ks++) {
            const int k0 = ks * 16;
            uint32_t af[4][4];
#pragma unroll
            for (int mt = 0; mt < 4; mt++) {
                uint32_t addr = aBase + (wm * 64 + mt * 16 + lrow) * ROWB
                              + k0 * 2 + lcol;
                ldmatrix_x4(af[mt][0], af[mt][1], af[mt][2], af[mt][3], addr);
            }
            uint32_t bf[2][4];
#pragma unroll
            for (int bt = 0; bt < 2; bt++) {
                uint32_t addr = bBase + (wn * 32 + bt * 16 + lrow) * ROWB
                              + k0 * 2 + lcol;
                ldmatrix_x4(bf[bt][0], bf[bt][1], bf[bt][2], bf[bt][3], addr);
            }
#pragma unroll
            for (int mt = 0; mt < 4; mt++)
#pragma unroll
                for (int nt = 0; nt < 4; nt++) {
                    const int bt = nt >> 1, sel = nt & 1;
                    mma_bf16(acc[mt][nt], af[mt], bf[bt][sel], bf[bt][sel + 2]);
                }
        }
        __syncthreads();
    }

    const int er = lane >> 2;
    const int ec = (lane & 3) * 2;
#pragma unroll
    for (int mt = 0; mt < 4; mt++) {
#pragma unroll
        for (int nt = 0; nt < 4; nt++) {
            const int col = bn + wn * 32 + nt * 8 + ec;
            const float b0 = bias[col], b1 = bias[col + 1];
            const int r0 = bm + wm * 64 + mt * 16 + er;
            float v00 = acc[mt][nt][0] + b0, v01 = acc[mt][nt][1] + b1;
            float v10 = acc[mt][nt][2] + b0, v11 = acc[mt][nt][3] + b1;
            if (MODE == 0) {
                *(float2*)(C + (size_t)r0 * N + col) = {v00, v01};
                *(float2*)(C + (size_t)(r0 + 8) * N + col) = {v10, v11};
            } else {
                // scatter into fp16 hi/lo planes [B,H,S,64]; Q scaled by 1/8
                const int type = col >> 10;           // 0=Q 1=K 2=V
                const int rem = col & 1023;
                const int h = rem >> 6;
                const int d = rem & 63;
                if (type == 0) { v00 *= 0.125f; v01 *= 0.125f;
                                 v10 *= 0.125f; v11 *= 0.125f; }
                const int b = r0 >> 11;
                const int s0 = r0 & 2047;
                size_t rowbase = (((size_t)(b * HEADS + h)) * SEQ + s0) * HDIM + d;
                __half* hp = f16out + (size_t)(type * 2) * PLANE;
                __half* lp = hp + PLANE;
#pragma unroll
                for (int rr = 0; rr < 2; rr++) {
                    float vx = rr ? v10 : v00;
                    float vy = rr ? v11 : v01;
                    __half hx = __float2half_rn(vx), hy = __float2half_rn(vy);
                    __half lx = __float2half_rn(vx - __half2float(hx));
                    __half ly = __float2half_rn(vy - __half2float(hy));
                    size_t o = rowbase + (size_t)rr * 8 * HDIM;
                    { __half2 t = {hx, hy}; *(__half2*)(hp + o) = t; }
                    { __half2 t = {lx, ly}; *(__half2*)(lp + o) = t; }
                }
            }
        }
    }
}

// ===========================================================================
// Flash attention on tensor cores, pre-split fp16 operands, cp.async pipelined.
// CTA: 128 queries x 64 keys/tile, 8 warps (16 q-rows each, full key tile).
// smem: loop = 2 stages x (Kh|Kl|Vh|Vl @ 64x144B) = 73728 B; Q staged in stage0.
// Output written directly as split-bf16 hi|lo|hi rows of abuf.
// ===========================================================================
#define FROWB 144
#define FTILE 9216                       // 64 * 144
#define FSTAGE (4 * FTILE)               // 36864
#define FLASH_SMEM (2 * FSTAGE)          // 73728

__global__ __launch_bounds__(256, 1) void flash_mma(
    const __half* __restrict__ f16, __nv_bfloat16* __restrict__ abuf)
{
    extern __shared__ __align__(16) char fsm[];
    const uint32_t sb = smem_u32(fsm);

    const int tid = threadIdx.x;
    const int w = tid >> 5;
    const int lane = tid & 31;
    const int er = lane >> 2;
    const int ec = (lane & 3) * 2;
    const int lrow = lane & 15;
    const int lcol = (lane >> 4) * 16;

    const int qt = (int)gridDim.x - 1 - (int)blockIdx.x;   // heavy tiles first
    const int h = blockIdx.y;
    const int b = blockIdx.z;
    const int q0 = qt * 128;

    const size_t hb = ((size_t)(b * HEADS + h)) * SEQ * HDIM;
    const __half* Qhg = f16 + hb;                 // plane 0
    const __half* Qlg = f16 + PLANE + hb;         // plane 1
    const __half* Khg = f16 + 2 * PLANE + hb;
    const __half* Klg = f16 + 3 * PLANE + hb;
    const __half* Vhg = f16 + 4 * PLANE + hb;
    const __half* Vlg = f16 + 5 * PLANE + hb;

    // ---- stage Q hi/lo (128 rows x 128 B) into stage-0 area, get fragments
#pragma unroll
    for (int i = 0; i < 8; i++) {
        int idx = tid + i * 256;          // 2048 chunks: op(1b) | row(7b) | c(3b)
        int op = idx >> 10;
        int within = idx & 1023;
        int r = within >> 3;
        int c = within & 7;
        const __half* src = (op ? Qlg : Qhg) + (size_t)(q0 + r) * HDIM + c * 8;
        cp_async16(sb + op * 18432 + r * FROWB + c * 16, src);
    }
    CP_COMMIT();
    CP_WAIT(0);
    __syncthreads();

    uint32_t qh[4][4], ql[4][4];
#pragma unroll
    for (int ks = 0; ks < 4; ks++) {
        uint32_t a = sb + (w * 16 + lrow) * FROWB + ks * 32 + lcol;
        ldmatrix_x4(qh[ks][0], qh[ks][1], qh[ks][2], qh[ks][3], a);
        uint32_t a2 = sb + 18432 + (w * 16 + lrow) * FROWB + ks * 32 + lcol;
        ldmatrix_x4(ql[ks][0], ql[ks][1], ql[ks][2], ql[ks][3], a2);
    }
    __syncthreads();

    float o[8][4];
#pragma unroll
    for (int nf = 0; nf < 8; nf++)
#pragma unroll
        for (int r = 0; r < 4; r++) o[nf][r] = 0.0f;
    float mprev[2] = {-INFINITY, -INFINITY};
    float lsum[2] = {0.0f, 0.0f};

    const int nkt = 2 * qt + 2;

    // issue K/V tile kt into stage st
    auto issue_tile = [&](int kt, int st) {
        const int k0 = kt * 64;
        const uint32_t sbase = sb + st * FSTAGE;
#pragma unroll
        for (int i = 0; i < 8; i++) {
            int idx = tid + i * 256;      // 2048 chunks: op(2b) | row(6b) | c(3b)
            int op = idx >> 9;
            int within = idx & 511;
            int r = within >> 3;
            int c = within & 7;
            const __half* base = (op == 0) ? Khg : (op == 1) ? Klg
                               : (op == 2) ? Vhg : Vlg;
            cp_async16(sbase + op * FTILE + r * FROWB + c * 16,
                       base + (size_t)(k0 + r) * HDIM + c * 8);
        }
        CP_COMMIT();
    };

    issue_tile(0, 0);

    for (int kt = 0; kt < nkt; kt++) {
        const int k0 = kt * 64;
        if (kt + 1 < nkt) { issue_tile(kt + 1, (kt + 1) & 1); CP_WAIT(1); }
        else              { CP_WAIT(0); }
        __syncthreads();

        const uint32_t Kh = sb + (kt & 1) * FSTAGE;
        const uint32_t Kl = Kh + FTILE;
        const uint32_t Vh = Kh + 2 * FTILE;
        const uint32_t Vl = Kh + 3 * FTILE;

        // ---- S = Q K^T (qh*kh + qh*kl + ql*kh) ----
        float s[8][4];
#pragma unroll
        for (int nf = 0; nf < 8; nf++)
#pragma unroll
            for (int r = 0; r < 4; r++) s[nf][r] = 0.0f;

#pragma unroll
        for (int ks = 0; ks < 4; ks++) {
#pragma unroll
            for (int g = 0; g < 4; g++) {
                uint32_t kh4[4], kl4[4];
                uint32_t a = Kh + (g * 16 + lrow) * FROWB + ks * 32 + lcol;
                ldmatrix_x4(kh4[0], kh4[1], kh4[2], kh4[3], a);
                uint32_t a2 = Kl + (g * 16 + lrow) * FROWB + ks * 32 + lcol;
                ldmatrix_x4(kl4[0], kl4[1], kl4[2], kl4[3], a2);
                mma_f16(s[2 * g],     qh[ks], kh4[0], kh4[2]);
                mma_f16(s[2 * g],     qh[ks], kl4[0], kl4[2]);
                mma_f16(s[2 * g],     ql[ks], kh4[0], kh4[2]);
                mma_f16(s[2 * g + 1], qh[ks], kh4[1], kh4[3]);
                mma_f16(s[2 * g + 1], qh[ks], kl4[1], kl4[3]);
                mma_f16(s[2 * g + 1], ql[ks], kh4[1], kh4[3]);
            }
        }

        // ---- causal mask ----
        if (kt >= 2 * qt) {
            const int row0 = q0 + w * 16 + er;
#pragma unroll
            for (int nf = 0; nf < 8; nf++) {
                const int keyb = k0 + (nf >> 1) * 16 + (nf & 1) * 8 + ec;
#pragma unroll
                for (int r = 0; r < 4; r++) {
                    int key = keyb + (r & 1);
                    int row = row0 + (r >> 1) * 8;
                    if (key > row) s[nf][r] = -INFINITY;
                }
            }
        }

        // ---- online softmax ----
        float mx0 = -INFINITY, mx1 = -INFINITY;
#pragma unroll
        for (int nf = 0; nf < 8; nf++) {
            mx0 = fmaxf(mx0, fmaxf(s[nf][0], s[nf][1]));
            mx1 = fmaxf(mx1, fmaxf(s[nf][2], s[nf][3]));
        }
        mx0 = fmaxf(mx0, __shfl_xor_sync(0xffffffffu, mx0, 1));
        mx0 = fmaxf(mx0, __shfl_xor_sync(0xffffffffu, mx0, 2));
        mx1 = fmaxf(mx1, __shfl_xor_sync(0xffffffffu, mx1, 1));
        mx1 = fmaxf(mx1, __shfl_xor_sync(0xffffffffu, mx1, 2));

        float mn0 = fmaxf(mprev[0], mx0);
        float mn1 = fmaxf(mprev[1], mx1);
        float al0 = __expf(mprev[0] - mn0);
        float al1 = __expf(mprev[1] - mn1);
        float sum0 = 0.0f, sum1 = 0.0f;
#pragma unroll
        for (int nf = 0; nf < 8; nf++) {
            s[nf][0] = __expf(s[nf][0] - mn0);
            s[nf][1] = __expf(s[nf][1] - mn0);
            s[nf][2] = __expf(s[nf][2] - mn1);
            s[nf][3] = __expf(s[nf][3] - mn1);
            sum0 += s[nf][0] + s[nf][1];
            sum1 += s[nf][2] + s[nf][3];
        }
        sum0 += __shfl_xor_sync(0xffffffffu, sum0, 1);
        sum0 += __shfl_xor_sync(0xffffffffu, sum0, 2);
        sum1 += __shfl_xor_sync(0xffffffffu, sum1, 1);
        sum1 += __shfl_xor_sync(0xffffffffu, sum1, 2);
        lsum[0] = lsum[0] * al0 + sum0;
        lsum[1] = lsum[1] * al1 + sum1;
        mprev[0] = mn0;
        mprev[1] = mn1;
#pragma unroll
        for (int nf = 0; nf < 8; nf++) {
            o[nf][0] *= al0; o[nf][1] *= al0;
            o[nf][2] *= al1; o[nf][3] *= al1;
        }

        // ---- O += P V ----
#pragma unroll
        for (int kk = 0; kk < 4; kk++) {
            uint32_t pa[4];
            pa[0] = packh2(s[2 * kk][0], s[2 * kk][1]);
            pa[1] = packh2(s[2 * kk][2], s[2 * kk][3]);
            pa[2] = packh2(s[2 * kk + 1][0], s[2 * kk + 1][1]);
            pa[3] = packh2(s[2 * kk + 1][2], s[2 * kk + 1][3]);
#pragma unroll
            for (int g = 0; g < 4; g++) {
                uint32_t vh4[4], vl4[4];
                uint32_t a = Vh + (kk * 16 + lrow) * FROWB + g * 32 + lcol;
                ldmatrix_x4_trans(vh4[0], vh4[1], vh4[2], vh4[3], a);
                uint32_t a2 = Vl + (kk * 16 + lrow) * FROWB + g * 32 + lcol;
                ldmatrix_x4_trans(vl4[0], vl4[1], vl4[2], vl4[3], a2);
                mma_f16(o[2 * g],     pa, vh4[0], vh4[1]);
                mma_f16(o[2 * g],     pa, vl4[0], vl4[1]);
                mma_f16(o[2 * g + 1], pa, vh4[2], vh4[3]);
                mma_f16(o[2 * g + 1], pa, vl4[2], vl4[3]);
            }
        }
        __syncthreads();   // stage (kt&1) free for reuse at iter kt+1
    }

    // ---- normalize + write abuf rows directly as split-bf16 hi|lo|hi ----
    const float inv0 = 1.0f / lsum[0];
    const float inv1 = 1.0f / lsum[1];
    const int mrow0 = b * SEQ + q0 + w * 16 + er;
#pragma unroll
    for (int nf = 0; nf < 8; nf++) {
        const int c = h * HDIM + nf * 8 + ec;
#pragma unroll
        for (int rr = 0; rr < 2; rr++) {
            float vx = o[nf][2 * rr + 0] * (rr ? inv1 : inv0);
            float vy = o[nf][2 * rr + 1] * (rr ? inv1 : inv0);
            __nv_bfloat16 hx = __float2bfloat16_rn(vx);
            __nv_bfloat16 hy = __float2bfloat16_rn(vy);
            __nv_bfloat16 lx = __float2bfloat16_rn(vx - __bfloat162float(hx));
            __nv_bfloat16 ly = __float2bfloat16_rn(vy - __bfloat162float(hy));
            __nv_bfloat16* row = abuf + (size_t)(mrow0 + rr * 8) * K3 + c;
            { __nv_bfloat162 t = {hx, hy}; *(__nv_bfloat162*)(row) = t;
              *(__nv_bfloat162*)(row + 2048) = t; }
            { __nv_bfloat162 t = {lx, ly}; *(__nv_bfloat162*)(row + 1024) = t; }
        }
    }
}

// ===========================================================================
// Residual + LayerNorm (unchanged)
// ===========================================================================
__global__ __launch_bounds__(256) void ln_kernel(
    const float* __restrict__ x, const float* __restrict__ att,
    const float* __restrict__ gamma, const float* __restrict__ beta,
    float* __restrict__ out)
{
    __shared__ float red[2][8];
    const int row = blockIdx.x;
    const int tid = threadIdx.x;
    const float* xr = x + (size_t)row * DIM;
    const float* ar = att + (size_t)row * DIM;

    float v[4];
    float s = 0.0f, s2 = 0.0f;
#pragma unroll
    for (int i = 0; i < 4; i++) {
        int c = tid + i * 256;
        float t = xr[c] + ar[c];
        v[i] = t;
        s += t;
        s2 += t * t;
    }
#pragma unroll
    for (int off = 16; off >= 1; off >>= 1) {
        s  += __shfl_xor_sync(0xffffffffu, s, off);
        s2 += __shfl_xor_sync(0xffffffffu, s2, off);
    }
    if ((tid & 31) == 0) { red[0][tid >> 5] = s; red[1][tid >> 5] = s2; }
    __syncthreads();
    s = 0.0f; s2 = 0.0f;
#pragma unroll
    for (int k = 0; k < 8; k++) { s += red[0][k]; s2 += red[1][k]; }

    const float mu = s * (1.0f / DIM);
    const float var = s2 * (1.0f / DIM) - mu * mu;
    const float rs = rsqrtf(var + 1e-5f);

    float* orow = out + (size_t)row * DIM;
#pragma unroll
    for (int i = 0; i < 4; i++) {
        int c = tid + i * 256;
        orow[c] = (v[i] - mu) * rs * gamma[c] + beta[c];
    }
}

// ===========================================================================
// Launch
// ===========================================================================
extern "C" void kernel_launch(void* const* d_in, const int* in_sizes, int n_in,
                              void* d_out, int out_size)
{
    const float* x      = (const float*)d_in[0];
    const float* w_in   = (const float*)d_in[1];
    const float* b_in   = (const float*)d_in[2];
    const float* w_out  = (const float*)d_in[3];
    const float* b_out  = (const float*)d_in[4];
    const float* gamma  = (const float*)d_in[5];
    const float* beta   = (const float*)d_in[6];
    float* out = (float*)d_out;

    void* p;
    cudaGetSymbolAddress(&p, g_abuf);  __nv_bfloat16* abuf = (__nv_bfloat16*)p;
    cudaGetSymbolAddress(&p, g_bbuf);  __nv_bfloat16* bbuf = (__nv_bfloat16*)p;
    cudaGetSymbolAddress(&p, g_f16);   __half* f16 = (__half*)p;
    cudaGetSymbolAddress(&p, g_att);   float* att = (float*)p;

    cudaFuncSetAttribute(gemm_mma<0>,
                         cudaFuncAttributeMaxDynamicSharedMemorySize, GEMM_SMEM);
    cudaFuncSetAttribute(gemm_mma<1>,
                         cudaFuncAttributeMaxDynamicSharedMemorySize, GEMM_SMEM);
    cudaFuncSetAttribute(flash_mma,
                         cudaFuncAttributeMaxDynamicSharedMemorySize, FLASH_SMEM);

    // 1) split-convert x (A side) and in_proj_w (B side)
    split_bf16_kernel<<<MROWS, 256>>>(x, abuf, 0);
    split_bf16_kernel<<<QKVN, 256>>>(w_in, bbuf, 1);

    // 2) QKV projection -> pre-split fp16 hi/lo planes (Q scaled by 1/8)
    gemm_mma<1><<<dim3(QKVN / 128, MROWS / 128), 256, GEMM_SMEM>>>(
        abuf, bbuf, b_in, nullptr, f16, QKVN);

    // 3) causal flash attention -> abuf (split-bf16 hi|lo|hi)
    flash_mma<<<dim3(SEQ / 128, HEADS, BATCH), 256, FLASH_SMEM>>>(f16, abuf);

    // 4) out projection: [8192,1024]
    split_bf16_kernel<<<DIM, 256>>>(w_out, bbuf, 1);
    gemm_mma<0><<<dim3(DIM / 128, MROWS / 128), 256, GEMM_SMEM>>>(
        abuf, bbuf, b_out, att, nullptr, DIM);

    // 5) residual + layernorm
    ln_kernel<<<MROWS, 256>>>(x, att, gamma, beta, out);
}

// round 8
// speedup vs baseline: 2.4782x; 1.0933x over previous
#include <cuda_runtime.h>
#include <cuda_fp16.h>
#include <cuda_bf16.h>
#include <stdint.h>
#include <math.h>

// Problem constants
#define BATCH 4
#define SEQ   2048
#define DIM   1024
#define HEADS 16
#define HDIM  64
#define MROWS (BATCH * SEQ)          // 8192
#define QKVN  (3 * DIM)              // 3072
#define K3    3072                   // split-bf16 K (3 * 1024)
#define K2    2048                   // split-fp16 K (2 * 1024) for out-proj
#define PLANE ((size_t)BATCH * HEADS * SEQ * HDIM)   // 8388608 halves / plane

// Scratch (device globals; no dynamic allocation allowed)
__device__ __nv_bfloat16 g_abuf[(size_t)MROWS * K3];   // A operand (bf16 or f16 reuse)
__device__ __nv_bfloat16 g_bbuf[(size_t)QKVN * K3];    // B operand
__device__ __half g_wo16[(size_t)DIM * K2];            // out_w fp16 h|h
__device__ __half g_f16[6 * PLANE];                    // Qh,Ql,Kh,Kl,Vh,Vl planes
__device__ float g_att[(size_t)MROWS * DIM];           // out-proj result

// ===========================================================================
// Helpers (base-ISA only: cp.async, ldmatrix, mma.sync)
// ===========================================================================
__device__ __forceinline__ uint32_t smem_u32(const void* p) {
    uint32_t a;
    asm("{ .reg .u64 t; cvta.to.shared.u64 t, %1; cvt.u32.u64 %0, t; }"
        : "=r"(a) : "l"(p));
    return a;
}
__device__ __forceinline__ void cp_async16(uint32_t dst, const void* src) {
    asm volatile("cp.async.cg.shared.global [%0], [%1], 16;"
                 :: "r"(dst), "l"(src) : "memory");
}
#define CP_COMMIT() asm volatile("cp.async.commit_group;" ::: "memory")
#define CP_WAIT(n)  asm volatile("cp.async.wait_group %0;" :: "n"(n) : "memory")

__device__ __forceinline__ void ldmatrix_x4(uint32_t& r0, uint32_t& r1,
                                            uint32_t& r2, uint32_t& r3,
                                            uint32_t addr) {
    asm volatile("ldmatrix.sync.aligned.m8n8.x4.shared.b16 {%0,%1,%2,%3}, [%4];"
                 : "=r"(r0), "=r"(r1), "=r"(r2), "=r"(r3) : "r"(addr));
}
__device__ __forceinline__ void ldmatrix_x4_trans(uint32_t& r0, uint32_t& r1,
                                                  uint32_t& r2, uint32_t& r3,
                                                  uint32_t addr) {
    asm volatile("ldmatrix.sync.aligned.m8n8.x4.trans.shared.b16 {%0,%1,%2,%3}, [%4];"
                 : "=r"(r0), "=r"(r1), "=r"(r2), "=r"(r3) : "r"(addr));
}
__device__ __forceinline__ void mma_bf16(float* d, const uint32_t* a,
                                         uint32_t b0, uint32_t b1) {
    asm volatile(
        "mma.sync.aligned.m16n8k16.row.col.f32.bf16.bf16.f32 "
        "{%0,%1,%2,%3}, {%4,%5,%6,%7}, {%8,%9}, {%0,%1,%2,%3};"
        : "+f"(d[0]), "+f"(d[1]), "+f"(d[2]), "+f"(d[3])
        : "r"(a[0]), "r"(a[1]), "r"(a[2]), "r"(a[3]), "r"(b0), "r"(b1));
}
__device__ __forceinline__ void mma_f16(float* d, const uint32_t* a,
                                        uint32_t b0, uint32_t b1) {
    asm volatile(
        "mma.sync.aligned.m16n8k16.row.col.f32.f16.f16.f32 "
        "{%0,%1,%2,%3}, {%4,%5,%6,%7}, {%8,%9}, {%0,%1,%2,%3};"
        : "+f"(d[0]), "+f"(d[1]), "+f"(d[2]), "+f"(d[3])
        : "r"(a[0]), "r"(a[1]), "r"(a[2]), "r"(a[3]), "r"(b0), "r"(b1));
}
__device__ __forceinline__ uint32_t packh2(float a, float b) {
    __half2 h = __floats2half2_rn(a, b);
    return *(uint32_t*)&h;
}

// ===========================================================================
// Split fp32 -> (hi, lo) bf16 along K3: mode 0 (A): hi|lo|hi, mode 1 (B): hi|hi|lo
// ===========================================================================
__global__ __launch_bounds__(256) void split_bf16_kernel(
    const float* __restrict__ in, __nv_bfloat16* __restrict__ out, int mode)
{
    const int i = blockIdx.x * 256 + threadIdx.x;
    const int row = i >> 8;
    const int c4 = (i & 255) * 4;
    float4 v = ((const float4*)in)[i];

    __nv_bfloat16 h0 = __float2bfloat16_rn(v.x);
    __nv_bfloat16 h1 = __float2bfloat16_rn(v.y);
    __nv_bfloat16 h2 = __float2bfloat16_rn(v.z);
    __nv_bfloat16 h3 = __float2bfloat16_rn(v.w);
    __nv_bfloat16 l0 = __float2bfloat16_rn(v.x - __bfloat162float(h0));
    __nv_bfloat16 l1 = __float2bfloat16_rn(v.y - __bfloat162float(h1));
    __nv_bfloat16 l2 = __float2bfloat16_rn(v.z - __bfloat162float(h2));
    __nv_bfloat16 l3 = __float2bfloat16_rn(v.w - __bfloat162float(h3));

    uint2 H, L;
    H.x = (uint32_t)__bfloat16_as_ushort(h0) | ((uint32_t)__bfloat16_as_ushort(h1) << 16);
    H.y = (uint32_t)__bfloat16_as_ushort(h2) | ((uint32_t)__bfloat16_as_ushort(h3) << 16);
    L.x = (uint32_t)__bfloat16_as_ushort(l0) | ((uint32_t)__bfloat16_as_ushort(l1) << 16);
    L.y = (uint32_t)__bfloat16_as_ushort(l2) | ((uint32_t)__bfloat16_as_ushort(l3) << 16);

    size_t ob = (size_t)row * K3 + c4;
    *(uint2*)(out + ob)        = H;
    *(uint2*)(out + ob + 1024) = mode ? H : L;
    *(uint2*)(out + ob + 2048) = mode ? L : H;
}

// ===========================================================================
// Split fp32 -> fp16 hi duplicated (B side of 2-term out-proj): out[r][c]=h, [r][1024+c]=h
// ===========================================================================
__global__ __launch_bounds__(256) void split_f16_w_kernel(
    const float* __restrict__ in, __half* __restrict__ out)
{
    const int i = blockIdx.x * 256 + threadIdx.x;
    const int row = i >> 8;
    const int c4 = (i & 255) * 4;
    float4 v = ((const float4*)in)[i];
    uint2 H;
    H.x = packh2(v.x, v.y);
    H.y = packh2(v.z, v.w);
    size_t ob = (size_t)row * K2 + c4;
    *(uint2*)(out + ob)        = H;
    *(uint2*)(out + ob + 1024) = H;
}

// ===========================================================================
// mma.sync GEMM skeleton: 128x128 tile, BK=32, 3-stage cp.async, 8 warps.
// DT=0: bf16 operands, KLEN=K3.  DT=1: fp16 operands, KLEN=K2.
// MODE=0: fp32 out + bias.  MODE=1: QKV -> fp16 hi/lo planes (Q scaled 1/8).
// ===========================================================================
#define BK 32
#define STG 3
#define ROWB 80
#define TILEB (128 * ROWB)
#define GEMM_SMEM (2 * STG * TILEB)

template <typename T>
__device__ __forceinline__ void g_load_tiles_t(
    const T* __restrict__ Ab, const T* __restrict__ Bb,
    uint32_t sA, uint32_t sB, int stage, int chunk, int tid, int klen)
{
    const uint32_t sa = sA + stage * TILEB;
    const uint32_t sb = sB + stage * TILEB;
#pragma unroll
    for (int i = 0; i < 2; i++) {
        int idx = tid + i * 256;
        int row = idx >> 2;
        int cc = idx & 3;
        uint32_t dst = row * ROWB + cc * 16;
        cp_async16(sa + dst, Ab + (size_t)row * klen + chunk * BK + cc * 8);
        cp_async16(sb + dst, Bb + (size_t)row * klen + chunk * BK + cc * 8);
    }
}

template <int MODE, int DT>
__global__ __launch_bounds__(256, 2) void gemm_mma(
    const void* __restrict__ Av, const void* __restrict__ Bv,
    const float* __restrict__ bias, float* __restrict__ C,
    __half* __restrict__ f16out, int N, int klen)
{
    extern __shared__ __align__(16) char smem[];
    const uint32_t sA = smem_u32(smem);
    const uint32_t sB = sA + STG * TILEB;

    const int tid = threadIdx.x;
    const int warp = tid >> 5;
    const int lane = tid & 31;
    const int wm = warp >> 2;
    const int wn = warp & 3;
    const int bm = blockIdx.y * 128;
    const int bn = blockIdx.x * 128;
    const int NC = klen / BK;

    const __nv_bfloat16* Ab = (const __nv_bfloat16*)Av + (size_t)bm * klen;
    const __nv_bfloat16* Bb = (const __nv_bfloat16*)Bv + (size_t)bn * klen;

    float acc[4][4][4];
#pragma unroll
    for (int mt = 0; mt < 4; mt++)
#pragma unroll
        for (int nt = 0; nt < 4; nt++)
#pragma unroll
            for (int r = 0; r < 4; r++) acc[mt][nt][r] = 0.0f;

    const int lrow = lane & 15;
    const int lcol = (lane >> 4) * 16;

#pragma unroll
    for (int c = 0; c < STG - 1; c++) {
        g_load_tiles_t(Ab, Bb, sA, sB, c, c, tid, klen);
        CP_COMMIT();
    }

    for (int c = 0; c < NC; c++) {
        CP_WAIT(STG - 2);
        __syncthreads();

        const int t = c + STG - 1;
        if (t < NC) g_load_tiles_t(Ab, Bb, sA, sB, t % STG, t, tid, klen);
        CP_COMMIT();

        const int s = c % STG;
        const uint32_t aBase = sA + s * TILEB;
        const uint32_t bBase = sB + s * TILEB;

#pragma unroll
        for (int ks = 0; ks < 2; ks++) {
            const int k0 = ks * 16;
            uint32_t af[4][4];
#pragma unroll
            for (int mt = 0; mt < 4; mt++) {
                uint32_t addr = aBase + (wm * 64 + mt * 16 + lrow) * ROWB
                              + k0 * 2 + lcol;
                ldmatrix_x4(af[mt][0], af[mt][1], af[mt][2], af[mt][3], addr);
            }
            uint32_t bf[2][4];
#pragma unroll
            for (int bt = 0; bt < 2; bt++) {
                uint32_t addr = bBase + (wn * 32 + bt * 16 + lrow) * ROWB
                              + k0 * 2 + lcol;
                ldmatrix_x4(bf[bt][0], bf[bt][1], bf[bt][2], bf[bt][3], addr);
            }
#pragma unroll
            for (int mt = 0; mt < 4; mt++)
#pragma unroll
                for (int nt = 0; nt < 4; nt++) {
                    const int bt = nt >> 1, sel = nt & 1;
                    if (DT == 0)
                        mma_bf16(acc[mt][nt], af[mt], bf[bt][sel], bf[bt][sel + 2]);
                    else
                        mma_f16(acc[mt][nt], af[mt], bf[bt][sel], bf[bt][sel + 2]);
                }
        }
        __syncthreads();
    }

    const int er = lane >> 2;
    const int ec = (lane & 3) * 2;
#pragma unroll
    for (int mt = 0; mt < 4; mt++) {
#pragma unroll
        for (int nt = 0; nt < 4; nt++) {
            const int col = bn + wn * 32 + nt * 8 + ec;
            const float b0 = bias[col], b1 = bias[col + 1];
            const int r0 = bm + wm * 64 + mt * 16 + er;
            float v00 = acc[mt][nt][0] + b0, v01 = acc[mt][nt][1] + b1;
            float v10 = acc[mt][nt][2] + b0, v11 = acc[mt][nt][3] + b1;
            if (MODE == 0) {
                *(float2*)(C + (size_t)r0 * N + col) = {v00, v01};
                *(float2*)(C + (size_t)(r0 + 8) * N + col) = {v10, v11};
            } else {
                const int type = col >> 10;           // 0=Q 1=K 2=V
                const int rem = col & 1023;
                const int h = rem >> 6;
                const int d = rem & 63;
                if (type == 0) { v00 *= 0.125f; v01 *= 0.125f;
                                 v10 *= 0.125f; v11 *= 0.125f; }
                const int b = r0 >> 11;
                const int s0 = r0 & 2047;
                size_t rowbase = (((size_t)(b * HEADS + h)) * SEQ + s0) * HDIM + d;
                __half* hp = f16out + (size_t)(type * 2) * PLANE;
                __half* lp = hp + PLANE;
#pragma unroll
                for (int rr = 0; rr < 2; rr++) {
                    float vx = rr ? v10 : v00;
                    float vy = rr ? v11 : v01;
                    __half hx = __float2half_rn(vx), hy = __float2half_rn(vy);
                    __half lx = __float2half_rn(vx - __half2float(hx));
                    __half ly = __float2half_rn(vy - __half2float(hy));
                    size_t o = rowbase + (size_t)rr * 8 * HDIM;
                    { __half2 t = {hx, hy}; *(__half2*)(hp + o) = t; }
                    { __half2 t = {lx, ly}; *(__half2*)(lp + o) = t; }
                }
            }
        }
    }
}

// ===========================================================================
// Flash attention (tensor cores). 2 CTAs/SM: Q fragments re-LDSM'd from a
// persistent smem region each tile (frees 32 regs -> fits 128/thread).
// smem = Qh|Ql (36864) + 2 stages x (Kh|Kl|Vh|Vl @ 64x144B) = 110592 B.
// Output written as fp16 h|l rows (K2 layout) for the 2-term out-proj.
// ===========================================================================
#define FROWB 144
#define FTILE 9216                       // 64 * 144
#define FSTAGE (4 * FTILE)               // 36864
#define FQREG  (2 * 128 * FROWB)         // 36864 (Qh | Ql)
#define FLASH_SMEM (FQREG + 2 * FSTAGE)  // 110592

__global__ __launch_bounds__(256, 2) void flash_mma(
    const __half* __restrict__ f16, __half* __restrict__ ctx16)
{
    extern __shared__ __align__(16) char fsm[];
    const uint32_t sb = smem_u32(fsm);

    const int tid = threadIdx.x;
    const int w = tid >> 5;
    const int lane = tid & 31;
    const int er = lane >> 2;
    const int ec = (lane & 3) * 2;
    const int lrow = lane & 15;
    const int lcol = (lane >> 4) * 16;

    const int qt = (int)gridDim.x - 1 - (int)blockIdx.x;   // heavy tiles first
    const int h = blockIdx.y;
    const int b = blockIdx.z;
    const int q0 = qt * 128;

    const size_t hb = ((size_t)(b * HEADS + h)) * SEQ * HDIM;
    const __half* Qhg = f16 + hb;
    const __half* Qlg = f16 + PLANE + hb;
    const __half* Khg = f16 + 2 * PLANE + hb;
    const __half* Klg = f16 + 3 * PLANE + hb;
    const __half* Vhg = f16 + 4 * PLANE + hb;
    const __half* Vlg = f16 + 5 * PLANE + hb;

    // ---- stage Q hi/lo into the persistent region ----
#pragma unroll
    for (int i = 0; i < 8; i++) {
        int idx = tid + i * 256;          // 2048 chunks: op(1b) | row(7b) | c(3b)
        int op = idx >> 10;
        int within = idx & 1023;
        int r = within >> 3;
        int c = within & 7;
        const __half* src = (op ? Qlg : Qhg) + (size_t)(q0 + r) * HDIM + c * 8;
        cp_async16(sb + op * 18432 + r * FROWB + c * 16, src);
    }
    CP_COMMIT();

    float o[8][4];
#pragma unroll
    for (int nf = 0; nf < 8; nf++)
#pragma unroll
        for (int r = 0; r < 4; r++) o[nf][r] = 0.0f;
    float mprev[2] = {-INFINITY, -INFINITY};
    float lsum[2] = {0.0f, 0.0f};

    const int nkt = 2 * qt + 2;

    auto issue_tile = [&](int kt, int st) {
        const int k0 = kt * 64;
        const uint32_t sbase = sb + FQREG + st * FSTAGE;
#pragma unroll
        for (int i = 0; i < 8; i++) {
            int idx = tid + i * 256;      // 2048 chunks: op(2b) | row(6b) | c(3b)
            int op = idx >> 9;
            int within = idx & 511;
            int r = within >> 3;
            int c = within & 7;
            const __half* base = (op == 0) ? Khg : (op == 1) ? Klg
                               : (op == 2) ? Vhg : Vlg;
            cp_async16(sbase + op * FTILE + r * FROWB + c * 16,
                       base + (size_t)(k0 + r) * HDIM + c * 8);
        }
        CP_COMMIT();
    };

    issue_tile(0, 0);

    for (int kt = 0; kt < nkt; kt++) {
        const int k0 = kt * 64;
        if (kt + 1 < nkt) { issue_tile(kt + 1, (kt + 1) & 1); CP_WAIT(1); }
        else              { CP_WAIT(0); }
        __syncthreads();

        const uint32_t Kh = sb + FQREG + (kt & 1) * FSTAGE;
        const uint32_t Kl = Kh + FTILE;
        const uint32_t Vh = Kh + 2 * FTILE;
        const uint32_t Vl = Kh + 3 * FTILE;

        // ---- S = Q K^T (qh*kh + qh*kl + ql*kh) ----
        float s[8][4];
#pragma unroll
        for (int nf = 0; nf < 8; nf++)
#pragma unroll
            for (int r = 0; r < 4; r++) s[nf][r] = 0.0f;

#pragma unroll
        for (int ks = 0; ks < 4; ks++) {
            uint32_t qh4[4], ql4[4];
            uint32_t qa = sb + (w * 16 + lrow) * FROWB + ks * 32 + lcol;
            ldmatrix_x4(qh4[0], qh4[1], qh4[2], qh4[3], qa);
            ldmatrix_x4(ql4[0], ql4[1], ql4[2], ql4[3], qa + 18432);
#pragma unroll
            for (int g = 0; g < 4; g++) {
                uint32_t kh4[4], kl4[4];
                uint32_t a = Kh + (g * 16 + lrow) * FROWB + ks * 32 + lcol;
                ldmatrix_x4(kh4[0], kh4[1], kh4[2], kh4[3], a);
                uint32_t a2 = Kl + (g * 16 + lrow) * FROWB + ks * 32 + lcol;
                ldmatrix_x4(kl4[0], kl4[1], kl4[2], kl4[3], a2);
                mma_f16(s[2 * g],     qh4, kh4[0], kh4[2]);
                mma_f16(s[2 * g],     qh4, kl4[0], kl4[2]);
                mma_f16(s[2 * g],     ql4, kh4[0], kh4[2]);
                mma_f16(s[2 * g + 1], qh4, kh4[1], kh4[3]);
                mma_f16(s[2 * g + 1], qh4, kl4[1], kl4[3]);
                mma_f16(s[2 * g + 1], ql4, kh4[1], kh4[3]);
            }
        }

        // ---- causal mask ----
        if (kt >= 2 * qt) {
            const int row0 = q0 + w * 16 + er;
#pragma unroll
            for (int nf = 0; nf < 8; nf++) {
                const int keyb = k0 + (nf >> 1) * 16 + (nf & 1) * 8 + ec;
#pragma unroll
                for (int r = 0; r < 4; r++) {
                    int key = keyb + (r & 1);
                    int row = row0 + (r >> 1) * 8;
                    if (key > row) s[nf][r] = -INFINITY;
                }
            }
        }

        // ---- online softmax ----
        float mx0 = -INFINITY, mx1 = -INFINITY;
#pragma unroll
        for (int nf = 0; nf < 8; nf++) {
            mx0 = fmaxf(mx0, fmaxf(s[nf][0], s[nf][1]));
            mx1 = fmaxf(mx1, fmaxf(s[nf][2], s[nf][3]));
        }
        mx0 = fmaxf(mx0, __shfl_xor_sync(0xffffffffu, mx0, 1));
        mx0 = fmaxf(mx0, __shfl_xor_sync(0xffffffffu, mx0, 2));
        mx1 = fmaxf(mx1, __shfl_xor_sync(0xffffffffu, mx1, 1));
        mx1 = fmaxf(mx1, __shfl_xor_sync(0xffffffffu, mx1, 2));

        float mn0 = fmaxf(mprev[0], mx0);
        float mn1 = fmaxf(mprev[1], mx1);
        float al0 = __expf(mprev[0] - mn0);
        float al1 = __expf(mprev[1] - mn1);
        float sum0 = 0.0f, sum1 = 0.0f;
#pragma unroll
        for (int nf = 0; nf < 8; nf++) {
            s[nf][0] = __expf(s[nf][0] - mn0);
            s[nf][1] = __expf(s[nf][1] - mn0);
            s[nf][2] = __expf(s[nf][2] - mn1);
            s[nf][3] = __expf(s[nf][3] - mn1);
            sum0 += s[nf][0] + s[nf][1];
            sum1 += s[nf][2] + s[nf][3];
        }
        sum0 += __shfl_xor_sync(0xffffffffu, sum0, 1);
        sum0 += __shfl_xor_sync(0xffffffffu, sum0, 2);
        sum1 += __shfl_xor_sync(0xffffffffu, sum1, 1);
        sum1 += __shfl_xor_sync(0xffffffffu, sum1, 2);
        lsum[0] = lsum[0] * al0 + sum0;
        lsum[1] = lsum[1] * al1 + sum1;
        mprev[0] = mn0;
        mprev[1] = mn1;
#pragma unroll
        for (int nf = 0; nf < 8; nf++) {
            o[nf][0] *= al0; o[nf][1] *= al0;
            o[nf][2] *= al1; o[nf][3] *= al1;
        }

        // ---- O += P V ----
#pragma unroll
        for (int kk = 0; kk < 4; kk++) {
            uint32_t pa[4];
            pa[0] = packh2(s[2 * kk][0], s[2 * kk][1]);
            pa[1] = packh2(s[2 * kk][2], s[2 * kk][3]);
            pa[2] = packh2(s[2 * kk + 1][0], s[2 * kk + 1][1]);
            pa[3] = packh2(s[2 * kk + 1][2], s[2 * kk + 1][3]);
#pragma unroll
            for (int g = 0; g < 4; g++) {
                uint32_t vh4[4], vl4[4];
                uint32_t a = Vh + (kk * 16 + lrow) * FROWB + g * 32 + lcol;
                ldmatrix_x4_trans(vh4[0], vh4[1], vh4[2], vh4[3], a);
                uint32_t a2 = Vl + (kk * 16 + lrow) * FROWB + g * 32 + lcol;
                ldmatrix_x4_trans(vl4[0], vl4[1], vl4[2], vl4[3], a2);
                mma_f16(o[2 * g],     pa, vh4[0], vh4[1]);
                mma_f16(o[2 * g],     pa, vl4[0], vl4[1]);
                mma_f16(o[2 * g + 1], pa, vh4[2], vh4[3]);
                mma_f16(o[2 * g + 1], pa, vl4[2], vl4[3]);
            }
        }
        __syncthreads();
    }

    // ---- normalize + write ctx as fp16 h|l rows ([MROWS][K2]) ----
    const float inv0 = 1.0f / lsum[0];
    const float inv1 = 1.0f / lsum[1];
    const int mrow0 = b * SEQ + q0 + w * 16 + er;
#pragma unroll
    for (int nf = 0; nf < 8; nf++) {
        const int c = h * HDIM + nf * 8 + ec;
#pragma unroll
        for (int rr = 0; rr < 2; rr++) {
            float vx = o[nf][2 * rr + 0] * (rr ? inv1 : inv0);
            float vy = o[nf][2 * rr + 1] * (rr ? inv1 : inv0);
            __half hx = __float2half_rn(vx), hy = __float2half_rn(vy);
            __half lx = __float2half_rn(vx - __half2float(hx));
            __half ly = __float2half_rn(vy - __half2float(hy));
            __half* row = ctx16 + (size_t)(mrow0 + rr * 8) * K2 + c;
            { __half2 t = {hx, hy}; *(__half2*)(row) = t; }
            { __half2 t = {lx, ly}; *(__half2*)(row + 1024) = t; }
        }
    }
}

// ===========================================================================
// Residual + LayerNorm (unchanged)
// ===========================================================================
__global__ __launch_bounds__(256) void ln_kernel(
    const float* __restrict__ x, const float* __restrict__ att,
    const float* __restrict__ gamma, const float* __restrict__ beta,
    float* __restrict__ out)
{
    __shared__ float red[2][8];
    const int row = blockIdx.x;
    const int tid = threadIdx.x;
    const float* xr = x + (size_t)row * DIM;
    const float* ar = att + (size_t)row * DIM;

    float v[4];
    float s = 0.0f, s2 = 0.0f;
#pragma unroll
    for (int i = 0; i < 4; i++) {
        int c = tid + i * 256;
        float t = xr[c] + ar[c];
        v[i] = t;
        s += t;
        s2 += t * t;
    }
#pragma unroll
    for (int off = 16; off >= 1; off >>= 1) {
        s  += __shfl_xor_sync(0xffffffffu, s, off);
        s2 += __shfl_xor_sync(0xffffffffu, s2, off);
    }
    if ((tid & 31) == 0) { red[0][tid >> 5] = s; red[1][tid >> 5] = s2; }
    __syncthreads();
    s = 0.0f; s2 = 0.0f;
#pragma unroll
    for (int k = 0; k < 8; k++) { s += red[0][k]; s2 += red[1][k]; }

    const float mu = s * (1.0f / DIM);
    const float var = s2 * (1.0f / DIM) - mu * mu;
    const float rs = rsqrtf(var + 1e-5f);

    float* orow = out + (size_t)row * DIM;
#pragma unroll
    for (int i = 0; i < 4; i++) {
        int c = tid + i * 256;
        orow[c] = (v[i] - mu) * rs * gamma[c] + beta[c];
    }
}

// ===========================================================================
// Launch
// ===========================================================================
extern "C" void kernel_launch(void* const* d_in, const int* in_sizes, int n_in,
                              void* d_out, int out_size)
{
    const float* x      = (const float*)d_in[0];
    const float* w_in   = (const float*)d_in[1];
    const float* b_in   = (const float*)d_in[2];
    const float* w_out  = (const float*)d_in[3];
    const float* b_out  = (const float*)d_in[4];
    const float* gamma  = (const float*)d_in[5];
    const float* beta   = (const float*)d_in[6];
    float* out = (float*)d_out;

    void* p;
    cudaGetSymbolAddress(&p, g_abuf);  __nv_bfloat16* abuf = (__nv_bfloat16*)p;
    cudaGetSymbolAddress(&p, g_bbuf);  __nv_bfloat16* bbuf = (__nv_bfloat16*)p;
    cudaGetSymbolAddress(&p, g_wo16);  __half* wo16 = (__half*)p;
    cudaGetSymbolAddress(&p, g_f16);   __half* f16 = (__half*)p;
    cudaGetSymbolAddress(&p, g_att);   float* att = (float*)p;

    cudaFuncSetAttribute(gemm_mma<1, 0>,
                         cudaFuncAttributeMaxDynamicSharedMemorySize, GEMM_SMEM);
    cudaFuncSetAttribute(gemm_mma<0, 1>,
                         cudaFuncAttributeMaxDynamicSharedMemorySize, GEMM_SMEM);
    cudaFuncSetAttribute(flash_mma,
                         cudaFuncAttributeMaxDynamicSharedMemorySize, FLASH_SMEM);

    // 1) split-convert x (A side, 3-term bf16) and in_proj_w (B side)
    split_bf16_kernel<<<MROWS, 256>>>(x, abuf, 0);
    split_bf16_kernel<<<QKVN, 256>>>(w_in, bbuf, 1);

    // 2) QKV projection (bf16 3-term) -> fp16 hi/lo planes (Q scaled 1/8)
    gemm_mma<1, 0><<<dim3(QKVN / 128, MROWS / 128), 256, GEMM_SMEM>>>(
        abuf, bbuf, b_in, nullptr, f16, QKVN, K3);

    // 3) causal flash attention -> ctx fp16 h|l (K2 layout, reuses abuf)
    flash_mma<<<dim3(SEQ / 128, HEADS, BATCH), 256, FLASH_SMEM>>>(
        f16, (__half*)abuf);

    // 4) out projection (fp16 2-term): [8192,1024]
    split_f16_w_kernel<<<DIM, 256>>>(w_out, wo16);
    gemm_mma<0, 1><<<dim3(DIM / 128, MROWS / 128), 256, GEMM_SMEM>>>(
        (__half*)abuf, wo16, b_out, att, nullptr, DIM, K2);

    // 5) residual + layernorm
    ln_kernel<<<MROWS, 256>>>(x, att, gamma, beta, out);
}

// round 10
// speedup vs baseline: 3.1788x; 1.2827x over previous
#include <cuda_runtime.h>
#include <cuda_fp16.h>
#include <cuda_bf16.h>
#include <stdint.h>
#include <math.h>

// Problem constants
#define BATCH 4
#define SEQ   2048
#define DIM   1024
#define HEADS 16
#define HDIM  64
#define MROWS (BATCH * SEQ)          // 8192
#define QKVN  (3 * DIM)              // 3072
#define K3    3072
#define K2    2048                   // split-fp16 K (2 * 1024)
#define PLANE ((size_t)BATCH * HEADS * SEQ * HDIM)   // 8388608 halves / plane

// Scratch (device globals; no dynamic allocation allowed)
__device__ __nv_bfloat16 g_abuf[(size_t)MROWS * K3];   // A operand (fp16 h|l reuse)
__device__ __nv_bfloat16 g_bbuf[(size_t)QKVN * K3];    // B operand (fp16 h|h reuse)
__device__ __half g_wo16[(size_t)DIM * K2];            // out_w fp16 h|h
__device__ __half g_f16[5 * PLANE];                    // Qh,Ql,Kh,Kl,Vh planes
__device__ float g_att[(size_t)MROWS * DIM];           // out-proj result

// ===========================================================================
// Helpers (base-ISA only: cp.async, ldmatrix, mma.sync)
// ===========================================================================
__device__ __forceinline__ uint32_t smem_u32(const void* p) {
    uint32_t a;
    asm("{ .reg .u64 t; cvta.to.shared.u64 t, %1; cvt.u32.u64 %0, t; }"
        : "=r"(a) : "l"(p));
    return a;
}
__device__ __forceinline__ void cp_async16(uint32_t dst, const void* src) {
    asm volatile("cp.async.cg.shared.global [%0], [%1], 16;"
                 :: "r"(dst), "l"(src) : "memory");
}
#define CP_COMMIT() asm volatile("cp.async.commit_group;" ::: "memory")
#define CP_WAIT(n)  asm volatile("cp.async.wait_group %0;" :: "n"(n) : "memory")

__device__ __forceinline__ void ldmatrix_x4(uint32_t& r0, uint32_t& r1,
                                            uint32_t& r2, uint32_t& r3,
                                            uint32_t addr) {
    asm volatile("ldmatrix.sync.aligned.m8n8.x4.shared.b16 {%0,%1,%2,%3}, [%4];"
                 : "=r"(r0), "=r"(r1), "=r"(r2), "=r"(r3) : "r"(addr));
}
__device__ __forceinline__ void ldmatrix_x4_trans(uint32_t& r0, uint32_t& r1,
                                                  uint32_t& r2, uint32_t& r3,
                                                  uint32_t addr) {
    asm volatile("ldmatrix.sync.aligned.m8n8.x4.trans.shared.b16 {%0,%1,%2,%3}, [%4];"
                 : "=r"(r0), "=r"(r1), "=r"(r2), "=r"(r3) : "r"(addr));
}
__device__ __forceinline__ void mma_f16(float* d, const uint32_t* a,
                                        uint32_t b0, uint32_t b1) {
    asm volatile(
        "mma.sync.aligned.m16n8k16.row.col.f32.f16.f16.f32 "
        "{%0,%1,%2,%3}, {%4,%5,%6,%7}, {%8,%9}, {%0,%1,%2,%3};"
        : "+f"(d[0]), "+f"(d[1]), "+f"(d[2]), "+f"(d[3])
        : "r"(a[0]), "r"(a[1]), "r"(a[2]), "r"(a[3]), "r"(b0), "r"(b1));
}
__device__ __forceinline__ uint32_t packh2(float a, float b) {
    __half2 h = __floats2half2_rn(a, b);
    return *(uint32_t*)&h;
}

// ===========================================================================
// Split fp32 -> fp16 h|l (A side): out[r][c]=hi, out[r][1024+c]=lo
// ===========================================================================
__global__ __launch_bounds__(256) void split_f16_x_kernel(
    const float* __restrict__ in, __half* __restrict__ out)
{
    const int i = blockIdx.x * 256 + threadIdx.x;
    const int row = i >> 8;
    const int c4 = (i & 255) * 4;
    float4 v = ((const float4*)in)[i];
    __half hx = __float2half_rn(v.x), hy = __float2half_rn(v.y);
    __half hz = __float2half_rn(v.z), hw = __float2half_rn(v.w);
    __half lx = __float2half_rn(v.x - __half2float(hx));
    __half ly = __float2half_rn(v.y - __half2float(hy));
    __half lz = __float2half_rn(v.z - __half2float(hz));
    __half lw = __float2half_rn(v.w - __half2float(hw));
    uint2 H, L;
    { __half2 t = {hx, hy}; H.x = *(uint32_t*)&t; }
    { __half2 t = {hz, hw}; H.y = *(uint32_t*)&t; }
    { __half2 t = {lx, ly}; L.x = *(uint32_t*)&t; }
    { __half2 t = {lz, lw}; L.y = *(uint32_t*)&t; }
    size_t ob = (size_t)row * K2 + c4;
    *(uint2*)(out + ob)        = H;
    *(uint2*)(out + ob + 1024) = L;
}

// ===========================================================================
// Split fp32 -> fp16 hi duplicated (B side): out[r][c]=h, out[r][1024+c]=h
// ===========================================================================
__global__ __launch_bounds__(256) void split_f16_w_kernel(
    const float* __restrict__ in, __half* __restrict__ out)
{
    const int i = blockIdx.x * 256 + threadIdx.x;
    const int row = i >> 8;
    const int c4 = (i & 255) * 4;
    float4 v = ((const float4*)in)[i];
    uint2 H;
    H.x = packh2(v.x, v.y);
    H.y = packh2(v.z, v.w);
    size_t ob = (size_t)row * K2 + c4;
    *(uint2*)(out + ob)        = H;
    *(uint2*)(out + ob + 1024) = H;
}

// ===========================================================================
// mma.sync fp16 GEMM: 128x128 tile, BK=32, 3-stage cp.async, 8 warps.
// MODE=0: fp32 out + bias.  MODE=1: QKV -> fp16 hi/lo planes (Q scaled 1/8;
//         V lo plane skipped).
// ===========================================================================
#define BK 32
#define STG 3
#define ROWB 80
#define TILEB (128 * ROWB)
#define GEMM_SMEM (2 * STG * TILEB)

__device__ __forceinline__ void g_load_tiles(
    const __half* __restrict__ Ab, const __half* __restrict__ Bb,
    uint32_t sA, uint32_t sB, int stage, int chunk, int tid)
{
    const uint32_t sa = sA + stage * TILEB;
    const uint32_t sb = sB + stage * TILEB;
#pragma unroll
    for (int i = 0; i < 2; i++) {
        int idx = tid + i * 256;
        int row = idx >> 2;
        int cc = idx & 3;
        uint32_t dst = row * ROWB + cc * 16;
        cp_async16(sa + dst, Ab + (size_t)row * K2 + chunk * BK + cc * 8);
        cp_async16(sb + dst, Bb + (size_t)row * K2 + chunk * BK + cc * 8);
    }
}

template <int MODE>
__global__ __launch_bounds__(256, 2) void gemm_mma(
    const __half* __restrict__ A, const __half* __restrict__ B,
    const float* __restrict__ bias, float* __restrict__ C,
    __half* __restrict__ f16out, int N)
{
    extern __shared__ __align__(16) char smem[];
    const uint32_t sA = smem_u32(smem);
    const uint32_t sB = sA + STG * TILEB;

    const int tid = threadIdx.x;
    const int warp = tid >> 5;
    const int lane = tid & 31;
    const int wm = warp >> 2;
    const int wn = warp & 3;
    const int bm = blockIdx.y * 128;
    const int bn = blockIdx.x * 128;
    const int NC = K2 / BK;          // 64

    const __half* Ab = A + (size_t)bm * K2;
    const __half* Bb = B + (size_t)bn * K2;

    float acc[4][4][4];
#pragma unroll
    for (int mt = 0; mt < 4; mt++)
#pragma unroll
        for (int nt = 0; nt < 4; nt++)
#pragma unroll
            for (int r = 0; r < 4; r++) acc[mt][nt][r] = 0.0f;

    const int lrow = lane & 15;
    const int lcol = (lane >> 4) * 16;

#pragma unroll
    for (int c = 0; c < STG - 1; c++) {
        g_load_tiles(Ab, Bb, sA, sB, c, c, tid);
        CP_COMMIT();
    }

    for (int c = 0; c < NC; c++) {
        CP_WAIT(STG - 2);
        __syncthreads();

        const int t = c + STG - 1;
        if (t < NC) g_load_tiles(Ab, Bb, sA, sB, t % STG, t, tid);
        CP_COMMIT();

        const int s = c % STG;
        const uint32_t aBase = sA + s * TILEB;
        const uint32_t bBase = sB + s * TILEB;

#pragma unroll
        for (int ks = 0; ks < 2; ks++) {
            const int k0 = ks * 16;
            uint32_t af[4][4];
#pragma unroll
            for (int mt = 0; mt < 4; mt++) {
                uint32_t addr = aBase + (wm * 64 + mt * 16 + lrow) * ROWB
                              + k0 * 2 + lcol;
                ldmatrix_x4(af[mt][0], af[mt][1], af[mt][2], af[mt][3], addr);
            }
            uint32_t bf[2][4];
#pragma unroll
            for (int bt = 0; bt < 2; bt++) {
                uint32_t addr = bBase + (wn * 32 + bt * 16 + lrow) * ROWB
                              + k0 * 2 + lcol;
                ldmatrix_x4(bf[bt][0], bf[bt][1], bf[bt][2], bf[bt][3], addr);
            }
#pragma unroll
            for (int mt = 0; mt < 4; mt++)
#pragma unroll
                for (int nt = 0; nt < 4; nt++) {
                    const int bt = nt >> 1, sel = nt & 1;
                    mma_f16(acc[mt][nt], af[mt], bf[bt][sel], bf[bt][sel + 2]);
                }
        }
        __syncthreads();
    }

    const int er = lane >> 2;
    const int ec = (lane & 3) * 2;
#pragma unroll
    for (int mt = 0; mt < 4; mt++) {
#pragma unroll
        for (int nt = 0; nt < 4; nt++) {
            const int col = bn + wn * 32 + nt * 8 + ec;
            const float b0 = bias[col], b1 = bias[col + 1];
            const int r0 = bm + wm * 64 + mt * 16 + er;
            float v00 = acc[mt][nt][0] + b0, v01 = acc[mt][nt][1] + b1;
            float v10 = acc[mt][nt][2] + b0, v11 = acc[mt][nt][3] + b1;
            if (MODE == 0) {
                *(float2*)(C + (size_t)r0 * N + col) = {v00, v01};
                *(float2*)(C + (size_t)(r0 + 8) * N + col) = {v10, v11};
            } else {
                const int type = col >> 10;           // 0=Q 1=K 2=V
                const int rem = col & 1023;
                const int h = rem >> 6;
                const int d = rem & 63;
                if (type == 0) { v00 *= 0.125f; v01 *= 0.125f;
                                 v10 *= 0.125f; v11 *= 0.125f; }
                const int b = r0 >> 11;
                const int s0 = r0 & 2047;
                size_t rowbase = (((size_t)(b * HEADS + h)) * SEQ + s0) * HDIM + d;
                __half* hp = f16out + (size_t)(type * 2) * PLANE;   // planes 0,2,4
                __half* lp = hp + PLANE;                            // planes 1,3
#pragma unroll
                for (int rr = 0; rr < 2; rr++) {
                    float vx = rr ? v10 : v00;
                    float vy = rr ? v11 : v01;
                    __half hx = __float2half_rn(vx), hy = __float2half_rn(vy);
                    size_t o = rowbase + (size_t)rr * 8 * HDIM;
                    { __half2 t = {hx, hy}; *(__half2*)(hp + o) = t; }
                    if (type < 2) {
                        __half lx = __float2half_rn(vx - __half2float(hx));
                        __half ly = __float2half_rn(vy - __half2float(hy));
                        __half2 t = {lx, ly}; *(__half2*)(lp + o) = t;
                    }
                }
            }
        }
    }
}

// ===========================================================================
// Flash attention (tensor cores), 2 CTAs/SM. Q re-LDSM'd from persistent smem.
// S = qh*kh + qh*kl + ql*kh (full 3-term); PV = P*Vh only (Vl dropped).
// smem = Qh|Ql (36864) + 2 stages x (Kh|Kl|Vh @ 64x144B) = 92160 B.
// Output written as fp16 h|l rows (K2 layout) for the 2-term out-proj.
// ===========================================================================
#define FROWB 144
#define FTILE 9216                       // 64 * 144
#define FSTAGE (3 * FTILE)               // 27648
#define FQREG  (2 * 128 * FROWB)         // 36864 (Qh | Ql)
#define FLASH_SMEM (FQREG + 2 * FSTAGE)  // 92160

__global__ __launch_bounds__(256, 2) void flash_mma(
    const __half* __restrict__ f16, __half* __restrict__ ctx16)
{
    extern __shared__ __align__(16) char fsm[];
    const uint32_t sb = smem_u32(fsm);

    const int tid = threadIdx.x;
    const int w = tid >> 5;
    const int lane = tid & 31;
    const int er = lane >> 2;
    const int ec = (lane & 3) * 2;
    const int lrow = lane & 15;
    const int lcol = (lane >> 4) * 16;

    const int qt = (int)gridDim.x - 1 - (int)blockIdx.x;   // heavy tiles first
    const int h = blockIdx.y;
    const int b = blockIdx.z;
    const int q0 = qt * 128;

    const size_t hb = ((size_t)(b * HEADS + h)) * SEQ * HDIM;
    const __half* Qhg = f16 + hb;
    const __half* Qlg = f16 + PLANE + hb;
    const __half* Khg = f16 + 2 * PLANE + hb;
    const __half* Klg = f16 + 3 * PLANE + hb;
    const __half* Vhg = f16 + 4 * PLANE + hb;

    // ---- stage Q hi/lo into the persistent region ----
#pragma unroll
    for (int i = 0; i < 8; i++) {
        int idx = tid + i * 256;          // 2048 chunks: op(1b) | row(7b) | c(3b)
        int op = idx >> 10;
        int within = idx & 1023;
        int r = within >> 3;
        int c = within & 7;
        const __half* src = (op ? Qlg : Qhg) + (size_t)(q0 + r) * HDIM + c * 8;
        cp_async16(sb + op * 18432 + r * FROWB + c * 16, src);
    }
    CP_COMMIT();

    float o[8][4];
#pragma unroll
    for (int nf = 0; nf < 8; nf++)
#pragma unroll
        for (int r = 0; r < 4; r++) o[nf][r] = 0.0f;
    float mprev[2] = {-INFINITY, -INFINITY};
    float lsum[2] = {0.0f, 0.0f};

    const int nkt = 2 * qt + 2;

    auto issue_tile = [&](int kt, int st) {
        const int k0 = kt * 64;
        const uint32_t sbase = sb + FQREG + st * FSTAGE;
#pragma unroll
        for (int i = 0; i < 6; i++) {
            int idx = tid + i * 256;      // 1536 chunks: op(0..2) | row(6b) | c(3b)
            int op = idx >> 9;
            int within = idx & 511;
            int r = within >> 3;
            int c = within & 7;
            const __half* base = (op == 0) ? Khg : (op == 1) ? Klg : Vhg;
            cp_async16(sbase + op * FTILE + r * FROWB + c * 16,
                       base + (size_t)(k0 + r) * HDIM + c * 8);
        }
        CP_COMMIT();
    };

    issue_tile(0, 0);

    for (int kt = 0; kt < nkt; kt++) {
        const int k0 = kt * 64;
        if (kt + 1 < nkt) { issue_tile(kt + 1, (kt + 1) & 1); CP_WAIT(1); }
        else              { CP_WAIT(0); }
        __syncthreads();

        const uint32_t Kh = sb + FQREG + (kt & 1) * FSTAGE;
        const uint32_t Kl = Kh + FTILE;
        const uint32_t Vh = Kh + 2 * FTILE;

        // ---- S = Q K^T (qh*kh + qh*kl + ql*kh) ----
        float s[8][4];
#pragma unroll
        for (int nf = 0; nf < 8; nf++)
#pragma unroll
            for (int r = 0; r < 4; r++) s[nf][r] = 0.0f;

#pragma unroll
        for (int ks = 0; ks < 4; ks++) {
            uint32_t qh4[4], ql4[4];
            uint32_t qa = sb + (w * 16 + lrow) * FROWB + ks * 32 + lcol;
            ldmatrix_x4(qh4[0], qh4[1], qh4[2], qh4[3], qa);
            ldmatrix_x4(ql4[0], ql4[1], ql4[2], ql4[3], qa + 18432);
#pragma unroll
            for (int g = 0; g < 4; g++) {
                uint32_t kh4[4], kl4[4];
                uint32_t a = Kh + (g * 16 + lrow) * FROWB + ks * 32 + lcol;
                ldmatrix_x4(kh4[0], kh4[1], kh4[2], kh4[3], a);
                uint32_t a2 = Kl + (g * 16 + lrow) * FROWB + ks * 32 + lcol;
                ldmatrix_x4(kl4[0], kl4[1], kl4[2], kl4[3], a2);
                mma_f16(s[2 * g],     qh4, kh4[0], kh4[2]);
                mma_f16(s[2 * g],     qh4, kl4[0], kl4[2]);
                mma_f16(s[2 * g],     ql4, kh4[0], kh4[2]);
                mma_f16(s[2 * g + 1], qh4, kh4[1], kh4[3]);
                mma_f16(s[2 * g + 1], qh4, kl4[1], kl4[3]);
                mma_f16(s[2 * g + 1], ql4, kh4[1], kh4[3]);
            }
        }

        // ---- causal mask ----
        if (kt >= 2 * qt) {
            const int row0 = q0 + w * 16 + er;
#pragma unroll
            for (int nf = 0; nf < 8; nf++) {
                const int keyb = k0 + (nf >> 1) * 16 + (nf & 1) * 8 + ec;
#pragma unroll
                for (int r = 0; r < 4; r++) {
                    int key = keyb + (r & 1);
                    int row = row0 + (r >> 1) * 8;
                    if (key > row) s[nf][r] = -INFINITY;
                }
            }
        }

        // ---- online softmax ----
        float mx0 = -INFINITY, mx1 = -INFINITY;
#pragma unroll
        for (int nf = 0; nf < 8; nf++) {
            mx0 = fmaxf(mx0, fmaxf(s[nf][0], s[nf][1]));
            mx1 = fmaxf(mx1, fmaxf(s[nf][2], s[nf][3]));
        }
        mx0 = fmaxf(mx0, __shfl_xor_sync(0xffffffffu, mx0, 1));
        mx0 = fmaxf(mx0, __shfl_xor_sync(0xffffffffu, mx0, 2));
        mx1 = fmaxf(mx1, __shfl_xor_sync(0xffffffffu, mx1, 1));
        mx1 = fmaxf(mx1, __shfl_xor_sync(0xffffffffu, mx1, 2));

        float mn0 = fmaxf(mprev[0], mx0);
        float mn1 = fmaxf(mprev[1], mx1);
        float al0 = __expf(mprev[0] - mn0);
        float al1 = __expf(mprev[1] - mn1);
        float sum0 = 0.0f, sum1 = 0.0f;
#pragma unroll
        for (int nf = 0; nf < 8; nf++) {
            s[nf][0] = __expf(s[nf][0] - mn0);
            s[nf][1] = __expf(s[nf][1] - mn0);
            s[nf][2] = __expf(s[nf][2] - mn1);
            s[nf][3] = __expf(s[nf][3] - mn1);
            sum0 += s[nf][0] + s[nf][1];
            sum1 += s[nf][2] + s[nf][3];
        }
        sum0 += __shfl_xor_sync(0xffffffffu, sum0, 1);
        sum0 += __shfl_xor_sync(0xffffffffu, sum0, 2);
        sum1 += __shfl_xor_sync(0xffffffffu, sum1, 1);
        sum1 += __shfl_xor_sync(0xffffffffu, sum1, 2);
        lsum[0] = lsum[0] * al0 + sum0;
        lsum[1] = lsum[1] * al1 + sum1;
        mprev[0] = mn0;
        mprev[1] = mn1;
#pragma unroll
        for (int nf = 0; nf < 8; nf++) {
            o[nf][0] *= al0; o[nf][1] *= al0;
            o[nf][2] *= al1; o[nf][3] *= al1;
        }

        // ---- O += P Vh ----
#pragma unroll
        for (int kk = 0; kk < 4; kk++) {
            uint32_t pa[4];
            pa[0] = packh2(s[2 * kk][0], s[2 * kk][1]);
            pa[1] = packh2(s[2 * kk][2], s[2 * kk][3]);
            pa[2] = packh2(s[2 * kk + 1][0], s[2 * kk + 1][1]);
            pa[3] = packh2(s[2 * kk + 1][2], s[2 * kk + 1][3]);
#pragma unroll
            for (int g = 0; g < 4; g++) {
                uint32_t vh4[4];
                uint32_t a = Vh + (kk * 16 + lrow) * FROWB + g * 32 + lcol;
                ldmatrix_x4_trans(vh4[0], vh4[1], vh4[2], vh4[3], a);
                mma_f16(o[2 * g],     pa, vh4[0], vh4[1]);
                mma_f16(o[2 * g + 1], pa, vh4[2], vh4[3]);
            }
        }
        __syncthreads();
    }

    // ---- normalize + write ctx as fp16 h|l rows ([MROWS][K2]) ----
    const float inv0 = 1.0f / lsum[0];
    const float inv1 = 1.0f / lsum[1];
    const int mrow0 = b * SEQ + q0 + w * 16 + er;
#pragma unroll
    for (int nf = 0; nf < 8; nf++) {
        const int c = h * HDIM + nf * 8 + ec;
#pragma unroll
        for (int rr = 0; rr < 2; rr++) {
            float vx = o[nf][2 * rr + 0] * (rr ? inv1 : inv0);
            float vy = o[nf][2 * rr + 1] * (rr ? inv1 : inv0);
            __half hx = __float2half_rn(vx), hy = __float2half_rn(vy);
            __half lx = __float2half_rn(vx - __half2float(hx));
            __half ly = __float2half_rn(vy - __half2float(hy));
            __half* row = ctx16 + (size_t)(mrow0 + rr * 8) * K2 + c;
            { __half2 t = {hx, hy}; *(__half2*)(row) = t; }
            { __half2 t = {lx, ly}; *(__half2*)(row + 1024) = t; }
        }
    }
}

// ===========================================================================
// Residual + LayerNorm (unchanged)
// ===========================================================================
__global__ __launch_bounds__(256) void ln_kernel(
    const float* __restrict__ x, const float* __restrict__ att,
    const float* __restrict__ gamma, const float* __restrict__ beta,
    float* __restrict__ out)
{
    __shared__ float red[2][8];
    const int row = blockIdx.x;
    const int tid = threadIdx.x;
    const float* xr = x + (size_t)row * DIM;
    const float* ar = att + (size_t)row * DIM;

    float v[4];
    float s = 0.0f, s2 = 0.0f;
#pragma unroll
    for (int i = 0; i < 4; i++) {
        int c = tid + i * 256;
        float t = xr[c] + ar[c];
        v[i] = t;
        s += t;
        s2 += t * t;
    }
#pragma unroll
    for (int off = 16; off >= 1; off >>= 1) {
        s  += __shfl_xor_sync(0xffffffffu, s, off);
        s2 += __shfl_xor_sync(0xffffffffu, s2, off);
    }
    if ((tid & 31) == 0) { red[0][tid >> 5] = s; red[1][tid >> 5] = s2; }
    __syncthreads();
    s = 0.0f; s2 = 0.0f;
#pragma unroll
    for (int k = 0; k < 8; k++) { s += red[0][k]; s2 += red[1][k]; }

    const float mu = s * (1.0f / DIM);
    const float var = s2 * (1.0f / DIM) - mu * mu;
    const float rs = rsqrtf(var + 1e-5f);

    float* orow = out + (size_t)row * DIM;
#pragma unroll
    for (int i = 0; i < 4; i++) {
        int c = tid + i * 256;
        orow[c] = (v[i] - mu) * rs * gamma[c] + beta[c];
    }
}

// ===========================================================================
// Launch
// ===========================================================================
extern "C" void kernel_launch(void* const* d_in, const int* in_sizes, int n_in,
                              void* d_out, int out_size)
{
    const float* x      = (const float*)d_in[0];
    const float* w_in   = (const float*)d_in[1];
    const float* b_in   = (const float*)d_in[2];
    const float* w_out  = (const float*)d_in[3];
    const float* b_out  = (const float*)d_in[4];
    const float* gamma  = (const float*)d_in[5];
    const float* beta   = (const float*)d_in[6];
    float* out = (float*)d_out;

    void* p;
    cudaGetSymbolAddress(&p, g_abuf);  __half* abuf = (__half*)p;
    cudaGetSymbolAddress(&p, g_bbuf);  __half* wi16 = (__half*)p;
    cudaGetSymbolAddress(&p, g_wo16);  __half* wo16 = (__half*)p;
    cudaGetSymbolAddress(&p, g_f16);   __half* f16 = (__half*)p;
    cudaGetSymbolAddress(&p, g_att);   float* att = (float*)p;

    cudaFuncSetAttribute(gemm_mma<0>,
                         cudaFuncAttributeMaxDynamicSharedMemorySize, GEMM_SMEM);
    cudaFuncSetAttribute(gemm_mma<1>,
                         cudaFuncAttributeMaxDynamicSharedMemorySize, GEMM_SMEM);
    cudaFuncSetAttribute(flash_mma,
                         cudaFuncAttributeMaxDynamicSharedMemorySize, FLASH_SMEM);

    // 1) split-convert x (fp16 h|l) and in_proj_w (fp16 h|h)
    split_f16_x_kernel<<<MROWS, 256>>>(x, abuf);
    split_f16_w_kernel<<<QKVN, 256>>>(w_in, wi16);

    // 2) QKV projection (fp16 2-term, K2) -> fp16 hi/lo planes (Q scaled 1/8)
    gemm_mma<1><<<dim3(QKVN / 128, MROWS / 128), 256, GEMM_SMEM>>>(
        abuf, wi16, b_in, nullptr, f16, QKVN);

    // 3) causal flash attention -> ctx fp16 h|l (K2 layout, reuses abuf)
    flash_mma<<<dim3(SEQ / 128, HEADS, BATCH), 256, FLASH_SMEM>>>(f16, abuf);

    // 4) out projection (fp16 2-term, K2)
    split_f16_w_kernel<<<DIM, 256>>>(w_out, wo16);
    gemm_mma<0><<<dim3(DIM / 128, MROWS / 128), 256, GEMM_SMEM>>>(
        abuf, wo16, b_out, att, nullptr, DIM);

    // 5) residual + layernorm
    ln_kernel<<<MROWS, 256>>>(x, att, gamma, beta, out);
}

// round 13
// speedup vs baseline: 3.8999x; 1.2268x over previous
#include <cuda_runtime.h>
#include <cuda_fp16.h>
#include <cuda_bf16.h>
#include <stdint.h>
#include <math.h>

// Problem constants
#define BATCH 4
#define SEQ   2048
#define DIM   1024
#define HEADS 16
#define HDIM  64
#define MROWS (BATCH * SEQ)          // 8192
#define QKVN  (3 * DIM)              // 3072
#define K3    3072
#define K2    2048                   // split-fp16 K (2 * 1024)
#define PLANE ((size_t)BATCH * HEADS * SEQ * HDIM)   // 8388608 halves / plane

// Scratch (device globals; no dynamic allocation allowed)
__device__ __nv_bfloat16 g_abuf[(size_t)MROWS * K3];   // x h|l, later ctx hi
__device__ __nv_bfloat16 g_bbuf[(size_t)QKVN * K3];    // in_proj_w fp16 h|h
__device__ __half g_wo16[(size_t)DIM * DIM];           // out_w fp16 hi
__device__ __half g_f16[5 * PLANE];                    // Qh,Ql,Kh,Kl,Vh planes
__device__ float g_att[(size_t)MROWS * DIM];           // out-proj result

// ===========================================================================
// Helpers (base-ISA only: cp.async, ldmatrix, mma.sync)
// ===========================================================================
__device__ __forceinline__ uint32_t smem_u32(const void* p) {
    uint32_t a;
    asm("{ .reg .u64 t; cvta.to.shared.u64 t, %1; cvt.u32.u64 %0, t; }"
        : "=r"(a) : "l"(p));
    return a;
}
__device__ __forceinline__ void cp_async16(uint32_t dst, const void* src) {
    asm volatile("cp.async.cg.shared.global [%0], [%1], 16;"
                 :: "r"(dst), "l"(src) : "memory");
}
#define CP_COMMIT() asm volatile("cp.async.commit_group;" ::: "memory")
#define CP_WAIT(n)  asm volatile("cp.async.wait_group %0;" :: "n"(n) : "memory")

__device__ __forceinline__ void ldmatrix_x4(uint32_t& r0, uint32_t& r1,
                                            uint32_t& r2, uint32_t& r3,
                                            uint32_t addr) {
    asm volatile("ldmatrix.sync.aligned.m8n8.x4.shared.b16 {%0,%1,%2,%3}, [%4];"
                 : "=r"(r0), "=r"(r1), "=r"(r2), "=r"(r3) : "r"(addr));
}
__device__ __forceinline__ void ldmatrix_x4_trans(uint32_t& r0, uint32_t& r1,
                                                  uint32_t& r2, uint32_t& r3,
                                                  uint32_t addr) {
    asm volatile("ldmatrix.sync.aligned.m8n8.x4.trans.shared.b16 {%0,%1,%2,%3}, [%4];"
                 : "=r"(r0), "=r"(r1), "=r"(r2), "=r"(r3) : "r"(addr));
}
__device__ __forceinline__ void mma_f16(float* d, const uint32_t* a,
                                        uint32_t b0, uint32_t b1) {
    asm volatile(
        "mma.sync.aligned.m16n8k16.row.col.f32.f16.f16.f32 "
        "{%0,%1,%2,%3}, {%4,%5,%6,%7}, {%8,%9}, {%0,%1,%2,%3};"
        : "+f"(d[0]), "+f"(d[1]), "+f"(d[2]), "+f"(d[3])
        : "r"(a[0]), "r"(a[1]), "r"(a[2]), "r"(a[3]), "r"(b0), "r"(b1));
}
__device__ __forceinline__ uint32_t packh2(float a, float b) {
    __half2 h = __floats2half2_rn(a, b);
    return *(uint32_t*)&h;
}

// ===========================================================================
// Split fp32 -> fp16 h|l (A side): out[r][c]=hi, out[r][1024+c]=lo
// ===========================================================================
__global__ __launch_bounds__(256) void split_f16_x_kernel(
    const float* __restrict__ in, __half* __restrict__ out)
{
    const int i = blockIdx.x * 256 + threadIdx.x;
    const int row = i >> 8;
    const int c4 = (i & 255) * 4;
    float4 v = ((const float4*)in)[i];
    __half hx = __float2half_rn(v.x), hy = __float2half_rn(v.y);
    __half hz = __float2half_rn(v.z), hw = __float2half_rn(v.w);
    __half lx = __float2half_rn(v.x - __half2float(hx));
    __half ly = __float2half_rn(v.y - __half2float(hy));
    __half lz = __float2half_rn(v.z - __half2float(hz));
    __half lw = __float2half_rn(v.w - __half2float(hw));
    uint2 H, L;
    { __half2 t = {hx, hy}; H.x = *(uint32_t*)&t; }
    { __half2 t = {hz, hw}; H.y = *(uint32_t*)&t; }
    { __half2 t = {lx, ly}; L.x = *(uint32_t*)&t; }
    { __half2 t = {lz, lw}; L.y = *(uint32_t*)&t; }
    size_t ob = (size_t)row * K2 + c4;
    *(uint2*)(out + ob)        = H;
    *(uint2*)(out + ob + 1024) = L;
}

// ===========================================================================
// Split fp32 -> fp16 hi duplicated (w_in rows, K2 h|h layout)
// ===========================================================================
__global__ __launch_bounds__(256) void split_f16_w_dup_kernel(
    const float* __restrict__ in, __half* __restrict__ out)
{
    const int i = blockIdx.x * 256 + threadIdx.x;
    const int row = i >> 8;
    const int c4 = (i & 255) * 4;
    float4 v = ((const float4*)in)[i];
    uint2 H;
    H.x = packh2(v.x, v.y);
    H.y = packh2(v.z, v.w);
    size_t ob = (size_t)row * K2 + c4;
    *(uint2*)(out + ob)        = H;
    *(uint2*)(out + ob + 1024) = H;
}

// ===========================================================================
// Convert fp32 -> fp16 hi only (w_out, [1024][1024])
// ===========================================================================
__global__ __launch_bounds__(256) void conv_f16_kernel(
    const float* __restrict__ in, __half* __restrict__ out)
{
    const int i = blockIdx.x * 256 + threadIdx.x;
    float4 v = ((const float4*)in)[i];
    uint2 H;
    H.x = packh2(v.x, v.y);
    H.y = packh2(v.z, v.w);
    *(uint2*)(out + (size_t)i * 4) = H;
}

// ===========================================================================
// mma.sync fp16 GEMM: 128x128 tile, BK=32, 3-stage cp.async, 8 warps.
// Runtime klen + row strides. MODE=0: fp32 out + bias.
// MODE=1: QKV -> fp16 hi/lo planes (type from col+colofs; Q scaled 1/8,
//         V lo plane skipped).
// ===========================================================================
#define BK 32
#define STG 3
#define ROWB 80
#define TILEB (128 * ROWB)
#define GEMM_SMEM (2 * STG * TILEB)

__device__ __forceinline__ void g_load_tiles(
    const __half* __restrict__ Ab, const __half* __restrict__ Bb,
    uint32_t sA, uint32_t sB, int stage, int chunk, int tid,
    int astride, int bstride)
{
    const uint32_t sa = sA + stage * TILEB;
    const uint32_t sb = sB + stage * TILEB;
#pragma unroll
    for (int i = 0; i < 2; i++) {
        int idx = tid + i * 256;
        int row = idx >> 2;
        int cc = idx & 3;
        uint32_t dst = row * ROWB + cc * 16;
        cp_async16(sa + dst, Ab + (size_t)row * astride + chunk * BK + cc * 8);
        cp_async16(sb + dst, Bb + (size_t)row * bstride + chunk * BK + cc * 8);
    }
}

template <int MODE>
__global__ __launch_bounds__(256, 2) void gemm_mma(
    const __half* __restrict__ A, const __half* __restrict__ B,
    const float* __restrict__ bias, float* __restrict__ C,
    __half* __restrict__ f16out, int N, int klen,
    int astride, int bstride, int colofs)
{
    extern __shared__ __align__(16) char smem[];
    const uint32_t sA = smem_u32(smem);
    const uint32_t sB = sA + STG * TILEB;

    const int tid = threadIdx.x;
    const int warp = tid >> 5;
    const int lane = tid & 31;
    const int wm = warp >> 2;
    const int wn = warp & 3;
    const int bm = blockIdx.y * 128;
    const int bn = blockIdx.x * 128;
    const int NC = klen / BK;

    const __half* Ab = A + (size_t)bm * astride;
    const __half* Bb = B + (size_t)bn * bstride;

    float acc[4][4][4];
#pragma unroll
    for (int mt = 0; mt < 4; mt++)
#pragma unroll
        for (int nt = 0; nt < 4; nt++)
#pragma unroll
            for (int r = 0; r < 4; r++) acc[mt][nt][r] = 0.0f;

    const int lrow = lane & 15;
    const int lcol = (lane >> 4) * 16;

#pragma unroll
    for (int c = 0; c < STG - 1; c++) {
        g_load_tiles(Ab, Bb, sA, sB, c, c, tid, astride, bstride);
        CP_COMMIT();
    }

    for (int c = 0; c < NC; c++) {
        CP_WAIT(STG - 2);
        __syncthreads();   // also orders stage-reuse writes vs prior reads

        const int t = c + STG - 1;
        if (t < NC) g_load_tiles(Ab, Bb, sA, sB, t % STG, t, tid,
                                 astride, bstride);
        CP_COMMIT();

        const int s = c % STG;
        const uint32_t aBase = sA + s * TILEB;
        const uint32_t bBase = sB + s * TILEB;

#pragma unroll
        for (int ks = 0; ks < 2; ks++) {
            const int k0 = ks * 16;
            uint32_t af[4][4];
#pragma unroll
            for (int mt = 0; mt < 4; mt++) {
                uint32_t addr = aBase + (wm * 64 + mt * 16 + lrow) * ROWB
                              + k0 * 2 + lcol;
                ldmatrix_x4(af[mt][0], af[mt][1], af[mt][2], af[mt][3], addr);
            }
            uint32_t bf[2][4];
#pragma unroll
            for (int bt = 0; bt < 2; bt++) {
                uint32_t addr = bBase + (wn * 32 + bt * 16 + lrow) * ROWB
                              + k0 * 2 + lcol;
                ldmatrix_x4(bf[bt][0], bf[bt][1], bf[bt][2], bf[bt][3], addr);
            }
#pragma unroll
            for (int mt = 0; mt < 4; mt++)
#pragma unroll
                for (int nt = 0; nt < 4; nt++) {
                    const int bt = nt >> 1, sel = nt & 1;
                    mma_f16(acc[mt][nt], af[mt], bf[bt][sel], bf[bt][sel + 2]);
                }
        }
        // no bottom barrier: next iter's top __syncthreads covers reuse
    }

    const int er = lane >> 2;
    const int ec = (lane & 3) * 2;
#pragma unroll
    for (int mt = 0; mt < 4; mt++) {
#pragma unroll
        for (int nt = 0; nt < 4; nt++) {
            const int col = bn + wn * 32 + nt * 8 + ec;
            const float b0 = bias[col], b1 = bias[col + 1];
            const int r0 = bm + wm * 64 + mt * 16 + er;
            float v00 = acc[mt][nt][0] + b0, v01 = acc[mt][nt][1] + b1;
            float v10 = acc[mt][nt][2] + b0, v11 = acc[mt][nt][3] + b1;
            if (MODE == 0) {
                *(float2*)(C + (size_t)r0 * N + col) = {v00, v01};
                *(float2*)(C + (size_t)(r0 + 8) * N + col) = {v10, v11};
            } else {
                const int gcol = col + colofs;
                const int type = gcol >> 10;          // 0=Q 1=K 2=V
                const int rem = gcol & 1023;
                const int h = rem >> 6;
                const int d = rem & 63;
                if (type == 0) { v00 *= 0.125f; v01 *= 0.125f;
                                 v10 *= 0.125f; v11 *= 0.125f; }
                const int b = r0 >> 11;
                const int s0 = r0 & 2047;
                size_t rowbase = (((size_t)(b * HEADS + h)) * SEQ + s0) * HDIM + d;
                __half* hp = f16out + (size_t)(type * 2) * PLANE;   // planes 0,2,4
                __half* lp = hp + PLANE;                            // planes 1,3
#pragma unroll
                for (int rr = 0; rr < 2; rr++) {
                    float vx = rr ? v10 : v00;
                    float vy = rr ? v11 : v01;
                    __half hx = __float2half_rn(vx), hy = __float2half_rn(vy);
                    size_t o = rowbase + (size_t)rr * 8 * HDIM;
                    { __half2 t = {hx, hy}; *(__half2*)(hp + o) = t; }
                    if (type < 2) {
                        __half lx = __float2half_rn(vx - __half2float(hx));
                        __half ly = __float2half_rn(vy - __half2float(hy));
                        __half2 t = {lx, ly}; *(__half2*)(lp + o) = t;
                    }
                }
            }
        }
    }
}

// ===========================================================================
// Flash attention (tensor cores), 2 CTAs/SM. Q re-LDSM'd from persistent smem.
// S = qh*kh + qh*kl + ql*kh (full 3-term); PV = P*Vh only.
// smem = Qh|Ql (36864) + 2 stages x (Kh|Kl|Vh @ 64x144B) = 92160 B.
// Output: ctx fp16 hi rows [MROWS][1024] (1-term out-proj).
// ===========================================================================
#define FROWB 144
#define FTILE 9216                       // 64 * 144
#define FSTAGE (3 * FTILE)               // 27648
#define FQREG  (2 * 128 * FROWB)         // 36864 (Qh | Ql)
#define FLASH_SMEM (FQREG + 2 * FSTAGE)  // 92160

__global__ __launch_bounds__(256, 2) void flash_mma(
    const __half* __restrict__ f16, __half* __restrict__ ctx16)
{
    extern __shared__ __align__(16) char fsm[];
    const uint32_t sb = smem_u32(fsm);

    const int tid = threadIdx.x;
    const int w = tid >> 5;
    const int lane = tid & 31;
    const int er = lane >> 2;
    const int ec = (lane & 3) * 2;
    const int lrow = lane & 15;
    const int lcol = (lane >> 4) * 16;

    const int qt = (int)gridDim.x - 1 - (int)blockIdx.x;   // heavy tiles first
    const int h = blockIdx.y;
    const int b = blockIdx.z;
    const int q0 = qt * 128;

    const size_t hb = ((size_t)(b * HEADS + h)) * SEQ * HDIM;
    const __half* Qhg = f16 + hb;
    const __half* Qlg = f16 + PLANE + hb;
    const __half* Khg = f16 + 2 * PLANE + hb;
    const __half* Klg = f16 + 3 * PLANE + hb;
    const __half* Vhg = f16 + 4 * PLANE + hb;

    // ---- stage Q hi/lo into the persistent region ----
#pragma unroll
    for (int i = 0; i < 8; i++) {
        int idx = tid + i * 256;          // 2048 chunks: op(1b) | row(7b) | c(3b)
        int op = idx >> 10;
        int within = idx & 1023;
        int r = within >> 3;
        int c = within & 7;
        const __half* src = (op ? Qlg : Qhg) + (size_t)(q0 + r) * HDIM + c * 8;
        cp_async16(sb + op * 18432 + r * FROWB + c * 16, src);
    }
    CP_COMMIT();

    float o[8][4];
#pragma unroll
    for (int nf = 0; nf < 8; nf++)
#pragma unroll
        for (int r = 0; r < 4; r++) o[nf][r] = 0.0f;
    float mprev[2] = {-INFINITY, -INFINITY};
    float lsum[2] = {0.0f, 0.0f};

    const int nkt = 2 * qt + 2;

    auto issue_tile = [&](int kt, int st) {
        const int k0 = kt * 64;
        const uint32_t sbase = sb + FQREG + st * FSTAGE;
#pragma unroll
        for (int i = 0; i < 6; i++) {
            int idx = tid + i * 256;      // 1536 chunks: op(0..2) | row(6b) | c(3b)
            int op = idx >> 9;
            int within = idx & 511;
            int r = within >> 3;
            int c = within & 7;
            const __half* base = (op == 0) ? Khg : (op == 1) ? Klg : Vhg;
            cp_async16(sbase + op * FTILE + r * FROWB + c * 16,
                       base + (size_t)(k0 + r) * HDIM + c * 8);
        }
        CP_COMMIT();
    };

    issue_tile(0, 0);

    for (int kt = 0; kt < nkt; kt++) {
        const int k0 = kt * 64;
        if (kt + 1 < nkt) { issue_tile(kt + 1, (kt + 1) & 1); CP_WAIT(1); }
        else              { CP_WAIT(0); }
        __syncthreads();

        const uint32_t Kh = sb + FQREG + (kt & 1) * FSTAGE;
        const uint32_t Kl = Kh + FTILE;
        const uint32_t Vh = Kh + 2 * FTILE;

        // ---- S = Q K^T (qh*kh + qh*kl + ql*kh) ----
        float s[8][4];
#pragma unroll
        for (int nf = 0; nf < 8; nf++)
#pragma unroll
            for (int r = 0; r < 4; r++) s[nf][r] = 0.0f;

#pragma unroll
        for (int ks = 0; ks < 4; ks++) {
            uint32_t qh4[4], ql4[4];
            uint32_t qa = sb + (w * 16 + lrow) * FROWB + ks * 32 + lcol;
            ldmatrix_x4(qh4[0], qh4[1], qh4[2], qh4[3], qa);
            ldmatrix_x4(ql4[0], ql4[1], ql4[2], ql4[3], qa + 18432);
#pragma unroll
            for (int g = 0; g < 4; g++) {
                uint32_t kh4[4], kl4[4];
                uint32_t a = Kh + (g * 16 + lrow) * FROWB + ks * 32 + lcol;
                ldmatrix_x4(kh4[0], kh4[1], kh4[2], kh4[3], a);
                uint32_t a2 = Kl + (g * 16 + lrow) * FROWB + ks * 32 + lcol;
                ldmatrix_x4(kl4[0], kl4[1], kl4[2], kl4[3], a2);
                mma_f16(s[2 * g],     qh4, kh4[0], kh4[2]);
                mma_f16(s[2 * g],     qh4, kl4[0], kl4[2]);
                mma_f16(s[2 * g],     ql4, kh4[0], kh4[2]);
                mma_f16(s[2 * g + 1], qh4, kh4[1], kh4[3]);
                mma_f16(s[2 * g + 1], qh4, kl4[1], kl4[3]);
                mma_f16(s[2 * g + 1], ql4, kh4[1], kh4[3]);
            }
        }

        // ---- causal mask ----
        if (kt >= 2 * qt) {
            const int row0 = q0 + w * 16 + er;
#pragma unroll
            for (int nf = 0; nf < 8; nf++) {
                const int keyb = k0 + (nf >> 1) * 16 + (nf & 1) * 8 + ec;
#pragma unroll
                for (int r = 0; r < 4; r++) {
                    int key = keyb + (r & 1);
                    int row = row0 + (r >> 1) * 8;
                    if (key > row) s[nf][r] = -INFINITY;
                }
            }
        }

        // ---- online softmax ----
        float mx0 = -INFINITY, mx1 = -INFINITY;
#pragma unroll
        for (int nf = 0; nf < 8; nf++) {
            mx0 = fmaxf(mx0, fmaxf(s[nf][0], s[nf][1]));
            mx1 = fmaxf(mx1, fmaxf(s[nf][2], s[nf][3]));
        }
        mx0 = fmaxf(mx0, __shfl_xor_sync(0xffffffffu, mx0, 1));
        mx0 = fmaxf(mx0, __shfl_xor_sync(0xffffffffu, mx0, 2));
        mx1 = fmaxf(mx1, __shfl_xor_sync(0xffffffffu, mx1, 1));
        mx1 = fmaxf(mx1, __shfl_xor_sync(0xffffffffu, mx1, 2));

        float mn0 = fmaxf(mprev[0], mx0);
        float mn1 = fmaxf(mprev[1], mx1);
        float al0 = __expf(mprev[0] - mn0);
        float al1 = __expf(mprev[1] - mn1);
        float sum0 = 0.0f, sum1 = 0.0f;
#pragma unroll
        for (int nf = 0; nf < 8; nf++) {
            s[nf][0] = __expf(s[nf][0] - mn0);
            s[nf][1] = __expf(s[nf][1] - mn0);
            s[nf][2] = __expf(s[nf][2] - mn1);
            s[nf][3] = __expf(s[nf][3] - mn1);
            sum0 += s[nf][0] + s[nf][1];
            sum1 += s[nf][2] + s[nf][3];
        }
        sum0 += __shfl_xor_sync(0xffffffffu, sum0, 1);
        sum0 += __shfl_xor_sync(0xffffffffu, sum0, 2);
        sum1 += __shfl_xor_sync(0xffffffffu, sum1, 1);
        sum1 += __shfl_xor_sync(0xffffffffu, sum1, 2);
        lsum[0] = lsum[0] * al0 + sum0;
        lsum[1] = lsum[1] * al1 + sum1;
        mprev[0] = mn0;
        mprev[1] = mn1;
#pragma unroll
        for (int nf = 0; nf < 8; nf++) {
            o[nf][0] *= al0; o[nf][1] *= al0;
            o[nf][2] *= al1; o[nf][3] *= al1;
        }

        // ---- O += P Vh ----
#pragma unroll
        for (int kk = 0; kk < 4; kk++) {
            uint32_t pa[4];
            pa[0] = packh2(s[2 * kk][0], s[2 * kk][1]);
            pa[1] = packh2(s[2 * kk][2], s[2 * kk][3]);
            pa[2] = packh2(s[2 * kk + 1][0], s[2 * kk + 1][1]);
            pa[3] = packh2(s[2 * kk + 1][2], s[2 * kk + 1][3]);
#pragma unroll
            for (int g = 0; g < 4; g++) {
                uint32_t vh4[4];
                uint32_t a = Vh + (kk * 16 + lrow) * FROWB + g * 32 + lcol;
                ldmatrix_x4_trans(vh4[0], vh4[1], vh4[2], vh4[3], a);
                mma_f16(o[2 * g],     pa, vh4[0], vh4[1]);
                mma_f16(o[2 * g + 1], pa, vh4[2], vh4[3]);
            }
        }
        __syncthreads();   // required: next iter's issue writes stage kt&1
    }

    // ---- normalize + write ctx fp16 hi rows [MROWS][1024] ----
    const float inv0 = 1.0f / lsum[0];
    const float inv1 = 1.0f / lsum[1];
    const int mrow0 = b * SEQ + q0 + w * 16 + er;
#pragma unroll
    for (int nf = 0; nf < 8; nf++) {
        const int c = h * HDIM + nf * 8 + ec;
#pragma unroll
        for (int rr = 0; rr < 2; rr++) {
            float vx = o[nf][2 * rr + 0] * (rr ? inv1 : inv0);
            float vy = o[nf][2 * rr + 1] * (rr ? inv1 : inv0);
            __half2 t = {__float2half_rn(vx), __float2half_rn(vy)};
            *(__half2*)(ctx16 + (size_t)(mrow0 + rr * 8) * DIM + c) = t;
        }
    }
}

// ===========================================================================
// Residual + LayerNorm (unchanged)
// ===========================================================================
__global__ __launch_bounds__(256) void ln_kernel(
    const float* __restrict__ x, const float* __restrict__ att,
    const float* __restrict__ gamma, const float* __restrict__ beta,
    float* __restrict__ out)
{
    __shared__ float red[2][8];
    const int row = blockIdx.x;
    const int tid = threadIdx.x;
    const float* xr = x + (size_t)row * DIM;
    const float* ar = att + (size_t)row * DIM;

    float v[4];
    float s = 0.0f, s2 = 0.0f;
#pragma unroll
    for (int i = 0; i < 4; i++) {
        int c = tid + i * 256;
        float t = xr[c] + ar[c];
        v[i] = t;
        s += t;
        s2 += t * t;
    }
#pragma unroll
    for (int off = 16; off >= 1; off >>= 1) {
        s  += __shfl_xor_sync(0xffffffffu, s, off);
        s2 += __shfl_xor_sync(0xffffffffu, s2, off);
    }
    if ((tid & 31) == 0) { red[0][tid >> 5] = s; red[1][tid >> 5] = s2; }
    __syncthreads();
    s = 0.0f; s2 = 0.0f;
#pragma unroll
    for (int k = 0; k < 8; k++) { s += red[0][k]; s2 += red[1][k]; }

    const float mu = s * (1.0f / DIM);
    const float var = s2 * (1.0f / DIM) - mu * mu;
    const float rs = rsqrtf(var + 1e-5f);

    float* orow = out + (size_t)row * DIM;
#pragma unroll
    for (int i = 0; i < 4; i++) {
        int c = tid + i * 256;
        orow[c] = (v[i] - mu) * rs * gamma[c] + beta[c];
    }
}

// ===========================================================================
// Launch
// ===========================================================================
extern "C" void kernel_launch(void* const* d_in, const int* in_sizes, int n_in,
                              void* d_out, int out_size)
{
    const float* x      = (const float*)d_in[0];
    const float* w_in   = (const float*)d_in[1];
    const float* b_in   = (const float*)d_in[2];
    const float* w_out  = (const float*)d_in[3];
    const float* b_out  = (const float*)d_in[4];
    const float* gamma  = (const float*)d_in[5];
    const float* beta   = (const float*)d_in[6];
    float* out = (float*)d_out;

    void* p;
    cudaGetSymbolAddress(&p, g_abuf);  __half* abuf = (__half*)p;
    cudaGetSymbolAddress(&p, g_bbuf);  __half* wi16 = (__half*)p;
    cudaGetSymbolAddress(&p, g_wo16);  __half* wo16 = (__half*)p;
    cudaGetSymbolAddress(&p, g_f16);   __half* f16 = (__half*)p;
    cudaGetSymbolAddress(&p, g_att);   float* att = (float*)p;

    cudaFuncSetAttribute(gemm_mma<0>,
                         cudaFuncAttributeMaxDynamicSharedMemorySize, GEMM_SMEM);
    cudaFuncSetAttribute(gemm_mma<1>,
                         cudaFuncAttributeMaxDynamicSharedMemorySize, GEMM_SMEM);
    cudaFuncSetAttribute(flash_mma,
                         cudaFuncAttributeMaxDynamicSharedMemorySize, FLASH_SMEM);

    // 1) split-convert x (fp16 h|l) and weights
    split_f16_x_kernel<<<MROWS, 256>>>(x, abuf);
    split_f16_w_dup_kernel<<<QKVN, 256>>>(w_in, wi16);
    conv_f16_kernel<<<DIM * DIM / 1024, 256>>>(w_out, wo16);

    // 2a) Q,K projection (fp16 2-term, K2=2048) -> planes (Q scaled 1/8)
    gemm_mma<1><<<dim3(2048 / 128, MROWS / 128), 256, GEMM_SMEM>>>(
        abuf, wi16, b_in, nullptr, f16, 2048, K2, K2, K2, 0);

    // 2b) V projection (fp16 1-term, K=1024; w rows 2048.. read hi half)
    gemm_mma<1><<<dim3(1024 / 128, MROWS / 128), 256, GEMM_SMEM>>>(
        abuf, wi16 + (size_t)2048 * K2, b_in + 2048, nullptr, f16,
        1024, 1024, K2, K2, 2048);

    // 3) causal flash attention -> ctx fp16 hi [MROWS][1024] (reuses abuf)
    flash_mma<<<dim3(SEQ / 128, HEADS, BATCH), 256, FLASH_SMEM>>>(f16, abuf);

    // 4) out projection (fp16 1-term, K=1024)
    gemm_mma<0><<<dim3(DIM / 128, MROWS / 128), 256, GEMM_SMEM>>>(
        abuf, wo16, b_out, att, nullptr, DIM, 1024, 1024, 1024, 0);

    // 5) residual + layernorm
    ln_kernel<<<MROWS, 256>>>(x, att, gamma, beta, out);
}

// round 14
// speedup vs baseline: 4.5554x; 1.1681x over previous
#include <cuda_runtime.h>
#include <cuda_fp16.h>
#include <cuda_bf16.h>
#include <stdint.h>
#include <math.h>

// Problem constants
#define BATCH 4
#define SEQ   2048
#define DIM   1024
#define HEADS 16
#define HDIM  64
#define MROWS (BATCH * SEQ)          // 8192
#define QKVN  (3 * DIM)              // 3072
#define K3    3072
#define K2    2048                   // split-fp16 K (2 * 1024)
#define PLANE ((size_t)BATCH * HEADS * SEQ * HDIM)   // 8388608 halves / plane

// Scratch (device globals; no dynamic allocation allowed)
__device__ __nv_bfloat16 g_abuf[(size_t)MROWS * K3];   // x h|l, later ctx hi
__device__ __nv_bfloat16 g_bbuf[(size_t)QKVN * K3];    // in_proj_w fp16 h|h
__device__ __half g_wo16[(size_t)DIM * DIM];           // out_w fp16 hi
__device__ __half g_f16[4 * PLANE];                    // Qh,Ql,Kh,Vh planes
__device__ float g_att[(size_t)MROWS * DIM];           // out-proj result

// ===========================================================================
// Helpers (base-ISA only: cp.async, ldmatrix, mma.sync)
// ===========================================================================
__device__ __forceinline__ uint32_t smem_u32(const void* p) {
    uint32_t a;
    asm("{ .reg .u64 t; cvta.to.shared.u64 t, %1; cvt.u32.u64 %0, t; }"
        : "=r"(a) : "l"(p));
    return a;
}
__device__ __forceinline__ void cp_async16(uint32_t dst, const void* src) {
    asm volatile("cp.async.cg.shared.global [%0], [%1], 16;"
                 :: "r"(dst), "l"(src) : "memory");
}
#define CP_COMMIT() asm volatile("cp.async.commit_group;" ::: "memory")
#define CP_WAIT(n)  asm volatile("cp.async.wait_group %0;" :: "n"(n) : "memory")

__device__ __forceinline__ void ldmatrix_x4(uint32_t& r0, uint32_t& r1,
                                            uint32_t& r2, uint32_t& r3,
                                            uint32_t addr) {
    asm volatile("ldmatrix.sync.aligned.m8n8.x4.shared.b16 {%0,%1,%2,%3}, [%4];"
                 : "=r"(r0), "=r"(r1), "=r"(r2), "=r"(r3) : "r"(addr));
}
__device__ __forceinline__ void ldmatrix_x4_trans(uint32_t& r0, uint32_t& r1,
                                                  uint32_t& r2, uint32_t& r3,
                                                  uint32_t addr) {
    asm volatile("ldmatrix.sync.aligned.m8n8.x4.trans.shared.b16 {%0,%1,%2,%3}, [%4];"
                 : "=r"(r0), "=r"(r1), "=r"(r2), "=r"(r3) : "r"(addr));
}
__device__ __forceinline__ void mma_f16(float* d, const uint32_t* a,
                                        uint32_t b0, uint32_t b1) {
    asm volatile(
        "mma.sync.aligned.m16n8k16.row.col.f32.f16.f16.f32 "
        "{%0,%1,%2,%3}, {%4,%5,%6,%7}, {%8,%9}, {%0,%1,%2,%3};"
        : "+f"(d[0]), "+f"(d[1]), "+f"(d[2]), "+f"(d[3])
        : "r"(a[0]), "r"(a[1]), "r"(a[2]), "r"(a[3]), "r"(b0), "r"(b1));
}
__device__ __forceinline__ uint32_t packh2(float a, float b) {
    __half2 h = __floats2half2_rn(a, b);
    return *(uint32_t*)&h;
}

// ===========================================================================
// Split fp32 -> fp16 h|l (A side): out[r][c]=hi, out[r][1024+c]=lo
// ===========================================================================
__global__ __launch_bounds__(256) void split_f16_x_kernel(
    const float* __restrict__ in, __half* __restrict__ out)
{
    const int i = blockIdx.x * 256 + threadIdx.x;
    const int row = i >> 8;
    const int c4 = (i & 255) * 4;
    float4 v = ((const float4*)in)[i];
    __half hx = __float2half_rn(v.x), hy = __float2half_rn(v.y);
    __half hz = __float2half_rn(v.z), hw = __float2half_rn(v.w);
    __half lx = __float2half_rn(v.x - __half2float(hx));
    __half ly = __float2half_rn(v.y - __half2float(hy));
    __half lz = __float2half_rn(v.z - __half2float(hz));
    __half lw = __float2half_rn(v.w - __half2float(hw));
    uint2 H, L;
    { __half2 t = {hx, hy}; H.x = *(uint32_t*)&t; }
    { __half2 t = {hz, hw}; H.y = *(uint32_t*)&t; }
    { __half2 t = {lx, ly}; L.x = *(uint32_t*)&t; }
    { __half2 t = {lz, lw}; L.y = *(uint32_t*)&t; }
    size_t ob = (size_t)row * K2 + c4;
    *(uint2*)(out + ob)        = H;
    *(uint2*)(out + ob + 1024) = L;
}

// ===========================================================================
// Split fp32 -> fp16 hi duplicated (w_in rows, K2 h|h layout)
// ===========================================================================
__global__ __launch_bounds__(256) void split_f16_w_dup_kernel(
    const float* __restrict__ in, __half* __restrict__ out)
{
    const int i = blockIdx.x * 256 + threadIdx.x;
    const int row = i >> 8;
    const int c4 = (i & 255) * 4;
    float4 v = ((const float4*)in)[i];
    uint2 H;
    H.x = packh2(v.x, v.y);
    H.y = packh2(v.z, v.w);
    size_t ob = (size_t)row * K2 + c4;
    *(uint2*)(out + ob)        = H;
    *(uint2*)(out + ob + 1024) = H;
}

// ===========================================================================
// Convert fp32 -> fp16 hi only (w_out, [1024][1024])
// ===========================================================================
__global__ __launch_bounds__(256) void conv_f16_kernel(
    const float* __restrict__ in, __half* __restrict__ out)
{
    const int i = blockIdx.x * 256 + threadIdx.x;
    float4 v = ((const float4*)in)[i];
    uint2 H;
    H.x = packh2(v.x, v.y);
    H.y = packh2(v.z, v.w);
    *(uint2*)(out + (size_t)i * 4) = H;
}

// ===========================================================================
// mma.sync fp16 GEMM: 128x128 tile, BK=32, 3-stage cp.async, 8 warps.
// Runtime klen + row strides. MODE=0: fp32 out + bias.
// MODE=1: QKV -> fp16 planes. Plane map: Q->hi(0)+lo(1) scaled 1/8,
//         K->hi(2) only, V->hi(3) only.
// ===========================================================================
#define BK 32
#define STG 3
#define ROWB 80
#define TILEB (128 * ROWB)
#define GEMM_SMEM (2 * STG * TILEB)

__device__ __forceinline__ void g_load_tiles(
    const __half* __restrict__ Ab, const __half* __restrict__ Bb,
    uint32_t sA, uint32_t sB, int stage, int chunk, int tid,
    int astride, int bstride)
{
    const uint32_t sa = sA + stage * TILEB;
    const uint32_t sb = sB + stage * TILEB;
#pragma unroll
    for (int i = 0; i < 2; i++) {
        int idx = tid + i * 256;
        int row = idx >> 2;
        int cc = idx & 3;
        uint32_t dst = row * ROWB + cc * 16;
        cp_async16(sa + dst, Ab + (size_t)row * astride + chunk * BK + cc * 8);
        cp_async16(sb + dst, Bb + (size_t)row * bstride + chunk * BK + cc * 8);
    }
}

template <int MODE>
__global__ __launch_bounds__(256, 2) void gemm_mma(
    const __half* __restrict__ A, const __half* __restrict__ B,
    const float* __restrict__ bias, float* __restrict__ C,
    __half* __restrict__ f16out, int N, int klen,
    int astride, int bstride, int colofs)
{
    extern __shared__ __align__(16) char smem[];
    const uint32_t sA = smem_u32(smem);
    const uint32_t sB = sA + STG * TILEB;

    const int tid = threadIdx.x;
    const int warp = tid >> 5;
    const int lane = tid & 31;
    const int wm = warp >> 2;
    const int wn = warp & 3;
    const int bm = blockIdx.y * 128;
    const int bn = blockIdx.x * 128;
    const int NC = klen / BK;

    const __half* Ab = A + (size_t)bm * astride;
    const __half* Bb = B + (size_t)bn * bstride;

    float acc[4][4][4];
#pragma unroll
    for (int mt = 0; mt < 4; mt++)
#pragma unroll
        for (int nt = 0; nt < 4; nt++)
#pragma unroll
            for (int r = 0; r < 4; r++) acc[mt][nt][r] = 0.0f;

    const int lrow = lane & 15;
    const int lcol = (lane >> 4) * 16;

#pragma unroll
    for (int c = 0; c < STG - 1; c++) {
        g_load_tiles(Ab, Bb, sA, sB, c, c, tid, astride, bstride);
        CP_COMMIT();
    }

    for (int c = 0; c < NC; c++) {
        CP_WAIT(STG - 2);
        __syncthreads();

        const int t = c + STG - 1;
        if (t < NC) g_load_tiles(Ab, Bb, sA, sB, t % STG, t, tid,
                                 astride, bstride);
        CP_COMMIT();

        const int s = c % STG;
        const uint32_t aBase = sA + s * TILEB;
        const uint32_t bBase = sB + s * TILEB;

#pragma unroll
        for (int ks = 0; ks < 2; ks++) {
            const int k0 = ks * 16;
            uint32_t af[4][4];
#pragma unroll
            for (int mt = 0; mt < 4; mt++) {
                uint32_t addr = aBase + (wm * 64 + mt * 16 + lrow) * ROWB
                              + k0 * 2 + lcol;
                ldmatrix_x4(af[mt][0], af[mt][1], af[mt][2], af[mt][3], addr);
            }
            uint32_t bf[2][4];
#pragma unroll
            for (int bt = 0; bt < 2; bt++) {
                uint32_t addr = bBase + (wn * 32 + bt * 16 + lrow) * ROWB
                              + k0 * 2 + lcol;
                ldmatrix_x4(bf[bt][0], bf[bt][1], bf[bt][2], bf[bt][3], addr);
            }
#pragma unroll
            for (int mt = 0; mt < 4; mt++)
#pragma unroll
                for (int nt = 0; nt < 4; nt++) {
                    const int bt = nt >> 1, sel = nt & 1;
                    mma_f16(acc[mt][nt], af[mt], bf[bt][sel], bf[bt][sel + 2]);
                }
        }
        // no bottom barrier: next iter's top __syncthreads covers reuse
    }

    const int er = lane >> 2;
    const int ec = (lane & 3) * 2;
#pragma unroll
    for (int mt = 0; mt < 4; mt++) {
#pragma unroll
        for (int nt = 0; nt < 4; nt++) {
            const int col = bn + wn * 32 + nt * 8 + ec;
            const float b0 = bias[col], b1 = bias[col + 1];
            const int r0 = bm + wm * 64 + mt * 16 + er;
            float v00 = acc[mt][nt][0] + b0, v01 = acc[mt][nt][1] + b1;
            float v10 = acc[mt][nt][2] + b0, v11 = acc[mt][nt][3] + b1;
            if (MODE == 0) {
                *(float2*)(C + (size_t)r0 * N + col) = {v00, v01};
                *(float2*)(C + (size_t)(r0 + 8) * N + col) = {v10, v11};
            } else {
                const int gcol = col + colofs;
                const int type = gcol >> 10;          // 0=Q 1=K 2=V
                const int rem = gcol & 1023;
                const int h = rem >> 6;
                const int d = rem & 63;
                if (type == 0) { v00 *= 0.125f; v01 *= 0.125f;
                                 v10 *= 0.125f; v11 *= 0.125f; }
                const int b = r0 >> 11;
                const int s0 = r0 & 2047;
                size_t rowbase = (((size_t)(b * HEADS + h)) * SEQ + s0) * HDIM + d;
                // plane map: Q->0(+1 lo), K->2, V->3
                const int hp_idx = (type == 0) ? 0 : (type + 1);
                __half* hp = f16out + (size_t)hp_idx * PLANE;
                __half* lp = f16out + PLANE;
#pragma unroll
                for (int rr = 0; rr < 2; rr++) {
                    float vx = rr ? v10 : v00;
                    float vy = rr ? v11 : v01;
                    __half hx = __float2half_rn(vx), hy = __float2half_rn(vy);
                    size_t o = rowbase + (size_t)rr * 8 * HDIM;
                    { __half2 t = {hx, hy}; *(__half2*)(hp + o) = t; }
                    if (type == 0) {
                        __half lx = __float2half_rn(vx - __half2float(hx));
                        __half ly = __float2half_rn(vy - __half2float(hy));
                        __half2 t = {lx, ly}; *(__half2*)(lp + o) = t;
                    }
                }
            }
        }
    }
}

// ===========================================================================
// Flash attention (tensor cores), 2 CTAs/SM. Q re-LDSM'd from persistent smem.
// S = qh*kh + ql*kh (K is 1-term); PV = P*Vh.
// smem = Qh|Ql (36864) + 2 stages x (Kh|Vh @ 64x144B) = 73728 B.
// Output: ctx fp16 hi rows [MROWS][1024] (1-term out-proj).
// ===========================================================================
#define FROWB 144
#define FTILE 9216                       // 64 * 144
#define FSTAGE (2 * FTILE)               // 18432
#define FQREG  (2 * 128 * FROWB)         // 36864 (Qh | Ql)
#define FLASH_SMEM (FQREG + 2 * FSTAGE)  // 73728

__global__ __launch_bounds__(256, 2) void flash_mma(
    const __half* __restrict__ f16, __half* __restrict__ ctx16)
{
    extern __shared__ __align__(16) char fsm[];
    const uint32_t sb = smem_u32(fsm);

    const int tid = threadIdx.x;
    const int w = tid >> 5;
    const int lane = tid & 31;
    const int er = lane >> 2;
    const int ec = (lane & 3) * 2;
    const int lrow = lane & 15;
    const int lcol = (lane >> 4) * 16;

    const int qt = (int)gridDim.x - 1 - (int)blockIdx.x;   // heavy tiles first
    const int h = blockIdx.y;
    const int b = blockIdx.z;
    const int q0 = qt * 128;

    const size_t hb = ((size_t)(b * HEADS + h)) * SEQ * HDIM;
    const __half* Qhg = f16 + hb;
    const __half* Qlg = f16 + PLANE + hb;
    const __half* Khg = f16 + 2 * PLANE + hb;
    const __half* Vhg = f16 + 3 * PLANE + hb;

    // ---- stage Q hi/lo into the persistent region ----
#pragma unroll
    for (int i = 0; i < 8; i++) {
        int idx = tid + i * 256;          // 2048 chunks: op(1b) | row(7b) | c(3b)
        int op = idx >> 10;
        int within = idx & 1023;
        int r = within >> 3;
        int c = within & 7;
        const __half* src = (op ? Qlg : Qhg) + (size_t)(q0 + r) * HDIM + c * 8;
        cp_async16(sb + op * 18432 + r * FROWB + c * 16, src);
    }
    CP_COMMIT();

    float o[8][4];
#pragma unroll
    for (int nf = 0; nf < 8; nf++)
#pragma unroll
        for (int r = 0; r < 4; r++) o[nf][r] = 0.0f;
    float mprev[2] = {-INFINITY, -INFINITY};
    float lsum[2] = {0.0f, 0.0f};

    const int nkt = 2 * qt + 2;

    auto issue_tile = [&](int kt, int st) {
        const int k0 = kt * 64;
        const uint32_t sbase = sb + FQREG + st * FSTAGE;
#pragma unroll
        for (int i = 0; i < 4; i++) {
            int idx = tid + i * 256;      // 1024 chunks: op(1b) | row(6b) | c(3b)
            int op = idx >> 9;
            int within = idx & 511;
            int r = within >> 3;
            int c = within & 7;
            const __half* base = (op == 0) ? Khg : Vhg;
            cp_async16(sbase + op * FTILE + r * FROWB + c * 16,
                       base + (size_t)(k0 + r) * HDIM + c * 8);
        }
        CP_COMMIT();
    };

    issue_tile(0, 0);

    for (int kt = 0; kt < nkt; kt++) {
        const int k0 = kt * 64;
        if (kt + 1 < nkt) { issue_tile(kt + 1, (kt + 1) & 1); CP_WAIT(1); }
        else              { CP_WAIT(0); }
        __syncthreads();

        const uint32_t Kh = sb + FQREG + (kt & 1) * FSTAGE;
        const uint32_t Vh = Kh + FTILE;

        // ---- S = Q K^T (qh*kh + ql*kh) ----
        float s[8][4];
#pragma unroll
        for (int nf = 0; nf < 8; nf++)
#pragma unroll
            for (int r = 0; r < 4; r++) s[nf][r] = 0.0f;

#pragma unroll
        for (int ks = 0; ks < 4; ks++) {
            uint32_t qh4[4], ql4[4];
            uint32_t qa = sb + (w * 16 + lrow) * FROWB + ks * 32 + lcol;
            ldmatrix_x4(qh4[0], qh4[1], qh4[2], qh4[3], qa);
            ldmatrix_x4(ql4[0], ql4[1], ql4[2], ql4[3], qa + 18432);
#pragma unroll
            for (int g = 0; g < 4; g++) {
                uint32_t kh4[4];
                uint32_t a = Kh + (g * 16 + lrow) * FROWB + ks * 32 + lcol;
                ldmatrix_x4(kh4[0], kh4[1], kh4[2], kh4[3], a);
                mma_f16(s[2 * g],     qh4, kh4[0], kh4[2]);
                mma_f16(s[2 * g],     ql4, kh4[0], kh4[2]);
                mma_f16(s[2 * g + 1], qh4, kh4[1], kh4[3]);
                mma_f16(s[2 * g + 1], ql4, kh4[1], kh4[3]);
            }
        }

        // ---- causal mask ----
        if (kt >= 2 * qt) {
            const int row0 = q0 + w * 16 + er;
#pragma unroll
            for (int nf = 0; nf < 8; nf++) {
                const int keyb = k0 + (nf >> 1) * 16 + (nf & 1) * 8 + ec;
#pragma unroll
                for (int r = 0; r < 4; r++) {
                    int key = keyb + (r & 1);
                    int row = row0 + (r >> 1) * 8;
                    if (key > row) s[nf][r] = -INFINITY;
                }
            }
        }

        // ---- online softmax ----
        float mx0 = -INFINITY, mx1 = -INFINITY;
#pragma unroll
        for (int nf = 0; nf < 8; nf++) {
            mx0 = fmaxf(mx0, fmaxf(s[nf][0], s[nf][1]));
            mx1 = fmaxf(mx1, fmaxf(s[nf][2], s[nf][3]));
        }
        mx0 = fmaxf(mx0, __shfl_xor_sync(0xffffffffu, mx0, 1));
        mx0 = fmaxf(mx0, __shfl_xor_sync(0xffffffffu, mx0, 2));
        mx1 = fmaxf(mx1, __shfl_xor_sync(0xffffffffu, mx1, 1));
        mx1 = fmaxf(mx1, __shfl_xor_sync(0xffffffffu, mx1, 2));

        float mn0 = fmaxf(mprev[0], mx0);
        float mn1 = fmaxf(mprev[1], mx1);
        float al0 = __expf(mprev[0] - mn0);
        float al1 = __expf(mprev[1] - mn1);
        float sum0 = 0.0f, sum1 = 0.0f;
#pragma unroll
        for (int nf = 0; nf < 8; nf++) {
            s[nf][0] = __expf(s[nf][0] - mn0);
            s[nf][1] = __expf(s[nf][1] - mn0);
            s[nf][2] = __expf(s[nf][2] - mn1);
            s[nf][3] = __expf(s[nf][3] - mn1);
            sum0 += s[nf][0] + s[nf][1];
            sum1 += s[nf][2] + s[nf][3];
        }
        sum0 += __shfl_xor_sync(0xffffffffu, sum0, 1);
        sum0 += __shfl_xor_sync(0xffffffffu, sum0, 2);
        sum1 += __shfl_xor_sync(0xffffffffu, sum1, 1);
        sum1 += __shfl_xor_sync(0xffffffffu, sum1, 2);
        lsum[0] = lsum[0] * al0 + sum0;
        lsum[1] = lsum[1] * al1 + sum1;
        mprev[0] = mn0;
        mprev[1] = mn1;
#pragma unroll
        for (int nf = 0; nf < 8; nf++) {
            o[nf][0] *= al0; o[nf][1] *= al0;
            o[nf][2] *= al1; o[nf][3] *= al1;
        }

        // ---- O += P Vh ----
#pragma unroll
        for (int kk = 0; kk < 4; kk++) {
            uint32_t pa[4];
            pa[0] = packh2(s[2 * kk][0], s[2 * kk][1]);
            pa[1] = packh2(s[2 * kk][2], s[2 * kk][3]);
            pa[2] = packh2(s[2 * kk + 1][0], s[2 * kk + 1][1]);
            pa[3] = packh2(s[2 * kk + 1][2], s[2 * kk + 1][3]);
#pragma unroll
            for (int g = 0; g < 4; g++) {
                uint32_t vh4[4];
                uint32_t a = Vh + (kk * 16 + lrow) * FROWB + g * 32 + lcol;
                ldmatrix_x4_trans(vh4[0], vh4[1], vh4[2], vh4[3], a);
                mma_f16(o[2 * g],     pa, vh4[0], vh4[1]);
                mma_f16(o[2 * g + 1], pa, vh4[2], vh4[3]);
            }
        }
        __syncthreads();   // required: next iter's issue writes stage kt&1
    }

    // ---- normalize + write ctx fp16 hi rows [MROWS][1024] ----
    const float inv0 = 1.0f / lsum[0];
    const float inv1 = 1.0f / lsum[1];
    const int mrow0 = b * SEQ + q0 + w * 16 + er;
#pragma unroll
    for (int nf = 0; nf < 8; nf++) {
        const int c = h * HDIM + nf * 8 + ec;
#pragma unroll
        for (int rr = 0; rr < 2; rr++) {
            float vx = o[nf][2 * rr + 0] * (rr ? inv1 : inv0);
            float vy = o[nf][2 * rr + 1] * (rr ? inv1 : inv0);
            __half2 t = {__float2half_rn(vx), __float2half_rn(vy)};
            *(__half2*)(ctx16 + (size_t)(mrow0 + rr * 8) * DIM + c) = t;
        }
    }
}

// ===========================================================================
// Residual + LayerNorm (unchanged)
// ===========================================================================
__global__ __launch_bounds__(256) void ln_kernel(
    const float* __restrict__ x, const float* __restrict__ att,
    const float* __restrict__ gamma, const float* __restrict__ beta,
    float* __restrict__ out)
{
    __shared__ float red[2][8];
    const int row = blockIdx.x;
    const int tid = threadIdx.x;
    const float* xr = x + (size_t)row * DIM;
    const float* ar = att + (size_t)row * DIM;

    float v[4];
    float s = 0.0f, s2 = 0.0f;
#pragma unroll
    for (int i = 0; i < 4; i++) {
        int c = tid + i * 256;
        float t = xr[c] + ar[c];
        v[i] = t;
        s += t;
        s2 += t * t;
    }
#pragma unroll
    for (int off = 16; off >= 1; off >>= 1) {
        s  += __shfl_xor_sync(0xffffffffu, s, off);
        s2 += __shfl_xor_sync(0xffffffffu, s2, off);
    }
    if ((tid & 31) == 0) { red[0][tid >> 5] = s; red[1][tid >> 5] = s2; }
    __syncthreads();
    s = 0.0f; s2 = 0.0f;
#pragma unroll
    for (int k = 0; k < 8; k++) { s += red[0][k]; s2 += red[1][k]; }

    const float mu = s * (1.0f / DIM);
    const float var = s2 * (1.0f / DIM) - mu * mu;
    const float rs = rsqrtf(var + 1e-5f);

    float* orow = out + (size_t)row * DIM;
#pragma unroll
    for (int i = 0; i < 4; i++) {
        int c = tid + i * 256;
        orow[c] = (v[i] - mu) * rs * gamma[c] + beta[c];
    }
}

// ===========================================================================
// Launch
// ===========================================================================
extern "C" void kernel_launch(void* const* d_in, const int* in_sizes, int n_in,
                              void* d_out, int out_size)
{
    const float* x      = (const float*)d_in[0];
    const float* w_in   = (const float*)d_in[1];
    const float* b_in   = (const float*)d_in[2];
    const float* w_out  = (const float*)d_in[3];
    const float* b_out  = (const float*)d_in[4];
    const float* gamma  = (const float*)d_in[5];
    const float* beta   = (const float*)d_in[6];
    float* out = (float*)d_out;

    void* p;
    cudaGetSymbolAddress(&p, g_abuf);  __half* abuf = (__half*)p;
    cudaGetSymbolAddress(&p, g_bbuf);  __half* wi16 = (__half*)p;
    cudaGetSymbolAddress(&p, g_wo16);  __half* wo16 = (__half*)p;
    cudaGetSymbolAddress(&p, g_f16);   __half* f16 = (__half*)p;
    cudaGetSymbolAddress(&p, g_att);   float* att = (float*)p;

    cudaFuncSetAttribute(gemm_mma<0>,
                         cudaFuncAttributeMaxDynamicSharedMemorySize, GEMM_SMEM);
    cudaFuncSetAttribute(gemm_mma<1>,
                         cudaFuncAttributeMaxDynamicSharedMemorySize, GEMM_SMEM);
    cudaFuncSetAttribute(flash_mma,
                         cudaFuncAttributeMaxDynamicSharedMemorySize, FLASH_SMEM);

    // 1) split-convert x (fp16 h|l) and weights
    split_f16_x_kernel<<<MROWS, 256>>>(x, abuf);
    split_f16_w_dup_kernel<<<QKVN, 256>>>(w_in, wi16);
    conv_f16_kernel<<<DIM * DIM / 1024, 256>>>(w_out, wo16);

    // 2a) Q projection (fp16 2-term, K=2048) -> Qh/Ql planes (scaled 1/8)
    gemm_mma<1><<<dim3(1024 / 128, MROWS / 128), 256, GEMM_SMEM>>>(
        abuf, wi16, b_in, nullptr, f16, 1024, K2, K2, K2, 0);

    // 2b) K+V projection (fp16 1-term, K=1024; w rows 1024..3071, hi half)
    gemm_mma<1><<<dim3(2048 / 128, MROWS / 128), 256, GEMM_SMEM>>>(
        abuf, wi16 + (size_t)1024 * K2, b_in + 1024, nullptr, f16,
        2048, 1024, K2, K2, 1024);

    // 3) causal flash attention -> ctx fp16 hi [MROWS][1024] (reuses abuf)
    flash_mma<<<dim3(SEQ / 128, HEADS, BATCH), 256, FLASH_SMEM>>>(f16, abuf);

    // 4) out projection (fp16 1-term, K=1024)
    gemm_mma<0><<<dim3(DIM / 128, MROWS / 128), 256, GEMM_SMEM>>>(
        abuf, wo16, b_out, att, nullptr, DIM, 1024, 1024, 1024, 0);

    // 5) residual + layernorm
    ln_kernel<<<MROWS, 256>>>(x, att, gamma, beta, out);
}

// round 15
// speedup vs baseline: 5.5563x; 1.2197x over previous
#include <cuda_runtime.h>
#include <cuda_fp16.h>
#include <cuda_bf16.h>
#include <stdint.h>
#include <math.h>

// Problem constants
#define BATCH 4
#define SEQ   2048
#define DIM   1024
#define HEADS 16
#define HDIM  64
#define MROWS (BATCH * SEQ)          // 8192
#define QKVN  (3 * DIM)              // 3072
#define K3    3072
#define PLANE ((size_t)BATCH * HEADS * SEQ * HDIM)   // 8388608 halves / plane

// Scratch (device globals; no dynamic allocation allowed)
__device__ __nv_bfloat16 g_abuf[(size_t)MROWS * K3];   // x fp16, later ctx fp16
__device__ __nv_bfloat16 g_bbuf[(size_t)QKVN * K3];    // in_proj_w fp16
__device__ __half g_wo16[(size_t)DIM * DIM];           // out_w fp16
__device__ __half g_f16[3 * PLANE];                    // Qh,Kh,Vh planes
__device__ float g_att[(size_t)MROWS * DIM];           // out-proj result

// ===========================================================================
// Helpers (base-ISA only: cp.async, ldmatrix, mma.sync)
// ===========================================================================
__device__ __forceinline__ uint32_t smem_u32(const void* p) {
    uint32_t a;
    asm("{ .reg .u64 t; cvta.to.shared.u64 t, %1; cvt.u32.u64 %0, t; }"
        : "=r"(a) : "l"(p));
    return a;
}
__device__ __forceinline__ void cp_async16(uint32_t dst, const void* src) {
    asm volatile("cp.async.cg.shared.global [%0], [%1], 16;"
                 :: "r"(dst), "l"(src) : "memory");
}
#define CP_COMMIT() asm volatile("cp.async.commit_group;" ::: "memory")
#define CP_WAIT(n)  asm volatile("cp.async.wait_group %0;" :: "n"(n) : "memory")

__device__ __forceinline__ void ldmatrix_x4(uint32_t& r0, uint32_t& r1,
                                            uint32_t& r2, uint32_t& r3,
                                            uint32_t addr) {
    asm volatile("ldmatrix.sync.aligned.m8n8.x4.shared.b16 {%0,%1,%2,%3}, [%4];"
                 : "=r"(r0), "=r"(r1), "=r"(r2), "=r"(r3) : "r"(addr));
}
__device__ __forceinline__ void ldmatrix_x4_trans(uint32_t& r0, uint32_t& r1,
                                                  uint32_t& r2, uint32_t& r3,
                                                  uint32_t addr) {
    asm volatile("ldmatrix.sync.aligned.m8n8.x4.trans.shared.b16 {%0,%1,%2,%3}, [%4];"
                 : "=r"(r0), "=r"(r1), "=r"(r2), "=r"(r3) : "r"(addr));
}
__device__ __forceinline__ void mma_f16(float* d, const uint32_t* a,
                                        uint32_t b0, uint32_t b1) {
    asm volatile(
        "mma.sync.aligned.m16n8k16.row.col.f32.f16.f16.f32 "
        "{%0,%1,%2,%3}, {%4,%5,%6,%7}, {%8,%9}, {%0,%1,%2,%3};"
        : "+f"(d[0]), "+f"(d[1]), "+f"(d[2]), "+f"(d[3])
        : "r"(a[0]), "r"(a[1]), "r"(a[2]), "r"(a[3]), "r"(b0), "r"(b1));
}
__device__ __forceinline__ uint32_t packh2(float a, float b) {
    __half2 h = __floats2half2_rn(a, b);
    return *(uint32_t*)&h;
}

// ===========================================================================
// Convert fp32 -> fp16 (contiguous), one float4 per thread
// ===========================================================================
__global__ __launch_bounds__(256) void conv_f16_kernel(
    const float* __restrict__ in, __half* __restrict__ out)
{
    const int i = blockIdx.x * 256 + threadIdx.x;
    float4 v = ((const float4*)in)[i];
    uint2 H;
    H.x = packh2(v.x, v.y);
    H.y = packh2(v.z, v.w);
    *(uint2*)(out + (size_t)i * 4) = H;
}

// ===========================================================================
// mma.sync fp16 GEMM: 128x128 tile, K=1024, BK=32, 3-stage cp.async, 8 warps.
// MODE=0: fp32 out + bias.  MODE=1: QKV -> fp16 planes Q(0,scaled 1/8),K(1),V(2)
// ===========================================================================
#define BK 32
#define GKLEN 1024
#define STG 3
#define ROWB 80
#define TILEB (128 * ROWB)
#define GEMM_SMEM (2 * STG * TILEB)

__device__ __forceinline__ void g_load_tiles(
    const __half* __restrict__ Ab, const __half* __restrict__ Bb,
    uint32_t sA, uint32_t sB, int stage, int chunk, int tid)
{
    const uint32_t sa = sA + stage * TILEB;
    const uint32_t sb = sB + stage * TILEB;
#pragma unroll
    for (int i = 0; i < 2; i++) {
        int idx = tid + i * 256;
        int row = idx >> 2;
        int cc = idx & 3;
        uint32_t dst = row * ROWB + cc * 16;
        cp_async16(sa + dst, Ab + (size_t)row * GKLEN + chunk * BK + cc * 8);
        cp_async16(sb + dst, Bb + (size_t)row * GKLEN + chunk * BK + cc * 8);
    }
}

template <int MODE>
__global__ __launch_bounds__(256, 2) void gemm_mma(
    const __half* __restrict__ A, const __half* __restrict__ B,
    const float* __restrict__ bias, float* __restrict__ C,
    __half* __restrict__ f16out, int N)
{
    extern __shared__ __align__(16) char smem[];
    const uint32_t sA = smem_u32(smem);
    const uint32_t sB = sA + STG * TILEB;

    const int tid = threadIdx.x;
    const int warp = tid >> 5;
    const int lane = tid & 31;
    const int wm = warp >> 2;
    const int wn = warp & 3;
    const int bm = blockIdx.y * 128;
    const int bn = blockIdx.x * 128;
    const int NC = GKLEN / BK;       // 32

    const __half* Ab = A + (size_t)bm * GKLEN;
    const __half* Bb = B + (size_t)bn * GKLEN;

    float acc[4][4][4];
#pragma unroll
    for (int mt = 0; mt < 4; mt++)
#pragma unroll
        for (int nt = 0; nt < 4; nt++)
#pragma unroll
            for (int r = 0; r < 4; r++) acc[mt][nt][r] = 0.0f;

    const int lrow = lane & 15;
    const int lcol = (lane >> 4) * 16;

#pragma unroll
    for (int c = 0; c < STG - 1; c++) {
        g_load_tiles(Ab, Bb, sA, sB, c, c, tid);
        CP_COMMIT();
    }

    for (int c = 0; c < NC; c++) {
        CP_WAIT(STG - 2);
        __syncthreads();

        const int t = c + STG - 1;
        if (t < NC) g_load_tiles(Ab, Bb, sA, sB, t % STG, t, tid);
        CP_COMMIT();

        const int s = c % STG;
        const uint32_t aBase = sA + s * TILEB;
        const uint32_t bBase = sB + s * TILEB;

#pragma unroll
        for (int ks = 0; ks < 2; ks++) {
            const int k0 = ks * 16;
            uint32_t af[4][4];
#pragma unroll
            for (int mt = 0; mt < 4; mt++) {
                uint32_t addr = aBase + (wm * 64 + mt * 16 + lrow) * ROWB
                              + k0 * 2 + lcol;
                ldmatrix_x4(af[mt][0], af[mt][1], af[mt][2], af[mt][3], addr);
            }
            uint32_t bf[2][4];
#pragma unroll
            for (int bt = 0; bt < 2; bt++) {
                uint32_t addr = bBase + (wn * 32 + bt * 16 + lrow) * ROWB
                              + k0 * 2 + lcol;
                ldmatrix_x4(bf[bt][0], bf[bt][1], bf[bt][2], bf[bt][3], addr);
            }
#pragma unroll
            for (int mt = 0; mt < 4; mt++)
#pragma unroll
                for (int nt = 0; nt < 4; nt++) {
                    const int bt = nt >> 1, sel = nt & 1;
                    mma_f16(acc[mt][nt], af[mt], bf[bt][sel], bf[bt][sel + 2]);
                }
        }
    }

    const int er = lane >> 2;
    const int ec = (lane & 3) * 2;
#pragma unroll
    for (int mt = 0; mt < 4; mt++) {
#pragma unroll
        for (int nt = 0; nt < 4; nt++) {
            const int col = bn + wn * 32 + nt * 8 + ec;
            const float b0 = bias[col], b1 = bias[col + 1];
            const int r0 = bm + wm * 64 + mt * 16 + er;
            float v00 = acc[mt][nt][0] + b0, v01 = acc[mt][nt][1] + b1;
            float v10 = acc[mt][nt][2] + b0, v11 = acc[mt][nt][3] + b1;
            if (MODE == 0) {
                *(float2*)(C + (size_t)r0 * N + col) = {v00, v01};
                *(float2*)(C + (size_t)(r0 + 8) * N + col) = {v10, v11};
            } else {
                const int type = col >> 10;           // 0=Q 1=K 2=V
                const int rem = col & 1023;
                const int h = rem >> 6;
                const int d = rem & 63;
                if (type == 0) { v00 *= 0.125f; v01 *= 0.125f;
                                 v10 *= 0.125f; v11 *= 0.125f; }
                const int b = r0 >> 11;
                const int s0 = r0 & 2047;
                size_t rowbase = (((size_t)(b * HEADS + h)) * SEQ + s0) * HDIM + d;
                __half* hp = f16out + (size_t)type * PLANE;
#pragma unroll
                for (int rr = 0; rr < 2; rr++) {
                    float vx = rr ? v10 : v00;
                    float vy = rr ? v11 : v01;
                    __half2 t = {__float2half_rn(vx), __float2half_rn(vy)};
                    *(__half2*)(hp + rowbase + (size_t)rr * 8 * HDIM) = t;
                }
            }
        }
    }
}

// ===========================================================================
// Flash attention (tensor cores), 2 CTAs/SM, pure fp16 operands.
// S = qh*kh; PV = P*Vh. Q re-LDSM'd from persistent smem region.
// smem = Qh (18432) + 2 stages x (Kh|Vh @ 64x144B) = 55296 B.
// Output: ctx fp16 rows [MROWS][1024].
// ===========================================================================
#define FROWB 144
#define FTILE 9216                       // 64 * 144
#define FSTAGE (2 * FTILE)               // 18432
#define FQREG  (128 * FROWB)             // 18432 (Qh)
#define FLASH_SMEM (FQREG + 2 * FSTAGE)  // 55296

__global__ __launch_bounds__(256, 2) void flash_mma(
    const __half* __restrict__ f16, __half* __restrict__ ctx16)
{
    extern __shared__ __align__(16) char fsm[];
    const uint32_t sb = smem_u32(fsm);

    const int tid = threadIdx.x;
    const int w = tid >> 5;
    const int lane = tid & 31;
    const int er = lane >> 2;
    const int ec = (lane & 3) * 2;
    const int lrow = lane & 15;
    const int lcol = (lane >> 4) * 16;

    const int qt = (int)gridDim.x - 1 - (int)blockIdx.x;   // heavy tiles first
    const int h = blockIdx.y;
    const int b = blockIdx.z;
    const int q0 = qt * 128;

    const size_t hb = ((size_t)(b * HEADS + h)) * SEQ * HDIM;
    const __half* Qhg = f16 + hb;
    const __half* Khg = f16 + PLANE + hb;
    const __half* Vhg = f16 + 2 * PLANE + hb;

    // ---- stage Q into the persistent region ----
#pragma unroll
    for (int i = 0; i < 4; i++) {
        int idx = tid + i * 256;          // 1024 chunks: row(7b) | c(3b)
        int r = idx >> 3;
        int c = idx & 7;
        cp_async16(sb + r * FROWB + c * 16,
                   Qhg + (size_t)(q0 + r) * HDIM + c * 8);
    }
    CP_COMMIT();

    float o[8][4];
#pragma unroll
    for (int nf = 0; nf < 8; nf++)
#pragma unroll
        for (int r = 0; r < 4; r++) o[nf][r] = 0.0f;
    float mprev[2] = {-INFINITY, -INFINITY};
    float lsum[2] = {0.0f, 0.0f};

    const int nkt = 2 * qt + 2;

    auto issue_tile = [&](int kt, int st) {
        const int k0 = kt * 64;
        const uint32_t sbase = sb + FQREG + st * FSTAGE;
#pragma unroll
        for (int i = 0; i < 4; i++) {
            int idx = tid + i * 256;      // 1024 chunks: op(1b) | row(6b) | c(3b)
            int op = idx >> 9;
            int within = idx & 511;
            int r = within >> 3;
            int c = within & 7;
            const __half* base = (op == 0) ? Khg : Vhg;
            cp_async16(sbase + op * FTILE + r * FROWB + c * 16,
                       base + (size_t)(k0 + r) * HDIM + c * 8);
        }
        CP_COMMIT();
    };

    issue_tile(0, 0);

    for (int kt = 0; kt < nkt; kt++) {
        const int k0 = kt * 64;
        if (kt + 1 < nkt) { issue_tile(kt + 1, (kt + 1) & 1); CP_WAIT(1); }
        else              { CP_WAIT(0); }
        __syncthreads();

        const uint32_t Kh = sb + FQREG + (kt & 1) * FSTAGE;
        const uint32_t Vh = Kh + FTILE;

        // ---- S = Q K^T ----
        float s[8][4];
#pragma unroll
        for (int nf = 0; nf < 8; nf++)
#pragma unroll
            for (int r = 0; r < 4; r++) s[nf][r] = 0.0f;

#pragma unroll
        for (int ks = 0; ks < 4; ks++) {
            uint32_t qh4[4];
            uint32_t qa = sb + (w * 16 + lrow) * FROWB + ks * 32 + lcol;
            ldmatrix_x4(qh4[0], qh4[1], qh4[2], qh4[3], qa);
#pragma unroll
            for (int g = 0; g < 4; g++) {
                uint32_t kh4[4];
                uint32_t a = Kh + (g * 16 + lrow) * FROWB + ks * 32 + lcol;
                ldmatrix_x4(kh4[0], kh4[1], kh4[2], kh4[3], a);
                mma_f16(s[2 * g],     qh4, kh4[0], kh4[2]);
                mma_f16(s[2 * g + 1], qh4, kh4[1], kh4[3]);
            }
        }

        // ---- causal mask ----
        if (kt >= 2 * qt) {
            const int row0 = q0 + w * 16 + er;
#pragma unroll
            for (int nf = 0; nf < 8; nf++) {
                const int keyb = k0 + (nf >> 1) * 16 + (nf & 1) * 8 + ec;
#pragma unroll
                for (int r = 0; r < 4; r++) {
                    int key = keyb + (r & 1);
                    int row = row0 + (r >> 1) * 8;
                    if (key > row) s[nf][r] = -INFINITY;
                }
            }
        }

        // ---- online softmax ----
        float mx0 = -INFINITY, mx1 = -INFINITY;
#pragma unroll
        for (int nf = 0; nf < 8; nf++) {
            mx0 = fmaxf(mx0, fmaxf(s[nf][0], s[nf][1]));
            mx1 = fmaxf(mx1, fmaxf(s[nf][2], s[nf][3]));
        }
        mx0 = fmaxf(mx0, __shfl_xor_sync(0xffffffffu, mx0, 1));
        mx0 = fmaxf(mx0, __shfl_xor_sync(0xffffffffu, mx0, 2));
        mx1 = fmaxf(mx1, __shfl_xor_sync(0xffffffffu, mx1, 1));
        mx1 = fmaxf(mx1, __shfl_xor_sync(0xffffffffu, mx1, 2));

        float mn0 = fmaxf(mprev[0], mx0);
        float mn1 = fmaxf(mprev[1], mx1);
        float al0 = __expf(mprev[0] - mn0);
        float al1 = __expf(mprev[1] - mn1);
        float sum0 = 0.0f, sum1 = 0.0f;
#pragma unroll
        for (int nf = 0; nf < 8; nf++) {
            s[nf][0] = __expf(s[nf][0] - mn0);
            s[nf][1] = __expf(s[nf][1] - mn0);
            s[nf][2] = __expf(s[nf][2] - mn1);
            s[nf][3] = __expf(s[nf][3] - mn1);
            sum0 += s[nf][0] + s[nf][1];
            sum1 += s[nf][2] + s[nf][3];
        }
        sum0 += __shfl_xor_sync(0xffffffffu, sum0, 1);
        sum0 += __shfl_xor_sync(0xffffffffu, sum0, 2);
        sum1 += __shfl_xor_sync(0xffffffffu, sum1, 1);
        sum1 += __shfl_xor_sync(0xffffffffu, sum1, 2);
        lsum[0] = lsum[0] * al0 + sum0;
        lsum[1] = lsum[1] * al1 + sum1;
        mprev[0] = mn0;
        mprev[1] = mn1;
#pragma unroll
        for (int nf = 0; nf < 8; nf++) {
            o[nf][0] *= al0; o[nf][1] *= al0;
            o[nf][2] *= al1; o[nf][3] *= al1;
        }

        // ---- O += P Vh ----
#pragma unroll
        for (int kk = 0; kk < 4; kk++) {
            uint32_t pa[4];
            pa[0] = packh2(s[2 * kk][0], s[2 * kk][1]);
            pa[1] = packh2(s[2 * kk][2], s[2 * kk][3]);
            pa[2] = packh2(s[2 * kk + 1][0], s[2 * kk + 1][1]);
            pa[3] = packh2(s[2 * kk + 1][2], s[2 * kk + 1][3]);
#pragma unroll
            for (int g = 0; g < 4; g++) {
                uint32_t vh4[4];
                uint32_t a = Vh + (kk * 16 + lrow) * FROWB + g * 32 + lcol;
                ldmatrix_x4_trans(vh4[0], vh4[1], vh4[2], vh4[3], a);
                mma_f16(o[2 * g],     pa, vh4[0], vh4[1]);
                mma_f16(o[2 * g + 1], pa, vh4[2], vh4[3]);
            }
        }
        __syncthreads();   // next iter's issue writes stage kt&1
    }

    // ---- normalize + write ctx fp16 rows [MROWS][1024] ----
    const float inv0 = 1.0f / lsum[0];
    const float inv1 = 1.0f / lsum[1];
    const int mrow0 = b * SEQ + q0 + w * 16 + er;
#pragma unroll
    for (int nf = 0; nf < 8; nf++) {
        const int c = h * HDIM + nf * 8 + ec;
#pragma unroll
        for (int rr = 0; rr < 2; rr++) {
            float vx = o[nf][2 * rr + 0] * (rr ? inv1 : inv0);
            float vy = o[nf][2 * rr + 1] * (rr ? inv1 : inv0);
            __half2 t = {__float2half_rn(vx), __float2half_rn(vy)};
            *(__half2*)(ctx16 + (size_t)(mrow0 + rr * 8) * DIM + c) = t;
        }
    }
}

// ===========================================================================
// Residual + LayerNorm (unchanged)
// ===========================================================================
__global__ __launch_bounds__(256) void ln_kernel(
    const float* __restrict__ x, const float* __restrict__ att,
    const float* __restrict__ gamma, const float* __restrict__ beta,
    float* __restrict__ out)
{
    __shared__ float red[2][8];
    const int row = blockIdx.x;
    const int tid = threadIdx.x;
    const float* xr = x + (size_t)row * DIM;
    const float* ar = att + (size_t)row * DIM;

    float v[4];
    float s = 0.0f, s2 = 0.0f;
#pragma unroll
    for (int i = 0; i < 4; i++) {
        int c = tid + i * 256;
        float t = xr[c] + ar[c];
        v[i] = t;
        s += t;
        s2 += t * t;
    }
#pragma unroll
    for (int off = 16; off >= 1; off >>= 1) {
        s  += __shfl_xor_sync(0xffffffffu, s, off);
        s2 += __shfl_xor_sync(0xffffffffu, s2, off);
    }
    if ((tid & 31) == 0) { red[0][tid >> 5] = s; red[1][tid >> 5] = s2; }
    __syncthreads();
    s = 0.0f; s2 = 0.0f;
#pragma unroll
    for (int k = 0; k < 8; k++) { s += red[0][k]; s2 += red[1][k]; }

    const float mu = s * (1.0f / DIM);
    const float var = s2 * (1.0f / DIM) - mu * mu;
    const float rs = rsqrtf(var + 1e-5f);

    float* orow = out + (size_t)row * DIM;
#pragma unroll
    for (int i = 0; i < 4; i++) {
        int c = tid + i * 256;
        orow[c] = (v[i] - mu) * rs * gamma[c] + beta[c];
    }
}

// ===========================================================================
// Launch
// ===========================================================================
extern "C" void kernel_launch(void* const* d_in, const int* in_sizes, int n_in,
                              void* d_out, int out_size)
{
    const float* x      = (const float*)d_in[0];
    const float* w_in   = (const float*)d_in[1];
    const float* b_in   = (const float*)d_in[2];
    const float* w_out  = (const float*)d_in[3];
    const float* b_out  = (const float*)d_in[4];
    const float* gamma  = (const float*)d_in[5];
    const float* beta   = (const float*)d_in[6];
    float* out = (float*)d_out;

    void* p;
    cudaGetSymbolAddress(&p, g_abuf);  __half* abuf = (__half*)p;
    cudaGetSymbolAddress(&p, g_bbuf);  __half* wi16 = (__half*)p;
    cudaGetSymbolAddress(&p, g_wo16);  __half* wo16 = (__half*)p;
    cudaGetSymbolAddress(&p, g_f16);   __half* f16 = (__half*)p;
    cudaGetSymbolAddress(&p, g_att);   float* att = (float*)p;

    cudaFuncSetAttribute(gemm_mma<0>,
                         cudaFuncAttributeMaxDynamicSharedMemorySize, GEMM_SMEM);
    cudaFuncSetAttribute(gemm_mma<1>,
                         cudaFuncAttributeMaxDynamicSharedMemorySize, GEMM_SMEM);
    cudaFuncSetAttribute(flash_mma,
                         cudaFuncAttributeMaxDynamicSharedMemorySize, FLASH_SMEM);

    // 1) convert x, in_proj_w, out_w to fp16
    conv_f16_kernel<<<(MROWS * DIM) / 1024, 256>>>(x, abuf);
    conv_f16_kernel<<<(QKVN * DIM) / 1024, 256>>>(w_in, wi16);
    conv_f16_kernel<<<(DIM * DIM) / 1024, 256>>>(w_out, wo16);

    // 2) QKV projection (single fp16 GEMM, K=1024) -> Q,K,V planes
    gemm_mma<1><<<dim3(QKVN / 128, MROWS / 128), 256, GEMM_SMEM>>>(
        abuf, wi16, b_in, nullptr, f16, QKVN);

    // 3) causal flash attention -> ctx fp16 [MROWS][1024] (reuses abuf)
    flash_mma<<<dim3(SEQ / 128, HEADS, BATCH), 256, FLASH_SMEM>>>(f16, abuf);

    // 4) out projection (fp16, K=1024)
    gemm_mma<0><<<dim3(DIM / 128, MROWS / 128), 256, GEMM_SMEM>>>(
        abuf, wo16, b_out, att, nullptr, DIM);

    // 5) residual + layernorm
    ln_kernel<<<MROWS, 256>>>(x, att, gamma, beta, out);
}

// round 16
// speedup vs baseline: 6.0477x; 1.0884x over previous
#include <cuda_runtime.h>
#include <cuda_fp16.h>
#include <cuda_bf16.h>
#include <stdint.h>
#include <math.h>

// Problem constants
#define BATCH 4
#define SEQ   2048
#define DIM   1024
#define HEADS 16
#define HDIM  64
#define MROWS (BATCH * SEQ)          // 8192
#define QKVN  (3 * DIM)              // 3072
#define K3    3072
#define PLANE ((size_t)BATCH * HEADS * SEQ * HDIM)   // 8388608 halves / plane

// Scratch (device globals; no dynamic allocation allowed)
__device__ __nv_bfloat16 g_abuf[(size_t)MROWS * K3];   // x fp16, later ctx fp16
__device__ __nv_bfloat16 g_bbuf[(size_t)QKVN * K3];    // in_proj_w fp16
__device__ __half g_wo16[(size_t)DIM * DIM];           // out_w fp16
__device__ __half g_f16[3 * PLANE];                    // Qh,Kh,Vh planes
__device__ float g_att[(size_t)MROWS * DIM];           // out-proj result

// ===========================================================================
// Helpers (base-ISA only: cp.async, ldmatrix, mma.sync)
// ===========================================================================
__device__ __forceinline__ uint32_t smem_u32(const void* p) {
    uint32_t a;
    asm("{ .reg .u64 t; cvta.to.shared.u64 t, %1; cvt.u32.u64 %0, t; }"
        : "=r"(a) : "l"(p));
    return a;
}
__device__ __forceinline__ void cp_async16(uint32_t dst, const void* src) {
    asm volatile("cp.async.cg.shared.global [%0], [%1], 16;"
                 :: "r"(dst), "l"(src) : "memory");
}
#define CP_COMMIT() asm volatile("cp.async.commit_group;" ::: "memory")
#define CP_WAIT(n)  asm volatile("cp.async.wait_group %0;" :: "n"(n) : "memory")

__device__ __forceinline__ void ldmatrix_x4(uint32_t& r0, uint32_t& r1,
                                            uint32_t& r2, uint32_t& r3,
                                            uint32_t addr) {
    asm volatile("ldmatrix.sync.aligned.m8n8.x4.shared.b16 {%0,%1,%2,%3}, [%4];"
                 : "=r"(r0), "=r"(r1), "=r"(r2), "=r"(r3) : "r"(addr));
}
__device__ __forceinline__ void ldmatrix_x4_trans(uint32_t& r0, uint32_t& r1,
                                                  uint32_t& r2, uint32_t& r3,
                                                  uint32_t addr) {
    asm volatile("ldmatrix.sync.aligned.m8n8.x4.trans.shared.b16 {%0,%1,%2,%3}, [%4];"
                 : "=r"(r0), "=r"(r1), "=r"(r2), "=r"(r3) : "r"(addr));
}
__device__ __forceinline__ void mma_f16(float* d, const uint32_t* a,
                                        uint32_t b0, uint32_t b1) {
    asm volatile(
        "mma.sync.aligned.m16n8k16.row.col.f32.f16.f16.f32 "
        "{%0,%1,%2,%3}, {%4,%5,%6,%7}, {%8,%9}, {%0,%1,%2,%3};"
        : "+f"(d[0]), "+f"(d[1]), "+f"(d[2]), "+f"(d[3])
        : "r"(a[0]), "r"(a[1]), "r"(a[2]), "r"(a[3]), "r"(b0), "r"(b1));
}
__device__ __forceinline__ uint32_t packh2(float a, float b) {
    __half2 h = __floats2half2_rn(a, b);
    return *(uint32_t*)&h;
}

// ===========================================================================
// Fused fp32 -> fp16 conversion of x | w_in | w_out (one float4 per thread)
// ===========================================================================
#define XF4   ((MROWS * DIM) / 4)          // 2097152
#define WIF4  ((QKVN * DIM) / 4)           // 786432
#define WOF4  ((DIM * DIM) / 4)            // 262144
#define CONVF4 (XF4 + WIF4 + WOF4)         // 3145728

__global__ __launch_bounds__(256) void conv_all_kernel(
    const float* __restrict__ x, const float* __restrict__ w_in,
    const float* __restrict__ w_out,
    __half* __restrict__ xo, __half* __restrict__ wio,
    __half* __restrict__ woo)
{
    const int i = blockIdx.x * 256 + threadIdx.x;
    const float* src;
    __half* dst;
    int j;
    if (i < XF4)              { src = x;     dst = xo;  j = i; }
    else if (i < XF4 + WIF4)  { src = w_in;  dst = wio; j = i - XF4; }
    else                      { src = w_out; dst = woo; j = i - XF4 - WIF4; }
    float4 v = ((const float4*)src)[j];
    uint2 H;
    H.x = packh2(v.x, v.y);
    H.y = packh2(v.z, v.w);
    *(uint2*)(dst + (size_t)j * 4) = H;
}

// ===========================================================================
// mma.sync fp16 GEMM: 128x128 tile, K=1024, BK=64, 3-stage cp.async, 8 warps.
// 16 mainloop iters, ONE __syncthreads per iter (64 MMAs/warp between syncs).
// MODE=0: fp32 out + bias.  MODE=1: QKV -> fp16 planes Q(0,scaled 1/8),K(1),V(2)
// ===========================================================================
#define BK 64
#define GKLEN 1024
#define STG 3
#define ROWB 144                         // 128 B data + 16 B pad
#define TILEB (128 * ROWB)               // 18432 B / operand / stage
#define GEMM_SMEM (2 * STG * TILEB)      // 110592 B

__device__ __forceinline__ void g_load_tiles(
    const __half* __restrict__ Ab, const __half* __restrict__ Bb,
    uint32_t sA, uint32_t sB, int stage, int chunk, int tid)
{
    const uint32_t sa = sA + stage * TILEB;
    const uint32_t sb = sB + stage * TILEB;
#pragma unroll
    for (int i = 0; i < 4; i++) {
        int idx = tid + i * 256;         // 1024 chunks: row(7b) | c(3b)
        int row = idx >> 3;
        int cc = idx & 7;
        uint32_t dst = row * ROWB + cc * 16;
        cp_async16(sa + dst, Ab + (size_t)row * GKLEN + chunk * BK + cc * 8);
        cp_async16(sb + dst, Bb + (size_t)row * GKLEN + chunk * BK + cc * 8);
    }
}

template <int MODE>
__global__ __launch_bounds__(256, 2) void gemm_mma(
    const __half* __restrict__ A, const __half* __restrict__ B,
    const float* __restrict__ bias, float* __restrict__ C,
    __half* __restrict__ f16out, int N)
{
    extern __shared__ __align__(16) char smem[];
    const uint32_t sA = smem_u32(smem);
    const uint32_t sB = sA + STG * TILEB;

    const int tid = threadIdx.x;
    const int warp = tid >> 5;
    const int lane = tid & 31;
    const int wm = warp >> 2;
    const int wn = warp & 3;
    const int bm = blockIdx.y * 128;
    const int bn = blockIdx.x * 128;
    const int NC = GKLEN / BK;           // 16

    const __half* Ab = A + (size_t)bm * GKLEN;
    const __half* Bb = B + (size_t)bn * GKLEN;

    float acc[4][4][4];
#pragma unroll
    for (int mt = 0; mt < 4; mt++)
#pragma unroll
        for (int nt = 0; nt < 4; nt++)
#pragma unroll
            for (int r = 0; r < 4; r++) acc[mt][nt][r] = 0.0f;

    const int lrow = lane & 15;
    const int lcol = (lane >> 4) * 16;

#pragma unroll
    for (int c = 0; c < STG - 1; c++) {
        g_load_tiles(Ab, Bb, sA, sB, c, c, tid);
        CP_COMMIT();
    }

    for (int c = 0; c < NC; c++) {
        CP_WAIT(STG - 2);
        __syncthreads();                 // data c visible; stage (c+2)%3 free

        const int t = c + STG - 1;
        if (t < NC) g_load_tiles(Ab, Bb, sA, sB, t % STG, t, tid);
        CP_COMMIT();

        const int s = c % STG;
        const uint32_t aBase = sA + s * TILEB;
        const uint32_t bBase = sB + s * TILEB;

#pragma unroll
        for (int ks = 0; ks < 4; ks++) {
            const int kb = ks * 32;      // byte offset of 16-elem k-slice
            uint32_t af[4][4];
#pragma unroll
            for (int mt = 0; mt < 4; mt++) {
                uint32_t addr = aBase + (wm * 64 + mt * 16 + lrow) * ROWB
                              + kb + lcol;
                ldmatrix_x4(af[mt][0], af[mt][1], af[mt][2], af[mt][3], addr);
            }
            uint32_t bf[2][4];
#pragma unroll
            for (int bt = 0; bt < 2; bt++) {
                uint32_t addr = bBase + (wn * 32 + bt * 16 + lrow) * ROWB
                              + kb + lcol;
                ldmatrix_x4(bf[bt][0], bf[bt][1], bf[bt][2], bf[bt][3], addr);
            }
#pragma unroll
            for (int mt = 0; mt < 4; mt++)
#pragma unroll
                for (int nt = 0; nt < 4; nt++) {
                    const int bt = nt >> 1, sel = nt & 1;
                    mma_f16(acc[mt][nt], af[mt], bf[bt][sel], bf[bt][sel + 2]);
                }
        }
    }

    const int er = lane >> 2;
    const int ec = (lane & 3) * 2;
#pragma unroll
    for (int mt = 0; mt < 4; mt++) {
#pragma unroll
        for (int nt = 0; nt < 4; nt++) {
            const int col = bn + wn * 32 + nt * 8 + ec;
            const float b0 = bias[col], b1 = bias[col + 1];
            const int r0 = bm + wm * 64 + mt * 16 + er;
            float v00 = acc[mt][nt][0] + b0, v01 = acc[mt][nt][1] + b1;
            float v10 = acc[mt][nt][2] + b0, v11 = acc[mt][nt][3] + b1;
            if (MODE == 0) {
                *(float2*)(C + (size_t)r0 * N + col) = {v00, v01};
                *(float2*)(C + (size_t)(r0 + 8) * N + col) = {v10, v11};
            } else {
                const int type = col >> 10;           // 0=Q 1=K 2=V
                const int rem = col & 1023;
                const int h = rem >> 6;
                const int d = rem & 63;
                if (type == 0) { v00 *= 0.125f; v01 *= 0.125f;
                                 v10 *= 0.125f; v11 *= 0.125f; }
                const int b = r0 >> 11;
                const int s0 = r0 & 2047;
                size_t rowbase = (((size_t)(b * HEADS + h)) * SEQ + s0) * HDIM + d;
                __half* hp = f16out + (size_t)type * PLANE;
#pragma unroll
                for (int rr = 0; rr < 2; rr++) {
                    float vx = rr ? v10 : v00;
                    float vy = rr ? v11 : v01;
                    __half2 t = {__float2half_rn(vx), __float2half_rn(vy)};
                    *(__half2*)(hp + rowbase + (size_t)rr * 8 * HDIM) = t;
                }
            }
        }
    }
}

// ===========================================================================
// Flash attention (tensor cores), 2 CTAs/SM, pure fp16, 3-stage K/V ring,
// ONE __syncthreads per key tile.
// smem = Qh (18432) + 3 stages x (Kh|Vh @ 64x144B) = 73728 B.
// Output: ctx fp16 rows [MROWS][1024].
// ===========================================================================
#define FROWB 144
#define FTILE 9216                       // 64 * 144
#define FSTAGE (2 * FTILE)               // 18432 (Kh|Vh)
#define FQREG  (128 * FROWB)             // 18432 (Qh)
#define FLASH_SMEM (FQREG + 3 * FSTAGE)  // 73728

__global__ __launch_bounds__(256, 2) void flash_mma(
    const __half* __restrict__ f16, __half* __restrict__ ctx16)
{
    extern __shared__ __align__(16) char fsm[];
    const uint32_t sb = smem_u32(fsm);

    const int tid = threadIdx.x;
    const int w = tid >> 5;
    const int lane = tid & 31;
    const int er = lane >> 2;
    const int ec = (lane & 3) * 2;
    const int lrow = lane & 15;
    const int lcol = (lane >> 4) * 16;

    const int qt = (int)gridDim.x - 1 - (int)blockIdx.x;   // heavy tiles first
    const int h = blockIdx.y;
    const int b = blockIdx.z;
    const int q0 = qt * 128;

    const size_t hb = ((size_t)(b * HEADS + h)) * SEQ * HDIM;
    const __half* Qhg = f16 + hb;
    const __half* Khg = f16 + PLANE + hb;
    const __half* Vhg = f16 + 2 * PLANE + hb;

    // ---- stage Q into the persistent region (own cp.async group) ----
#pragma unroll
    for (int i = 0; i < 4; i++) {
        int idx = tid + i * 256;          // 1024 chunks: row(7b) | c(3b)
        int r = idx >> 3;
        int c = idx & 7;
        cp_async16(sb + r * FROWB + c * 16,
                   Qhg + (size_t)(q0 + r) * HDIM + c * 8);
    }
    CP_COMMIT();

    float o[8][4];
#pragma unroll
    for (int nf = 0; nf < 8; nf++)
#pragma unroll
        for (int r = 0; r < 4; r++) o[nf][r] = 0.0f;
    float mprev[2] = {-INFINITY, -INFINITY};
    float lsum[2] = {0.0f, 0.0f};

    const int nkt = 2 * qt + 2;

    auto issue_tile = [&](int kt, int st) {
        const int k0 = kt * 64;
        const uint32_t sbase = sb + FQREG + st * FSTAGE;
#pragma unroll
        for (int i = 0; i < 4; i++) {
            int idx = tid + i * 256;      // 1024 chunks: op(1b) | row(6b) | c(3b)
            int op = idx >> 9;
            int within = idx & 511;
            int r = within >> 3;
            int c = within & 7;
            const __half* base = (op == 0) ? Khg : Vhg;
            cp_async16(sbase + op * FTILE + r * FROWB + c * 16,
                       base + (size_t)(k0 + r) * HDIM + c * 8);
        }
        CP_COMMIT();
    };

    issue_tile(0, 0);
    if (nkt > 1) issue_tile(1, 1);

    for (int kt = 0; kt < nkt; kt++) {
        const int k0 = kt * 64;
        if (kt + 1 < nkt) { CP_WAIT(1); }
        else              { CP_WAIT(0); }
        __syncthreads();   // data kt visible; stage (kt+2)%3 drained (== kt-1)

        const int t = kt + 2;
        if (t < nkt) issue_tile(t, t % 3);

        const uint32_t Kh = sb + FQREG + (kt % 3) * FSTAGE;
        const uint32_t Vh = Kh + FTILE;

        // ---- S = Q K^T ----
        float s[8][4];
#pragma unroll
        for (int nf = 0; nf < 8; nf++)
#pragma unroll
            for (int r = 0; r < 4; r++) s[nf][r] = 0.0f;

#pragma unroll
        for (int ks = 0; ks < 4; ks++) {
            uint32_t qh4[4];
            uint32_t qa = sb + (w * 16 + lrow) * FROWB + ks * 32 + lcol;
            ldmatrix_x4(qh4[0], qh4[1], qh4[2], qh4[3], qa);
#pragma unroll
            for (int g = 0; g < 4; g++) {
                uint32_t kh4[4];
                uint32_t a = Kh + (g * 16 + lrow) * FROWB + ks * 32 + lcol;
                ldmatrix_x4(kh4[0], kh4[1], kh4[2], kh4[3], a);
                mma_f16(s[2 * g],     qh4, kh4[0], kh4[2]);
                mma_f16(s[2 * g + 1], qh4, kh4[1], kh4[3]);
            }
        }

        // ---- causal mask ----
        if (kt >= 2 * qt) {
            const int row0 = q0 + w * 16 + er;
#pragma unroll
            for (int nf = 0; nf < 8; nf++) {
                const int keyb = k0 + (nf >> 1) * 16 + (nf & 1) * 8 + ec;
#pragma unroll
                for (int r = 0; r < 4; r++) {
                    int key = keyb + (r & 1);
                    int row = row0 + (r >> 1) * 8;
                    if (key > row) s[nf][r] = -INFINITY;
                }
            }
        }

        // ---- online softmax ----
        float mx0 = -INFINITY, mx1 = -INFINITY;
#pragma unroll
        for (int nf = 0; nf < 8; nf++) {
            mx0 = fmaxf(mx0, fmaxf(s[nf][0], s[nf][1]));
            mx1 = fmaxf(mx1, fmaxf(s[nf][2], s[nf][3]));
        }
        mx0 = fmaxf(mx0, __shfl_xor_sync(0xffffffffu, mx0, 1));
        mx0 = fmaxf(mx0, __shfl_xor_sync(0xffffffffu, mx0, 2));
        mx1 = fmaxf(mx1, __shfl_xor_sync(0xffffffffu, mx1, 1));
        mx1 = fmaxf(mx1, __shfl_xor_sync(0xffffffffu, mx1, 2));

        float mn0 = fmaxf(mprev[0], mx0);
        float mn1 = fmaxf(mprev[1], mx1);
        float al0 = __expf(mprev[0] - mn0);
        float al1 = __expf(mprev[1] - mn1);
        float sum0 = 0.0f, sum1 = 0.0f;
#pragma unroll
        for (int nf = 0; nf < 8; nf++) {
            s[nf][0] = __expf(s[nf][0] - mn0);
            s[nf][1] = __expf(s[nf][1] - mn0);
            s[nf][2] = __expf(s[nf][2] - mn1);
            s[nf][3] = __expf(s[nf][3] - mn1);
            sum0 += s[nf][0] + s[nf][1];
            sum1 += s[nf][2] + s[nf][3];
        }
        sum0 += __shfl_xor_sync(0xffffffffu, sum0, 1);
        sum0 += __shfl_xor_sync(0xffffffffu, sum0, 2);
        sum1 += __shfl_xor_sync(0xffffffffu, sum1, 1);
        sum1 += __shfl_xor_sync(0xffffffffu, sum1, 2);
        lsum[0] = lsum[0] * al0 + sum0;
        lsum[1] = lsum[1] * al1 + sum1;
        mprev[0] = mn0;
        mprev[1] = mn1;
#pragma unroll
        for (int nf = 0; nf < 8; nf++) {
            o[nf][0] *= al0; o[nf][1] *= al0;
            o[nf][2] *= al1; o[nf][3] *= al1;
        }

        // ---- O += P Vh ----
#pragma unroll
        for (int kk = 0; kk < 4; kk++) {
            uint32_t pa[4];
            pa[0] = packh2(s[2 * kk][0], s[2 * kk][1]);
            pa[1] = packh2(s[2 * kk][2], s[2 * kk][3]);
            pa[2] = packh2(s[2 * kk + 1][0], s[2 * kk + 1][1]);
            pa[3] = packh2(s[2 * kk + 1][2], s[2 * kk + 1][3]);
#pragma unroll
            for (int g = 0; g < 4; g++) {
                uint32_t vh4[4];
                uint32_t a = Vh + (kk * 16 + lrow) * FROWB + g * 32 + lcol;
                ldmatrix_x4_trans(vh4[0], vh4[1], vh4[2], vh4[3], a);
                mma_f16(o[2 * g],     pa, vh4[0], vh4[1]);
                mma_f16(o[2 * g + 1], pa, vh4[2], vh4[3]);
            }
        }
        // no bottom barrier: 3-stage ring + top barrier covers reuse
    }

    // ---- normalize + write ctx fp16 rows [MROWS][1024] ----
    const float inv0 = 1.0f / lsum[0];
    const float inv1 = 1.0f / lsum[1];
    const int mrow0 = b * SEQ + q0 + w * 16 + er;
#pragma unroll
    for (int nf = 0; nf < 8; nf++) {
        const int c = h * HDIM + nf * 8 + ec;
#pragma unroll
        for (int rr = 0; rr < 2; rr++) {
            float vx = o[nf][2 * rr + 0] * (rr ? inv1 : inv0);
            float vy = o[nf][2 * rr + 1] * (rr ? inv1 : inv0);
            __half2 t = {__float2half_rn(vx), __float2half_rn(vy)};
            *(__half2*)(ctx16 + (size_t)(mrow0 + rr * 8) * DIM + c) = t;
        }
    }
}

// ===========================================================================
// Residual + LayerNorm (unchanged)
// ===========================================================================
__global__ __launch_bounds__(256) void ln_kernel(
    const float* __restrict__ x, const float* __restrict__ att,
    const float* __restrict__ gamma, const float* __restrict__ beta,
    float* __restrict__ out)
{
    __shared__ float red[2][8];
    const int row = blockIdx.x;
    const int tid = threadIdx.x;
    const float* xr = x + (size_t)row * DIM;
    const float* ar = att + (size_t)row * DIM;

    float v[4];
    float s = 0.0f, s2 = 0.0f;
#pragma unroll
    for (int i = 0; i < 4; i++) {
        int c = tid + i * 256;
        float t = xr[c] + ar[c];
        v[i] = t;
        s += t;
        s2 += t * t;
    }
#pragma unroll
    for (int off = 16; off >= 1; off >>= 1) {
        s  += __shfl_xor_sync(0xffffffffu, s, off);
        s2 += __shfl_xor_sync(0xffffffffu, s2, off);
    }
    if ((tid & 31) == 0) { red[0][tid >> 5] = s; red[1][tid >> 5] = s2; }
    __syncthreads();
    s = 0.0f; s2 = 0.0f;
#pragma unroll
    for (int k = 0; k < 8; k++) { s += red[0][k]; s2 += red[1][k]; }

    const float mu = s * (1.0f / DIM);
    const float var = s2 * (1.0f / DIM) - mu * mu;
    const float rs = rsqrtf(var + 1e-5f);

    float* orow = out + (size_t)row * DIM;
#pragma unroll
    for (int i = 0; i < 4; i++) {
        int c = tid + i * 256;
        orow[c] = (v[i] - mu) * rs * gamma[c] + beta[c];
    }
}

// ===========================================================================
// Launch
// ===========================================================================
extern "C" void kernel_launch(void* const* d_in, const int* in_sizes, int n_in,
                              void* d_out, int out_size)
{
    const float* x      = (const float*)d_in[0];
    const float* w_in   = (const float*)d_in[1];
    const float* b_in   = (const float*)d_in[2];
    const float* w_out  = (const float*)d_in[3];
    const float* b_out  = (const float*)d_in[4];
    const float* gamma  = (const float*)d_in[5];
    const float* beta   = (const float*)d_in[6];
    float* out = (float*)d_out;

    void* p;
    cudaGetSymbolAddress(&p, g_abuf);  __half* abuf = (__half*)p;
    cudaGetSymbolAddress(&p, g_bbuf);  __half* wi16 = (__half*)p;
    cudaGetSymbolAddress(&p, g_wo16);  __half* wo16 = (__half*)p;
    cudaGetSymbolAddress(&p, g_f16);   __half* f16 = (__half*)p;
    cudaGetSymbolAddress(&p, g_att);   float* att = (float*)p;

    cudaFuncSetAttribute(gemm_mma<0>,
                         cudaFuncAttributeMaxDynamicSharedMemorySize, GEMM_SMEM);
    cudaFuncSetAttribute(gemm_mma<1>,
                         cudaFuncAttributeMaxDynamicSharedMemorySize, GEMM_SMEM);
    cudaFuncSetAttribute(flash_mma,
                         cudaFuncAttributeMaxDynamicSharedMemorySize, FLASH_SMEM);

    // 1) fused fp32->fp16 conversion of x, in_proj_w, out_w
    conv_all_kernel<<<CONVF4 / 256, 256>>>(x, w_in, w_out, abuf, wi16, wo16);

    // 2) QKV projection (single fp16 GEMM, K=1024) -> Q,K,V planes
    gemm_mma<1><<<dim3(QKVN / 128, MROWS / 128), 256, GEMM_SMEM>>>(
        abuf, wi16, b_in, nullptr, f16, QKVN);

    // 3) causal flash attention -> ctx fp16 [MROWS][1024] (reuses abuf)
    flash_mma<<<dim3(SEQ / 128, HEADS, BATCH), 256, FLASH_SMEM>>>(f16, abuf);

    // 4) out projection (fp16, K=1024)
    gemm_mma<0><<<dim3(DIM / 128, MROWS / 128), 256, GEMM_SMEM>>>(
        abuf, wo16, b_out, att, nullptr, DIM);

    // 5) residual + layernorm
    ln_kernel<<<MROWS, 256>>>(x, att, gamma, beta, out);
}